// round 9
// baseline (speedup 1.0000x reference)
#include <cuda_runtime.h>
#include <cuda_bf16.h>
#include <cstdint>

#define TT 2048
#define BB 8
#define FD 768
#define HH 3
#define DH 256
#define MROWS (TT*BB)      // 16384
#define NBH (BB*HH)        // 24

// ------------------------- device scratch (static) -------------------------
__device__ __align__(16) __nv_bfloat16 g_xh[MROWS*FD], g_xl[MROWS*FD];
__device__ __align__(16) __nv_bfloat16 g_wqh[FD*FD], g_wql[FD*FD];
__device__ __align__(16) __nv_bfloat16 g_wkh[FD*FD], g_wkl[FD*FD];
__device__ __align__(16) __nv_bfloat16 g_wvh[FD*FD], g_wvl[FD*FD];
__device__ __align__(16) __nv_bfloat16 g_woh[FD*FD], g_wol[FD*FD];
__device__ __align__(16) __nv_bfloat16 g_qh[NBH*TT*DH], g_ql[NBH*TT*DH];
__device__ __align__(16) __nv_bfloat16 g_kh[NBH*TT*DH], g_kl[NBH*TT*DH];
__device__ __align__(16) __nv_bfloat16 g_vh[NBH*TT*DH], g_vl[NBH*TT*DH];   // (BH,T,D)
__device__ __align__(16) __nv_bfloat16 g_oh[MROWS*FD], g_ol[MROWS*FD];

// ------------------------------ PTX helpers --------------------------------
__device__ __forceinline__ uint32_t smem_u32(const void* p) {
    uint32_t a;
    asm("{ .reg .u64 t; cvta.to.shared.u64 t, %1; cvt.u32.u64 %0, t; }" : "=r"(a) : "l"(p));
    return a;
}
#define CP16(dst, src) \
    asm volatile("cp.async.cg.shared.global [%0], [%1], 16;" :: "r"(dst), "l"(src) : "memory")
#define CP_COMMIT() asm volatile("cp.async.commit_group;" ::: "memory")
#define CP_WAIT1()  asm volatile("cp.async.wait_group 1;" ::: "memory")

#define LDSM4(r, addr) \
    asm volatile("ldmatrix.sync.aligned.m8n8.x4.shared.b16 {%0,%1,%2,%3}, [%4];" \
        : "=r"((r)[0]), "=r"((r)[1]), "=r"((r)[2]), "=r"((r)[3]) : "r"(addr))
#define LDSM4T(r, addr) \
    asm volatile("ldmatrix.sync.aligned.m8n8.x4.trans.shared.b16 {%0,%1,%2,%3}, [%4];" \
        : "=r"((r)[0]), "=r"((r)[1]), "=r"((r)[2]), "=r"((r)[3]) : "r"(addr))

#define MMA16816(d, a, b0v, b1v) \
    asm volatile("mma.sync.aligned.m16n8k16.row.col.f32.bf16.bf16.f32 " \
        "{%0,%1,%2,%3}, {%4,%5,%6,%7}, {%8,%9}, {%0,%1,%2,%3};" \
        : "+f"((d)[0]), "+f"((d)[1]), "+f"((d)[2]), "+f"((d)[3]) \
        : "r"((a)[0]), "r"((a)[1]), "r"((a)[2]), "r"((a)[3]), "r"(b0v), "r"(b1v))

#define SWZ(o) ((uint32_t)(o) ^ ((((uint32_t)(o)) >> 3) & 0x70))

__device__ __forceinline__ void split2(float v, __nv_bfloat16& h, __nv_bfloat16& l) {
    h = __float2bfloat16(v);
    l = __float2bfloat16(v - __bfloat162float(h));
}

// ------------- split-bf16 GEMM via mma.sync, 512 threads, 256x128 -----------
#define BM 256
#define BN 128
#define BK 32
#define ROWB 80
#define MAT_A (256*ROWB)
#define MAT_B (128*ROWB)
#define OFF_AH 0
#define OFF_AL MAT_A
#define OFF_BH (2*MAT_A)
#define OFF_BL (2*MAT_A + MAT_B)
#define STAGE_BYTES (2*MAT_A + 2*MAT_B)
#define NSTAGE 3
#define SMEM_BYTES (NSTAGE*STAGE_BYTES)   // 184320

#define QSCALE 0.1803368801111204f    // 0.125 * log2(e)

// mode = blockIdx.z + mode_base: 0=Q, 1=K, 2=V, 3=out-proj
__global__ __launch_bounds__(512, 1) void gemm_fused(
    const __nv_bfloat16* __restrict__ Ah, const __nv_bfloat16* __restrict__ Al,
    int mode_base,
    const float* __restrict__ bq, const float* __restrict__ bk,
    const float* __restrict__ bv, const float* __restrict__ bo,
    float* __restrict__ outF)
{
    extern __shared__ char smem[];
    const uint32_t sb = smem_u32(smem);

    const int tid = threadIdx.x;
    const int wid = tid >> 5, lane = tid & 31;
    const int wm = wid >> 2, wn = wid & 3;
    const int m0 = blockIdx.x * BM, n0 = blockIdx.y * BN;
    const int mode = blockIdx.z + mode_base;

    const __nv_bfloat16* Bh = mode == 0 ? g_wqh : mode == 1 ? g_wkh : mode == 2 ? g_wvh : g_woh;
    const __nv_bfloat16* Bl = mode == 0 ? g_wql : mode == 1 ? g_wkl : mode == 2 ? g_wvl : g_wol;
    const float* bias = mode == 0 ? bq : mode == 1 ? bk : mode == 2 ? bv : bo;
    const int K = FD;

    float acc[4][4][4] = {};

    const int ra0 = tid >> 2,          ca0 = tid & 3;
    const int ra1 = (tid + 512) >> 2,  ca1 = (tid + 512) & 3;
    const int rb  = tid >> 2,          cb  = tid & 3;

    auto load_stage = [&](int kb, int s) {
        const uint32_t st = sb + s * STAGE_BYTES;
        {
            size_t g = (size_t)(m0 + ra0) * K + kb * BK + ca0 * 8;
            uint32_t so = ra0 * ROWB + ca0 * 16;
            CP16(st + OFF_AH + so, Ah + g);
            CP16(st + OFF_AL + so, Al + g);
        }
        {
            size_t g = (size_t)(m0 + ra1) * K + kb * BK + ca1 * 8;
            uint32_t so = ra1 * ROWB + ca1 * 16;
            CP16(st + OFF_AH + so, Ah + g);
            CP16(st + OFF_AL + so, Al + g);
        }
        {
            size_t g = (size_t)(n0 + rb) * K + kb * BK + cb * 8;
            uint32_t so = rb * ROWB + cb * 16;
            CP16(st + OFF_BH + so, Bh + g);
            CP16(st + OFF_BL + so, Bl + g);
        }
    };

    const int NKB = K / BK;
    load_stage(0, 0); CP_COMMIT();
    load_stage(1, 1); CP_COMMIT();

    const int a_row = wm * 64 + (lane & 7) + ((lane >> 3) & 1) * 8;
    const int a_kb  = ((lane >> 4) & 1) * 16;
    const int b_row = wn * 32 + (lane & 7) + (lane >= 16 ? 8 : 0);
    const int b_kb  = ((lane >> 3) & 1) * 16;

    for (int kb = 0; kb < NKB; kb++) {
        CP_WAIT1();
        __syncthreads();
        if (kb + 2 < NKB) load_stage(kb + 2, (kb + 2) % NSTAGE);
        CP_COMMIT();

        const uint32_t st = sb + (kb % NSTAGE) * STAGE_BYTES;
        #pragma unroll
        for (int ks = 0; ks < 2; ks++) {
            uint32_t bhf[2][4], blf[2][4];
            #pragma unroll
            for (int np = 0; np < 2; np++) {
                uint32_t bo2 = (b_row + np * 16) * ROWB + b_kb + ks * 32;
                LDSM4(bhf[np], st + OFF_BH + bo2);
                LDSM4(blf[np], st + OFF_BL + bo2);
            }
            #pragma unroll
            for (int mf = 0; mf < 4; mf++) {
                uint32_t ah[4], al[4];
                uint32_t ao = (a_row + mf * 16) * ROWB + a_kb + ks * 32;
                LDSM4(ah, st + OFF_AH + ao);
                LDSM4(al, st + OFF_AL + ao);
                #pragma unroll
                for (int np = 0; np < 2; np++) {
                    MMA16816(acc[mf][np*2],   ah, bhf[np][0], bhf[np][1]);
                    MMA16816(acc[mf][np*2+1], ah, bhf[np][2], bhf[np][3]);
                }
                #pragma unroll
                for (int np = 0; np < 2; np++) {
                    MMA16816(acc[mf][np*2],   ah, blf[np][0], blf[np][1]);
                    MMA16816(acc[mf][np*2+1], ah, blf[np][2], blf[np][3]);
                }
                #pragma unroll
                for (int np = 0; np < 2; np++) {
                    MMA16816(acc[mf][np*2],   al, bhf[np][0], bhf[np][1]);
                    MMA16816(acc[mf][np*2+1], al, bhf[np][2], bhf[np][3]);
                }
            }
        }
        __syncthreads();
    }

    const int mrow = m0 + wm * 64 + (lane >> 2);
    const int ncol = n0 + wn * 32 + (lane & 3) * 2;
    const float oscale = (mode == 0) ? QSCALE : 1.0f;

    #pragma unroll
    for (int mf = 0; mf < 4; mf++) {
        #pragma unroll
        for (int half = 0; half < 2; half++) {
            const int m = mrow + mf * 16 + half * 8;
            #pragma unroll
            for (int nf = 0; nf < 4; nf++) {
                const int n = ncol + nf * 8;
                float v0 = (acc[mf][nf][half * 2]     + __ldg(&bias[n]))     * oscale;
                float v1 = (acc[mf][nf][half * 2 + 1] + __ldg(&bias[n + 1])) * oscale;

                if (mode <= 2) {           // Q/K/V: (BH,T,D) hi/lo, coalesced
                    __nv_bfloat16* oH = mode == 0 ? g_qh : mode == 1 ? g_kh : g_vh;
                    __nv_bfloat16* oL = mode == 0 ? g_ql : mode == 1 ? g_kl : g_vl;
                    const int t = m >> 3, b = m & 7, h = n >> 8, d = n & 255;
                    size_t o = ((size_t)(b * HH + h) * TT + t) * DH + d;
                    __nv_bfloat16 h0, l0, h1, l1; split2(v0, h0, l0); split2(v1, h1, l1);
                    __nv_bfloat162 ph; ph.x = h0; ph.y = h1;
                    __nv_bfloat162 pl; pl.x = l0; pl.y = l1;
                    *(__nv_bfloat162*)(oH + o) = ph;
                    *(__nv_bfloat162*)(oL + o) = pl;
                } else {                   // out projection: fp32 (T*B, F)
                    size_t o = (size_t)m * FD + n;
                    float2 f; f.x = v0; f.y = v1;
                    *(float2*)(outF + o) = f;
                }
            }
        }
    }
}

// --------------------------- fused flash attention --------------------------
// CTA: 64 q-rows of one bh; 16 kv-tiles of 128 t. 256 threads, warps 2m x 4n.
// QK warp tile m32 x n32 (t); AV warp tile m32 x n32 (d per phase).
// Two 64KB ping-pong buffers hold [128 t][128 d] hi/lo chunks (K or V).
#define QMAT 8192
#define Q_OFF 0
#define B0_OFF 65536
#define B1_OFF 131072
#define P_OFF 196608
#define RMAX_OFF 229376
#define RSUM_OFF 230400
#define ATT_SMEM 231424
#define NKV (TT/128)    // 16

__global__ __launch_bounds__(256, 1) void attn_kernel()
{
    extern __shared__ char sm[];
    const uint32_t sb = smem_u32(sm);
    const int tid = threadIdx.x, lane = tid & 31, wid = tid >> 5;
    const int wm = wid >> 2, wn = wid & 3;             // 2m x 4n
    const int bh = blockIdx.y, m0 = blockIdx.x * 64;

    auto load_kv = [&](const __nv_bfloat16* __restrict__ srcH,
                       const __nv_bfloat16* __restrict__ srcL,
                       int tile, int c, uint32_t bufoff) {
        #pragma unroll
        for (int dh = 0; dh < 2; dh++) {
            #pragma unroll
            for (int i = 0; i < 4; i++) {
                int ci = tid + i * 256;
                int r = ci >> 3, cc = ci & 7;
                size_t g = ((size_t)bh * TT + tile * 128 + r) * DH + c * 128 + dh * 64 + cc * 8;
                uint32_t so = SWZ(r * 128 + cc * 16);
                CP16(sb + bufoff + dh * 32768 + so,         srcH + g);
                CP16(sb + bufoff + dh * 32768 + 16384 + so, srcL + g);
            }
        }
    };

    #pragma unroll
    for (int i = 0; i < 16; i++) {
        int ci = tid + i * 256;
        int mat = ci >> 9, w = ci & 511, r = w >> 3, c = w & 7;
        int j = mat >> 1, hl = mat & 1;
        size_t g = ((size_t)bh * TT + m0 + r) * DH + j * 64 + c * 8;
        const __nv_bfloat16* src = hl ? g_ql : g_qh;
        CP16(sb + Q_OFF + mat * QMAT + SWZ(r * 128 + c * 16), src + g);
    }
    load_kv(g_kh, g_kl, 0, 0, B0_OFF); CP_COMMIT();
    load_kv(g_kh, g_kl, 0, 1, B1_OFF); CP_COMMIT();

    const int a_rl = (lane & 7) + ((lane >> 3) & 1) * 8;
    const int a_kb = ((lane >> 4) & 1) * 16;
    const int b_rl = (lane & 7) + (lane >= 16 ? 8 : 0);
    const int b_kb = ((lane >> 3) & 1) * 16;
    const int v_rl = (lane & 7) + ((lane >> 3) & 1) * 8;
    const int v_cb = ((lane >> 4) & 1) * 16;

    float oacc[16][4] = {};      // [phase*8 + mf*4 + g16*2 + f8]
    float sacc[8][4];            // [mf*4 + g16*2 + f8]
    float mrun[2][2], lrun[2][2];
    #pragma unroll
    for (int i = 0; i < 2; i++)
        #pragma unroll
        for (int j = 0; j < 2; j++) { mrun[i][j] = -1e30f; lrun[i][j] = 0.f; }

    const int rl = lane >> 2;           // row within m16 (0..7)
    float* rmax = (float*)(sm + RMAX_OFF);   // [4 wn][64 rows]
    float* rsum = (float*)(sm + RSUM_OFF);

    for (int tile = 0; tile < NKV; tile++) {
        #pragma unroll
        for (int f = 0; f < 8; f++) { sacc[f][0]=0.f; sacc[f][1]=0.f; sacc[f][2]=0.f; sacc[f][3]=0.f; }

        // ---- QK: 2 phases over d-halves; warp tile m32 x t32 ----
        #pragma unroll
        for (int c = 0; c < 2; c++) {
            CP_WAIT1(); __syncthreads();
            const uint32_t kb_buf = sb + (c ? B1_OFF : B0_OFF);
            #pragma unroll
            for (int ks = 0; ks < 8; ks++) {
                const uint32_t qm = sb + Q_OFF + (c * 2 + (ks >> 2)) * 16384;
                const uint32_t km = kb_buf + (ks >> 2) * 32768;
                uint32_t qh2[2][4], ql2[2][4], kh[2][4], kl[2][4];
                #pragma unroll
                for (int mf = 0; mf < 2; mf++) {
                    uint32_t ao = SWZ((wm * 32 + mf * 16 + a_rl) * 128 + (ks & 3) * 32 + a_kb);
                    LDSM4(qh2[mf], qm + ao);
                    LDSM4(ql2[mf], qm + 8192 + ao);
                }
                #pragma unroll
                for (int g = 0; g < 2; g++) {
                    uint32_t bo = SWZ((wn * 32 + g * 16 + b_rl) * 128 + (ks & 3) * 32 + b_kb);
                    LDSM4(kh[g], km + bo);
                    LDSM4(kl[g], km + 16384 + bo);
                }
                #pragma unroll
                for (int mf = 0; mf < 2; mf++)
                    #pragma unroll
                    for (int g = 0; g < 2; g++) {
                        MMA16816(sacc[mf*4+g*2],   qh2[mf], kh[g][0], kh[g][1]);
                        MMA16816(sacc[mf*4+g*2+1], qh2[mf], kh[g][2], kh[g][3]);
                    }
                #pragma unroll
                for (int mf = 0; mf < 2; mf++)
                    #pragma unroll
                    for (int g = 0; g < 2; g++) {
                        MMA16816(sacc[mf*4+g*2],   qh2[mf], kl[g][0], kl[g][1]);
                        MMA16816(sacc[mf*4+g*2+1], qh2[mf], kl[g][2], kl[g][3]);
                    }
                #pragma unroll
                for (int mf = 0; mf < 2; mf++)
                    #pragma unroll
                    for (int g = 0; g < 2; g++) {
                        MMA16816(sacc[mf*4+g*2],   ql2[mf], kh[g][0], kh[g][1]);
                        MMA16816(sacc[mf*4+g*2+1], ql2[mf], kh[g][2], kh[g][3]);
                    }
            }
            __syncthreads();
            load_kv(g_vh, g_vl, tile, c, c ? B1_OFF : B0_OFF);
            CP_COMMIT();
        }

        // ---- online softmax (log2 units) ----
        float mx[2][2];
        #pragma unroll
        for (int mf = 0; mf < 2; mf++) { mx[mf][0] = -1e30f; mx[mf][1] = -1e30f; }
        #pragma unroll
        for (int f = 0; f < 8; f++) {
            const int mf = f >> 2;
            mx[mf][0] = fmaxf(mx[mf][0], fmaxf(sacc[f][0], sacc[f][1]));
            mx[mf][1] = fmaxf(mx[mf][1], fmaxf(sacc[f][2], sacc[f][3]));
        }
        #pragma unroll
        for (int mf = 0; mf < 2; mf++)
            #pragma unroll
            for (int hf = 0; hf < 2; hf++) {
                mx[mf][hf] = fmaxf(mx[mf][hf], __shfl_xor_sync(0xffffffffu, mx[mf][hf], 1));
                mx[mf][hf] = fmaxf(mx[mf][hf], __shfl_xor_sync(0xffffffffu, mx[mf][hf], 2));
            }
        if ((lane & 3) == 0) {
            #pragma unroll
            for (int mf = 0; mf < 2; mf++)
                #pragma unroll
                for (int hf = 0; hf < 2; hf++)
                    rmax[wn * 64 + wm * 32 + mf * 16 + hf * 8 + rl] = mx[mf][hf];
        }
        __syncthreads();

        float aa[2][2];
        #pragma unroll
        for (int mf = 0; mf < 2; mf++)
            #pragma unroll
            for (int hf = 0; hf < 2; hf++) {
                const int row = wm * 32 + mf * 16 + hf * 8 + rl;
                float mn = mrun[mf][hf];
                #pragma unroll
                for (int w = 0; w < 4; w++) mn = fmaxf(mn, rmax[w * 64 + row]);
                aa[mf][hf] = exp2f(mrun[mf][hf] - mn);
                mrun[mf][hf] = mn;
            }

        float ss[2][2] = {};
        #pragma unroll
        for (int f = 0; f < 8; f++) {
            const int mf = f >> 2;
            sacc[f][0] = exp2f(sacc[f][0] - mrun[mf][0]);
            sacc[f][1] = exp2f(sacc[f][1] - mrun[mf][0]);
            sacc[f][2] = exp2f(sacc[f][2] - mrun[mf][1]);
            sacc[f][3] = exp2f(sacc[f][3] - mrun[mf][1]);
            ss[mf][0] += sacc[f][0] + sacc[f][1];
            ss[mf][1] += sacc[f][2] + sacc[f][3];
        }
        #pragma unroll
        for (int mf = 0; mf < 2; mf++)
            #pragma unroll
            for (int hf = 0; hf < 2; hf++) {
                ss[mf][hf] += __shfl_xor_sync(0xffffffffu, ss[mf][hf], 1);
                ss[mf][hf] += __shfl_xor_sync(0xffffffffu, ss[mf][hf], 2);
            }
        if ((lane & 3) == 0) {
            #pragma unroll
            for (int mf = 0; mf < 2; mf++)
                #pragma unroll
                for (int hf = 0; hf < 2; hf++)
                    rsum[wn * 64 + wm * 32 + mf * 16 + hf * 8 + rl] = ss[mf][hf];
        }

        // rescale O accumulators
        #pragma unroll
        for (int f = 0; f < 16; f++) {
            const int mf = (f >> 2) & 1;
            oacc[f][0] *= aa[mf][0]; oacc[f][1] *= aa[mf][0];
            oacc[f][2] *= aa[mf][1]; oacc[f][3] *= aa[mf][1];
        }

        // P -> smem: row = wm*32+mf*16+hf*8+rl, col = wn*32+g*16+f8*8+(lane&3)*2
        {
            const int th = wn >> 1, cbase = (wn & 1) * 32;
            #pragma unroll
            for (int f = 0; f < 8; f++) {
                const int mf = f >> 2, g = (f >> 1) & 1, f8 = f & 1;
                const int colm = cbase + g * 16 + f8 * 8 + (lane & 3) * 2;
                const uint32_t pmo = P_OFF + th * 16384;
                __nv_bfloat16 h0, l0, h1, l1;
                split2(sacc[f][0], h0, l0); split2(sacc[f][1], h1, l1);
                __nv_bfloat162 ph; ph.x = h0; ph.y = h1;
                __nv_bfloat162 pl; pl.x = l0; pl.y = l1;
                uint32_t off = SWZ((wm * 32 + mf * 16 + rl) * 128 + colm * 2);
                *(__nv_bfloat162*)(sm + pmo + off)        = ph;
                *(__nv_bfloat162*)(sm + pmo + 8192 + off) = pl;
                split2(sacc[f][2], h0, l0); split2(sacc[f][3], h1, l1);
                ph.x = h0; ph.y = h1; pl.x = l0; pl.y = l1;
                off = SWZ((wm * 32 + mf * 16 + 8 + rl) * 128 + colm * 2);
                *(__nv_bfloat162*)(sm + pmo + off)        = ph;
                *(__nv_bfloat162*)(sm + pmo + 8192 + off) = pl;
            }
        }
        __syncthreads();

        #pragma unroll
        for (int mf = 0; mf < 2; mf++)
            #pragma unroll
            for (int hf = 0; hf < 2; hf++) {
                const int row = wm * 32 + mf * 16 + hf * 8 + rl;
                float s = 0.f;
                #pragma unroll
                for (int w = 0; w < 4; w++) s += rsum[w * 64 + row];
                lrun[mf][hf] = lrun[mf][hf] * aa[mf][hf] + s;
            }

        // ---- AV: 2 phases over d-halves; warp tile m32 x d32 ----
        #pragma unroll
        for (int c = 0; c < 2; c++) {
            CP_WAIT1(); __syncthreads();
            const uint32_t v_buf = sb + (c ? B1_OFF : B0_OFF) + (wn >> 1) * 32768;
            const int vcb = (wn & 1) * 64;   // byte offset of warp's d32 within 64-d mat
            #pragma unroll
            for (int ks = 0; ks < 8; ks++) {
                const uint32_t pm = sb + P_OFF + (ks >> 2) * 16384;
                uint32_t ph2[2][4], pl2[2][4], vh[2][4], vl[2][4];
                #pragma unroll
                for (int mf = 0; mf < 2; mf++) {
                    uint32_t ao = SWZ((wm * 32 + mf * 16 + a_rl) * 128 + (ks & 3) * 32 + a_kb);
                    LDSM4(ph2[mf], pm + ao);
                    LDSM4(pl2[mf], pm + 8192 + ao);
                }
                const uint32_t vrow = ks * 16 + v_rl;
                #pragma unroll
                for (int g = 0; g < 2; g++) {
                    uint32_t bo = SWZ(vrow * 128 + vcb + g * 32 + v_cb);
                    LDSM4T(vh[g], v_buf + bo);
                    LDSM4T(vl[g], v_buf + 16384 + bo);
                }
                #pragma unroll
                for (int mf = 0; mf < 2; mf++)
                    #pragma unroll
                    for (int g = 0; g < 2; g++) {
                        MMA16816(oacc[c*8+mf*4+g*2],   ph2[mf], vh[g][0], vh[g][1]);
                        MMA16816(oacc[c*8+mf*4+g*2+1], ph2[mf], vh[g][2], vh[g][3]);
                    }
                #pragma unroll
                for (int mf = 0; mf < 2; mf++)
                    #pragma unroll
                    for (int g = 0; g < 2; g++) {
                        MMA16816(oacc[c*8+mf*4+g*2],   ph2[mf], vl[g][0], vl[g][1]);
                        MMA16816(oacc[c*8+mf*4+g*2+1], ph2[mf], vl[g][2], vl[g][3]);
                    }
                #pragma unroll
                for (int mf = 0; mf < 2; mf++)
                    #pragma unroll
                    for (int g = 0; g < 2; g++) {
                        MMA16816(oacc[c*8+mf*4+g*2],   pl2[mf], vh[g][0], vh[g][1]);
                        MMA16816(oacc[c*8+mf*4+g*2+1], pl2[mf], vh[g][2], vh[g][3]);
                    }
            }
            __syncthreads();
            if (tile + 1 < NKV) load_kv(g_kh, g_kl, tile + 1, c, c ? B1_OFF : B0_OFF);
            CP_COMMIT();
        }
    }

    // ---- epilogue: normalize + write hi/lo for output projection ----
    const int bb = bh / HH, hh = bh % HH;
    #pragma unroll
    for (int f = 0; f < 16; f++) {
        const int c = f >> 3, mf = (f >> 2) & 1, g = (f >> 1) & 1, f8 = f & 1;
        const int d = c * 128 + wn * 32 + g * 16 + f8 * 8 + (lane & 3) * 2;
        #pragma unroll
        for (int hf = 0; hf < 2; hf++) {
            const int t = m0 + wm * 32 + mf * 16 + hf * 8 + rl;
            const float inv = 1.f / lrun[mf][hf];
            float v0 = oacc[f][hf*2] * inv, v1 = oacc[f][hf*2+1] * inv;
            size_t o = ((size_t)t * BB + bb) * FD + hh * DH + d;
            __nv_bfloat16 h0, l0, h1, l1; split2(v0, h0, l0); split2(v1, h1, l1);
            __nv_bfloat162 ph; ph.x = h0; ph.y = h1;
            __nv_bfloat162 pl; pl.x = l0; pl.y = l1;
            *(__nv_bfloat162*)(g_oh + o) = ph;
            *(__nv_bfloat162*)(g_ol + o) = pl;
        }
    }
}

// ------------------------------ helper kernels ------------------------------
__global__ __launch_bounds__(256) void split_kernel(
    const float* __restrict__ in, __nv_bfloat16* __restrict__ h,
    __nv_bfloat16* __restrict__ l, int n4)
{
    int i = blockIdx.x * 256 + threadIdx.x;
    if (i >= n4) return;
    float4 v = *(const float4*)(in + (size_t)i * 4);
    __nv_bfloat16 h0,l0,h1,l1,h2,l2,h3,l3;
    split2(v.x,h0,l0); split2(v.y,h1,l1); split2(v.z,h2,l2); split2(v.w,h3,l3);
    __nv_bfloat162 a; a.x=h0; a.y=h1; __nv_bfloat162 b; b.x=h2; b.y=h3;
    __nv_bfloat162 c; c.x=l0; c.y=l1; __nv_bfloat162 d; d.x=l2; d.y=l3;
    *(__nv_bfloat162*)(h + (size_t)i*4)     = a;
    *(__nv_bfloat162*)(h + (size_t)i*4 + 2) = b;
    *(__nv_bfloat162*)(l + (size_t)i*4)     = c;
    *(__nv_bfloat162*)(l + (size_t)i*4 + 2) = d;
}

__global__ __launch_bounds__(256) void split_w_kernel(
    const float* __restrict__ w0, const float* __restrict__ w1,
    const float* __restrict__ w2, const float* __restrict__ w3)
{
    const int which = blockIdx.y;
    const float* in = which == 0 ? w0 : which == 1 ? w1 : which == 2 ? w2 : w3;
    __nv_bfloat16* h = which == 0 ? g_wqh : which == 1 ? g_wkh : which == 2 ? g_wvh : g_woh;
    __nv_bfloat16* l = which == 0 ? g_wql : which == 1 ? g_wkl : which == 2 ? g_wvl : g_wol;
    int i = blockIdx.x * 256 + threadIdx.x;
    if (i >= FD*FD/4) return;
    float4 v = *(const float4*)(in + (size_t)i * 4);
    __nv_bfloat16 a0,b0,a1,b1,a2,b2,a3,b3;
    split2(v.x,a0,b0); split2(v.y,a1,b1); split2(v.z,a2,b2); split2(v.w,a3,b3);
    __nv_bfloat162 p; p.x=a0; p.y=a1; __nv_bfloat162 q; q.x=a2; q.y=a3;
    __nv_bfloat162 r; r.x=b0; r.y=b1; __nv_bfloat162 s; s.x=b2; s.y=b3;
    *(__nv_bfloat162*)(h + (size_t)i*4)     = p;
    *(__nv_bfloat162*)(h + (size_t)i*4 + 2) = q;
    *(__nv_bfloat162*)(l + (size_t)i*4)     = r;
    *(__nv_bfloat162*)(l + (size_t)i*4 + 2) = s;
}

// --------------------------------- launch ----------------------------------
extern "C" void kernel_launch(void* const* d_in, const int* in_sizes, int n_in,
                              void* d_out, int out_size)
{
    const float* x  = (const float*)d_in[0];
    const float* Wq = (const float*)d_in[1];
    const float* bq = (const float*)d_in[2];
    const float* Wk = (const float*)d_in[3];
    const float* bk = (const float*)d_in[4];
    const float* Wv = (const float*)d_in[5];
    const float* bv = (const float*)d_in[6];
    const float* Wo = (const float*)d_in[7];
    const float* bo = (const float*)d_in[8];
    float* out = (float*)d_out;

    cudaFuncSetAttribute(gemm_fused,  cudaFuncAttributeMaxDynamicSharedMemorySize, SMEM_BYTES);
    cudaFuncSetAttribute(attn_kernel, cudaFuncAttributeMaxDynamicSharedMemorySize, ATT_SMEM);

    __nv_bfloat16 *xh, *xl, *oh, *ol;
    cudaGetSymbolAddress((void**)&xh, g_xh);  cudaGetSymbolAddress((void**)&xl, g_xl);
    cudaGetSymbolAddress((void**)&oh, g_oh);  cudaGetSymbolAddress((void**)&ol, g_ol);

    // 0: x split
    split_kernel<<<(MROWS*FD/4 + 255)/256, 256>>>(x, xh, xl, MROWS*FD/4);
    // 1: W splits
    dim3 gW((FD*FD/4 + 255)/256, 4);
    split_w_kernel<<<gW, 256>>>(Wq, Wk, Wv, Wo);
    // 2: fused QKV projection (z = 0,1,2)
    dim3 gQKV(MROWS/BM, FD/BN, 3);
    gemm_fused<<<gQKV, 512, SMEM_BYTES>>>(xh, xl, 0, bq, bk, bv, bo, out);
    // 3: fused flash attention
    dim3 gA(TT/64, NBH);
    attn_kernel<<<gA, 256, ATT_SMEM>>>();
    // 4: output projection (mode 3)
    dim3 gO(MROWS/BM, FD/BN, 1);
    gemm_fused<<<gO, 512, SMEM_BYTES>>>(oh, ol, 3, bq, bk, bv, bo, out);
}

// round 10
// speedup vs baseline: 1.0816x; 1.0816x over previous
#include <cuda_runtime.h>
#include <cuda_bf16.h>
#include <cuda_fp16.h>
#include <cstdint>

#define TT 2048
#define BB 8
#define FD 768
#define HH 3
#define DH 256
#define MROWS (TT*BB)      // 16384
#define NBH (BB*HH)        // 24

// ------------------------- device scratch (static) -------------------------
__device__ __align__(16) __nv_bfloat16 g_xh[MROWS*FD], g_xl[MROWS*FD];
__device__ __align__(16) __nv_bfloat16 g_wqh[FD*FD], g_wql[FD*FD];
__device__ __align__(16) __nv_bfloat16 g_wkh[FD*FD], g_wkl[FD*FD];
__device__ __align__(16) __nv_bfloat16 g_wvh[FD*FD], g_wvl[FD*FD];
__device__ __align__(16) __nv_bfloat16 g_woh[FD*FD], g_wol[FD*FD];
__device__ __align__(16) __nv_bfloat16 g_qh[NBH*TT*DH], g_ql[NBH*TT*DH];
__device__ __align__(16) __nv_bfloat16 g_kh[NBH*TT*DH], g_kl[NBH*TT*DH];
__device__ __align__(16) __half        g_vh[NBH*TT*DH], g_vl[NBH*TT*DH];   // (BH,T,D) fp16
__device__ __align__(16) __nv_bfloat16 g_oh[MROWS*FD], g_ol[MROWS*FD];

// ------------------------------ PTX helpers --------------------------------
__device__ __forceinline__ uint32_t smem_u32(const void* p) {
    uint32_t a;
    asm("{ .reg .u64 t; cvta.to.shared.u64 t, %1; cvt.u32.u64 %0, t; }" : "=r"(a) : "l"(p));
    return a;
}
#define CP16(dst, src) \
    asm volatile("cp.async.cg.shared.global [%0], [%1], 16;" :: "r"(dst), "l"(src) : "memory")
#define CP_COMMIT() asm volatile("cp.async.commit_group;" ::: "memory")
#define CP_WAIT1()  asm volatile("cp.async.wait_group 1;" ::: "memory")

#define LDSM4(r, addr) \
    asm volatile("ldmatrix.sync.aligned.m8n8.x4.shared.b16 {%0,%1,%2,%3}, [%4];" \
        : "=r"((r)[0]), "=r"((r)[1]), "=r"((r)[2]), "=r"((r)[3]) : "r"(addr))
#define LDSM4T(r, addr) \
    asm volatile("ldmatrix.sync.aligned.m8n8.x4.trans.shared.b16 {%0,%1,%2,%3}, [%4];" \
        : "=r"((r)[0]), "=r"((r)[1]), "=r"((r)[2]), "=r"((r)[3]) : "r"(addr))

#define MMA16816(d, a, b0v, b1v) \
    asm volatile("mma.sync.aligned.m16n8k16.row.col.f32.bf16.bf16.f32 " \
        "{%0,%1,%2,%3}, {%4,%5,%6,%7}, {%8,%9}, {%0,%1,%2,%3};" \
        : "+f"((d)[0]), "+f"((d)[1]), "+f"((d)[2]), "+f"((d)[3]) \
        : "r"((a)[0]), "r"((a)[1]), "r"((a)[2]), "r"((a)[3]), "r"(b0v), "r"(b1v))

#define MMA16816H(d, a, b0v, b1v) \
    asm volatile("mma.sync.aligned.m16n8k16.row.col.f32.f16.f16.f32 " \
        "{%0,%1,%2,%3}, {%4,%5,%6,%7}, {%8,%9}, {%0,%1,%2,%3};" \
        : "+f"((d)[0]), "+f"((d)[1]), "+f"((d)[2]), "+f"((d)[3]) \
        : "r"((a)[0]), "r"((a)[1]), "r"((a)[2]), "r"((a)[3]), "r"(b0v), "r"(b1v))

#define SWZ(o) ((uint32_t)(o) ^ ((((uint32_t)(o)) >> 3) & 0x70))

__device__ __forceinline__ void split2(float v, __nv_bfloat16& h, __nv_bfloat16& l) {
    h = __float2bfloat16(v);
    l = __float2bfloat16(v - __bfloat162float(h));
}
__device__ __forceinline__ void split2h(float v, __half& h, __half& l) {
    h = __float2half(v);
    l = __float2half(v - __half2float(h));
}

// ------------- split-bf16 GEMM via mma.sync, 512 threads, 256x128 -----------
#define BM 256
#define BN 128
#define BK 32
#define ROWB 80
#define MAT_A (256*ROWB)
#define MAT_B (128*ROWB)
#define OFF_AH 0
#define OFF_AL MAT_A
#define OFF_BH (2*MAT_A)
#define OFF_BL (2*MAT_A + MAT_B)
#define STAGE_BYTES (2*MAT_A + 2*MAT_B)
#define NSTAGE 3
#define SMEM_BYTES (NSTAGE*STAGE_BYTES)   // 184320

#define QSCALE 0.1803368801111204f    // 0.125 * log2(e)

// mode = blockIdx.z + mode_base: 0=Q, 1=K, 2=V(fp16 out), 3=out-proj
__global__ __launch_bounds__(512, 1) void gemm_fused(
    const __nv_bfloat16* __restrict__ Ah, const __nv_bfloat16* __restrict__ Al,
    int mode_base,
    const float* __restrict__ bq, const float* __restrict__ bk,
    const float* __restrict__ bv, const float* __restrict__ bo,
    float* __restrict__ outF)
{
    extern __shared__ char smem[];
    const uint32_t sb = smem_u32(smem);

    const int tid = threadIdx.x;
    const int wid = tid >> 5, lane = tid & 31;
    const int wm = wid >> 2, wn = wid & 3;
    const int m0 = blockIdx.x * BM, n0 = blockIdx.y * BN;
    const int mode = blockIdx.z + mode_base;

    const __nv_bfloat16* Bh = mode == 0 ? g_wqh : mode == 1 ? g_wkh : mode == 2 ? g_wvh : g_woh;
    const __nv_bfloat16* Bl = mode == 0 ? g_wql : mode == 1 ? g_wkl : mode == 2 ? g_wvl : g_wol;
    const float* bias = mode == 0 ? bq : mode == 1 ? bk : mode == 2 ? bv : bo;
    const int K = FD;

    float acc[4][4][4] = {};

    const int ra0 = tid >> 2,          ca0 = tid & 3;
    const int ra1 = (tid + 512) >> 2,  ca1 = (tid + 512) & 3;
    const int rb  = tid >> 2,          cb  = tid & 3;

    auto load_stage = [&](int kb, int s) {
        const uint32_t st = sb + s * STAGE_BYTES;
        {
            size_t g = (size_t)(m0 + ra0) * K + kb * BK + ca0 * 8;
            uint32_t so = ra0 * ROWB + ca0 * 16;
            CP16(st + OFF_AH + so, Ah + g);
            CP16(st + OFF_AL + so, Al + g);
        }
        {
            size_t g = (size_t)(m0 + ra1) * K + kb * BK + ca1 * 8;
            uint32_t so = ra1 * ROWB + ca1 * 16;
            CP16(st + OFF_AH + so, Ah + g);
            CP16(st + OFF_AL + so, Al + g);
        }
        {
            size_t g = (size_t)(n0 + rb) * K + kb * BK + cb * 8;
            uint32_t so = rb * ROWB + cb * 16;
            CP16(st + OFF_BH + so, Bh + g);
            CP16(st + OFF_BL + so, Bl + g);
        }
    };

    const int NKB = K / BK;
    load_stage(0, 0); CP_COMMIT();
    load_stage(1, 1); CP_COMMIT();

    const int a_row = wm * 64 + (lane & 7) + ((lane >> 3) & 1) * 8;
    const int a_kb  = ((lane >> 4) & 1) * 16;
    const int b_row = wn * 32 + (lane & 7) + (lane >= 16 ? 8 : 0);
    const int b_kb  = ((lane >> 3) & 1) * 16;

    for (int kb = 0; kb < NKB; kb++) {
        CP_WAIT1();
        __syncthreads();
        if (kb + 2 < NKB) load_stage(kb + 2, (kb + 2) % NSTAGE);
        CP_COMMIT();

        const uint32_t st = sb + (kb % NSTAGE) * STAGE_BYTES;
        #pragma unroll
        for (int ks = 0; ks < 2; ks++) {
            uint32_t bhf[2][4], blf[2][4];
            #pragma unroll
            for (int np = 0; np < 2; np++) {
                uint32_t bo2 = (b_row + np * 16) * ROWB + b_kb + ks * 32;
                LDSM4(bhf[np], st + OFF_BH + bo2);
                LDSM4(blf[np], st + OFF_BL + bo2);
            }
            #pragma unroll
            for (int mf = 0; mf < 4; mf++) {
                uint32_t ah[4], al[4];
                uint32_t ao = (a_row + mf * 16) * ROWB + a_kb + ks * 32;
                LDSM4(ah, st + OFF_AH + ao);
                LDSM4(al, st + OFF_AL + ao);
                #pragma unroll
                for (int np = 0; np < 2; np++) {
                    MMA16816(acc[mf][np*2],   ah, bhf[np][0], bhf[np][1]);
                    MMA16816(acc[mf][np*2+1], ah, bhf[np][2], bhf[np][3]);
                }
                #pragma unroll
                for (int np = 0; np < 2; np++) {
                    MMA16816(acc[mf][np*2],   ah, blf[np][0], blf[np][1]);
                    MMA16816(acc[mf][np*2+1], ah, blf[np][2], blf[np][3]);
                }
                #pragma unroll
                for (int np = 0; np < 2; np++) {
                    MMA16816(acc[mf][np*2],   al, bhf[np][0], bhf[np][1]);
                    MMA16816(acc[mf][np*2+1], al, bhf[np][2], bhf[np][3]);
                }
            }
        }
        __syncthreads();
    }

    const int mrow = m0 + wm * 64 + (lane >> 2);
    const int ncol = n0 + wn * 32 + (lane & 3) * 2;
    const float oscale = (mode == 0) ? QSCALE : 1.0f;

    #pragma unroll
    for (int mf = 0; mf < 4; mf++) {
        #pragma unroll
        for (int half = 0; half < 2; half++) {
            const int m = mrow + mf * 16 + half * 8;
            #pragma unroll
            for (int nf = 0; nf < 4; nf++) {
                const int n = ncol + nf * 8;
                float v0 = (acc[mf][nf][half * 2]     + __ldg(&bias[n]))     * oscale;
                float v1 = (acc[mf][nf][half * 2 + 1] + __ldg(&bias[n + 1])) * oscale;

                if (mode <= 1) {           // Q/K: (BH,T,D) bf16 hi/lo
                    __nv_bfloat16* oH = mode == 0 ? g_qh : g_kh;
                    __nv_bfloat16* oL = mode == 0 ? g_ql : g_kl;
                    const int t = m >> 3, b = m & 7, h = n >> 8, d = n & 255;
                    size_t o = ((size_t)(b * HH + h) * TT + t) * DH + d;
                    __nv_bfloat16 h0, l0, h1, l1; split2(v0, h0, l0); split2(v1, h1, l1);
                    __nv_bfloat162 ph; ph.x = h0; ph.y = h1;
                    __nv_bfloat162 pl; pl.x = l0; pl.y = l1;
                    *(__nv_bfloat162*)(oH + o) = ph;
                    *(__nv_bfloat162*)(oL + o) = pl;
                } else if (mode == 2) {    // V: (BH,T,D) fp16 hi/lo
                    const int t = m >> 3, b = m & 7, h = n >> 8, d = n & 255;
                    size_t o = ((size_t)(b * HH + h) * TT + t) * DH + d;
                    __half h0, l0, h1, l1; split2h(v0, h0, l0); split2h(v1, h1, l1);
                    __half2 ph; ph.x = h0; ph.y = h1;
                    __half2 pl; pl.x = l0; pl.y = l1;
                    *(__half2*)(g_vh + o) = ph;
                    *(__half2*)(g_vl + o) = pl;
                } else {                   // out projection: fp32 (T*B, F)
                    size_t o = (size_t)m * FD + n;
                    float2 f; f.x = v0; f.y = v1;
                    *(float2*)(outF + o) = f;
                }
            }
        }
    }
}

// --------------------------- fused flash attention --------------------------
// CTA: 64 q-rows of one bh; 16 kv-tiles of 128 t. 256 threads, warps 2m x 4n.
// QK: bf16 3-term, warp tile m32 x t32.  AV: fp16 2-term (P single + V hi/lo),
// warp tile m32 x d32.  P stored fp16 (two 8KB mats, one per t-half).
// Two 64KB ping-pong buffers hold [128 t][128 d] hi/lo chunks (K bf16 or V fp16).
#define QMAT 8192
#define Q_OFF 0
#define B0_OFF 65536
#define B1_OFF 131072
#define P_OFF 196608
#define RMAX_OFF 212992
#define RSUM_OFF 214016
#define ATT_SMEM 215040
#define NKV (TT/128)    // 16

__global__ __launch_bounds__(256, 1) void attn_kernel()
{
    extern __shared__ char sm[];
    const uint32_t sb = smem_u32(sm);
    const int tid = threadIdx.x, lane = tid & 31, wid = tid >> 5;
    const int wm = wid >> 2, wn = wid & 3;             // 2m x 4n
    const int bh = blockIdx.y, m0 = blockIdx.x * 64;

    // K chunk (bf16) — [128t x 64d x 2dh] hi/lo into buffer
    auto load_k = [&](int tile, int c, uint32_t bufoff) {
        #pragma unroll
        for (int dh = 0; dh < 2; dh++) {
            #pragma unroll
            for (int i = 0; i < 4; i++) {
                int ci = tid + i * 256;
                int r = ci >> 3, cc = ci & 7;
                size_t g = ((size_t)bh * TT + tile * 128 + r) * DH + c * 128 + dh * 64 + cc * 8;
                uint32_t so = SWZ(r * 128 + cc * 16);
                CP16(sb + bufoff + dh * 32768 + so,         g_kh + g);
                CP16(sb + bufoff + dh * 32768 + 16384 + so, g_kl + g);
            }
        }
    };
    // V chunk (fp16) — identical byte layout
    auto load_v = [&](int tile, int c, uint32_t bufoff) {
        #pragma unroll
        for (int dh = 0; dh < 2; dh++) {
            #pragma unroll
            for (int i = 0; i < 4; i++) {
                int ci = tid + i * 256;
                int r = ci >> 3, cc = ci & 7;
                size_t g = ((size_t)bh * TT + tile * 128 + r) * DH + c * 128 + dh * 64 + cc * 8;
                uint32_t so = SWZ(r * 128 + cc * 16);
                CP16(sb + bufoff + dh * 32768 + so,         g_vh + g);
                CP16(sb + bufoff + dh * 32768 + 16384 + so, g_vl + g);
            }
        }
    };

    #pragma unroll
    for (int i = 0; i < 16; i++) {
        int ci = tid + i * 256;
        int mat = ci >> 9, w = ci & 511, r = w >> 3, c = w & 7;
        int j = mat >> 1, hl = mat & 1;
        size_t g = ((size_t)bh * TT + m0 + r) * DH + j * 64 + c * 8;
        const __nv_bfloat16* src = hl ? g_ql : g_qh;
        CP16(sb + Q_OFF + mat * QMAT + SWZ(r * 128 + c * 16), src + g);
    }
    load_k(0, 0, B0_OFF); CP_COMMIT();
    load_k(0, 1, B1_OFF); CP_COMMIT();

    const int a_rl = (lane & 7) + ((lane >> 3) & 1) * 8;
    const int a_kb = ((lane >> 4) & 1) * 16;
    const int b_rl = (lane & 7) + (lane >= 16 ? 8 : 0);
    const int b_kb = ((lane >> 3) & 1) * 16;
    const int v_rl = (lane & 7) + ((lane >> 3) & 1) * 8;
    const int v_cb = ((lane >> 4) & 1) * 16;

    float oacc[16][4] = {};      // [phase*8 + mf*4 + g16*2 + f8]
    float sacc[8][4];            // [mf*4 + g16*2 + f8]
    float mrun[2][2], lrun[2][2];
    #pragma unroll
    for (int i = 0; i < 2; i++)
        #pragma unroll
        for (int j = 0; j < 2; j++) { mrun[i][j] = -1e30f; lrun[i][j] = 0.f; }

    const int rl = lane >> 2;
    float* rmax = (float*)(sm + RMAX_OFF);   // [4 wn][64 rows]
    float* rsum = (float*)(sm + RSUM_OFF);

    for (int tile = 0; tile < NKV; tile++) {
        #pragma unroll
        for (int f = 0; f < 8; f++) { sacc[f][0]=0.f; sacc[f][1]=0.f; sacc[f][2]=0.f; sacc[f][3]=0.f; }

        // ---- QK: 2 phases over d-halves; warp tile m32 x t32 (bf16 3-term) ----
        #pragma unroll
        for (int c = 0; c < 2; c++) {
            CP_WAIT1(); __syncthreads();
            const uint32_t kb_buf = sb + (c ? B1_OFF : B0_OFF);
            #pragma unroll
            for (int ks = 0; ks < 8; ks++) {
                const uint32_t qm = sb + Q_OFF + (c * 2 + (ks >> 2)) * 16384;
                const uint32_t km = kb_buf + (ks >> 2) * 32768;
                uint32_t qh2[2][4], ql2[2][4], kh[2][4], kl[2][4];
                #pragma unroll
                for (int mf = 0; mf < 2; mf++) {
                    uint32_t ao = SWZ((wm * 32 + mf * 16 + a_rl) * 128 + (ks & 3) * 32 + a_kb);
                    LDSM4(qh2[mf], qm + ao);
                    LDSM4(ql2[mf], qm + 8192 + ao);
                }
                #pragma unroll
                for (int g = 0; g < 2; g++) {
                    uint32_t bo = SWZ((wn * 32 + g * 16 + b_rl) * 128 + (ks & 3) * 32 + b_kb);
                    LDSM4(kh[g], km + bo);
                    LDSM4(kl[g], km + 16384 + bo);
                }
                #pragma unroll
                for (int mf = 0; mf < 2; mf++)
                    #pragma unroll
                    for (int g = 0; g < 2; g++) {
                        MMA16816(sacc[mf*4+g*2],   qh2[mf], kh[g][0], kh[g][1]);
                        MMA16816(sacc[mf*4+g*2+1], qh2[mf], kh[g][2], kh[g][3]);
                    }
                #pragma unroll
                for (int mf = 0; mf < 2; mf++)
                    #pragma unroll
                    for (int g = 0; g < 2; g++) {
                        MMA16816(sacc[mf*4+g*2],   qh2[mf], kl[g][0], kl[g][1]);
                        MMA16816(sacc[mf*4+g*2+1], qh2[mf], kl[g][2], kl[g][3]);
                    }
                #pragma unroll
                for (int mf = 0; mf < 2; mf++)
                    #pragma unroll
                    for (int g = 0; g < 2; g++) {
                        MMA16816(sacc[mf*4+g*2],   ql2[mf], kh[g][0], kh[g][1]);
                        MMA16816(sacc[mf*4+g*2+1], ql2[mf], kh[g][2], kh[g][3]);
                    }
            }
            __syncthreads();
            load_v(tile, c, c ? B1_OFF : B0_OFF);
            CP_COMMIT();
        }

        // ---- online softmax (log2 units) ----
        float mx[2][2];
        #pragma unroll
        for (int mf = 0; mf < 2; mf++) { mx[mf][0] = -1e30f; mx[mf][1] = -1e30f; }
        #pragma unroll
        for (int f = 0; f < 8; f++) {
            const int mf = f >> 2;
            mx[mf][0] = fmaxf(mx[mf][0], fmaxf(sacc[f][0], sacc[f][1]));
            mx[mf][1] = fmaxf(mx[mf][1], fmaxf(sacc[f][2], sacc[f][3]));
        }
        #pragma unroll
        for (int mf = 0; mf < 2; mf++)
            #pragma unroll
            for (int hf = 0; hf < 2; hf++) {
                mx[mf][hf] = fmaxf(mx[mf][hf], __shfl_xor_sync(0xffffffffu, mx[mf][hf], 1));
                mx[mf][hf] = fmaxf(mx[mf][hf], __shfl_xor_sync(0xffffffffu, mx[mf][hf], 2));
            }
        if ((lane & 3) == 0) {
            #pragma unroll
            for (int mf = 0; mf < 2; mf++)
                #pragma unroll
                for (int hf = 0; hf < 2; hf++)
                    rmax[wn * 64 + wm * 32 + mf * 16 + hf * 8 + rl] = mx[mf][hf];
        }
        __syncthreads();

        float aa[2][2];
        #pragma unroll
        for (int mf = 0; mf < 2; mf++)
            #pragma unroll
            for (int hf = 0; hf < 2; hf++) {
                const int row = wm * 32 + mf * 16 + hf * 8 + rl;
                float mn = mrun[mf][hf];
                #pragma unroll
                for (int w = 0; w < 4; w++) mn = fmaxf(mn, rmax[w * 64 + row]);
                aa[mf][hf] = exp2f(mrun[mf][hf] - mn);
                mrun[mf][hf] = mn;
            }

        float ss[2][2] = {};
        #pragma unroll
        for (int f = 0; f < 8; f++) {
            const int mf = f >> 2;
            sacc[f][0] = exp2f(sacc[f][0] - mrun[mf][0]);
            sacc[f][1] = exp2f(sacc[f][1] - mrun[mf][0]);
            sacc[f][2] = exp2f(sacc[f][2] - mrun[mf][1]);
            sacc[f][3] = exp2f(sacc[f][3] - mrun[mf][1]);
            ss[mf][0] += sacc[f][0] + sacc[f][1];
            ss[mf][1] += sacc[f][2] + sacc[f][3];
        }
        #pragma unroll
        for (int mf = 0; mf < 2; mf++)
            #pragma unroll
            for (int hf = 0; hf < 2; hf++) {
                ss[mf][hf] += __shfl_xor_sync(0xffffffffu, ss[mf][hf], 1);
                ss[mf][hf] += __shfl_xor_sync(0xffffffffu, ss[mf][hf], 2);
            }
        if ((lane & 3) == 0) {
            #pragma unroll
            for (int mf = 0; mf < 2; mf++)
                #pragma unroll
                for (int hf = 0; hf < 2; hf++)
                    rsum[wn * 64 + wm * 32 + mf * 16 + hf * 8 + rl] = ss[mf][hf];
        }

        // rescale O accumulators (skip when running max unchanged warp-wide)
        {
            bool need = (aa[0][0] < 1.f) || (aa[0][1] < 1.f) ||
                        (aa[1][0] < 1.f) || (aa[1][1] < 1.f);
            if (__any_sync(0xffffffffu, need)) {
                #pragma unroll
                for (int f = 0; f < 16; f++) {
                    const int mf = (f >> 2) & 1;
                    oacc[f][0] *= aa[mf][0]; oacc[f][1] *= aa[mf][0];
                    oacc[f][2] *= aa[mf][1]; oacc[f][3] *= aa[mf][1];
                }
            }
        }

        // P -> smem, fp16 single: two 8KB mats (t-halves), row = 64 fp16 = 128B
        {
            const int th = wn >> 1, cbase = (wn & 1) * 32;
            #pragma unroll
            for (int f = 0; f < 8; f++) {
                const int mf = f >> 2, g = (f >> 1) & 1, f8 = f & 1;
                const int colm = cbase + g * 16 + f8 * 8 + (lane & 3) * 2;
                const uint32_t pmo = P_OFF + th * 8192;
                __half2 p0; p0.x = __float2half(sacc[f][0]); p0.y = __float2half(sacc[f][1]);
                __half2 p1; p1.x = __float2half(sacc[f][2]); p1.y = __float2half(sacc[f][3]);
                uint32_t off = SWZ((wm * 32 + mf * 16 + rl) * 128 + colm * 2);
                *(__half2*)(sm + pmo + off) = p0;
                off = SWZ((wm * 32 + mf * 16 + 8 + rl) * 128 + colm * 2);
                *(__half2*)(sm + pmo + off) = p1;
            }
        }
        __syncthreads();

        #pragma unroll
        for (int mf = 0; mf < 2; mf++)
            #pragma unroll
            for (int hf = 0; hf < 2; hf++) {
                const int row = wm * 32 + mf * 16 + hf * 8 + rl;
                float s = 0.f;
                #pragma unroll
                for (int w = 0; w < 4; w++) s += rsum[w * 64 + row];
                lrun[mf][hf] = lrun[mf][hf] * aa[mf][hf] + s;
            }

        // ---- AV: 2 phases over d-halves; fp16 2-term (P single, V hi/lo) ----
        #pragma unroll
        for (int c = 0; c < 2; c++) {
            CP_WAIT1(); __syncthreads();
            const uint32_t v_buf = sb + (c ? B1_OFF : B0_OFF) + (wn >> 1) * 32768;
            const int vcb = (wn & 1) * 64;   // warp's d32 within the 64-d mat
            #pragma unroll
            for (int ks = 0; ks < 8; ks++) {
                const uint32_t pm = sb + P_OFF + (ks >> 2) * 8192;
                uint32_t ph2[2][4], vh[2][4], vl[2][4];
                #pragma unroll
                for (int mf = 0; mf < 2; mf++) {
                    uint32_t ao = SWZ((wm * 32 + mf * 16 + a_rl) * 128 + (ks & 3) * 32 + a_kb);
                    LDSM4(ph2[mf], pm + ao);
                }
                const uint32_t vrow = ks * 16 + v_rl;
                #pragma unroll
                for (int g = 0; g < 2; g++) {
                    uint32_t bo = SWZ(vrow * 128 + vcb + g * 32 + v_cb);
                    LDSM4T(vh[g], v_buf + bo);
                    LDSM4T(vl[g], v_buf + 16384 + bo);
                }
                #pragma unroll
                for (int mf = 0; mf < 2; mf++)
                    #pragma unroll
                    for (int g = 0; g < 2; g++) {
                        MMA16816H(oacc[c*8+mf*4+g*2],   ph2[mf], vh[g][0], vh[g][1]);
                        MMA16816H(oacc[c*8+mf*4+g*2+1], ph2[mf], vh[g][2], vh[g][3]);
                    }
                #pragma unroll
                for (int mf = 0; mf < 2; mf++)
                    #pragma unroll
                    for (int g = 0; g < 2; g++) {
                        MMA16816H(oacc[c*8+mf*4+g*2],   ph2[mf], vl[g][0], vl[g][1]);
                        MMA16816H(oacc[c*8+mf*4+g*2+1], ph2[mf], vl[g][2], vl[g][3]);
                    }
            }
            __syncthreads();
            if (tile + 1 < NKV) load_k(tile + 1, c, c ? B1_OFF : B0_OFF);
            CP_COMMIT();
        }
    }

    // ---- epilogue: normalize + write hi/lo (bf16) for output projection ----
    const int bb = bh / HH, hh = bh % HH;
    #pragma unroll
    for (int f = 0; f < 16; f++) {
        const int c = f >> 3, mf = (f >> 2) & 1, g = (f >> 1) & 1, f8 = f & 1;
        const int d = c * 128 + wn * 32 + g * 16 + f8 * 8 + (lane & 3) * 2;
        #pragma unroll
        for (int hf = 0; hf < 2; hf++) {
            const int t = m0 + wm * 32 + mf * 16 + hf * 8 + rl;
            const float inv = 1.f / lrun[mf][hf];
            float v0 = oacc[f][hf*2] * inv, v1 = oacc[f][hf*2+1] * inv;
            size_t o = ((size_t)t * BB + bb) * FD + hh * DH + d;
            __nv_bfloat16 h0, l0, h1, l1; split2(v0, h0, l0); split2(v1, h1, l1);
            __nv_bfloat162 ph; ph.x = h0; ph.y = h1;
            __nv_bfloat162 pl; pl.x = l0; pl.y = l1;
            *(__nv_bfloat162*)(g_oh + o) = ph;
            *(__nv_bfloat162*)(g_ol + o) = pl;
        }
    }
}

// ------------------------------ helper kernels ------------------------------
__global__ __launch_bounds__(256) void split_kernel(
    const float* __restrict__ in, __nv_bfloat16* __restrict__ h,
    __nv_bfloat16* __restrict__ l, int n4)
{
    int i = blockIdx.x * 256 + threadIdx.x;
    if (i >= n4) return;
    float4 v = *(const float4*)(in + (size_t)i * 4);
    __nv_bfloat16 h0,l0,h1,l1,h2,l2,h3,l3;
    split2(v.x,h0,l0); split2(v.y,h1,l1); split2(v.z,h2,l2); split2(v.w,h3,l3);
    __nv_bfloat162 a; a.x=h0; a.y=h1; __nv_bfloat162 b; b.x=h2; b.y=h3;
    __nv_bfloat162 c; c.x=l0; c.y=l1; __nv_bfloat162 d; d.x=l2; d.y=l3;
    *(__nv_bfloat162*)(h + (size_t)i*4)     = a;
    *(__nv_bfloat162*)(h + (size_t)i*4 + 2) = b;
    *(__nv_bfloat162*)(l + (size_t)i*4)     = c;
    *(__nv_bfloat162*)(l + (size_t)i*4 + 2) = d;
}

__global__ __launch_bounds__(256) void split_w_kernel(
    const float* __restrict__ w0, const float* __restrict__ w1,
    const float* __restrict__ w2, const float* __restrict__ w3)
{
    const int which = blockIdx.y;
    const float* in = which == 0 ? w0 : which == 1 ? w1 : which == 2 ? w2 : w3;
    __nv_bfloat16* h = which == 0 ? g_wqh : which == 1 ? g_wkh : which == 2 ? g_wvh : g_woh;
    __nv_bfloat16* l = which == 0 ? g_wql : which == 1 ? g_wkl : which == 2 ? g_wvl : g_wol;
    int i = blockIdx.x * 256 + threadIdx.x;
    if (i >= FD*FD/4) return;
    float4 v = *(const float4*)(in + (size_t)i * 4);
    __nv_bfloat16 a0,b0,a1,b1,a2,b2,a3,b3;
    split2(v.x,a0,b0); split2(v.y,a1,b1); split2(v.z,a2,b2); split2(v.w,a3,b3);
    __nv_bfloat162 p; p.x=a0; p.y=a1; __nv_bfloat162 q; q.x=a2; q.y=a3;
    __nv_bfloat162 r; r.x=b0; r.y=b1; __nv_bfloat162 s; s.x=b2; s.y=b3;
    *(__nv_bfloat162*)(h + (size_t)i*4)     = p;
    *(__nv_bfloat162*)(h + (size_t)i*4 + 2) = q;
    *(__nv_bfloat162*)(l + (size_t)i*4)     = r;
    *(__nv_bfloat162*)(l + (size_t)i*4 + 2) = s;
}

// --------------------------------- launch ----------------------------------
extern "C" void kernel_launch(void* const* d_in, const int* in_sizes, int n_in,
                              void* d_out, int out_size)
{
    const float* x  = (const float*)d_in[0];
    const float* Wq = (const float*)d_in[1];
    const float* bq = (const float*)d_in[2];
    const float* Wk = (const float*)d_in[3];
    const float* bk = (const float*)d_in[4];
    const float* Wv = (const float*)d_in[5];
    const float* bv = (const float*)d_in[6];
    const float* Wo = (const float*)d_in[7];
    const float* bo = (const float*)d_in[8];
    float* out = (float*)d_out;

    cudaFuncSetAttribute(gemm_fused,  cudaFuncAttributeMaxDynamicSharedMemorySize, SMEM_BYTES);
    cudaFuncSetAttribute(attn_kernel, cudaFuncAttributeMaxDynamicSharedMemorySize, ATT_SMEM);

    __nv_bfloat16 *xh, *xl, *oh, *ol;
    cudaGetSymbolAddress((void**)&xh, g_xh);  cudaGetSymbolAddress((void**)&xl, g_xl);
    cudaGetSymbolAddress((void**)&oh, g_oh);  cudaGetSymbolAddress((void**)&ol, g_ol);

    // 0: x split
    split_kernel<<<(MROWS*FD/4 + 255)/256, 256>>>(x, xh, xl, MROWS*FD/4);
    // 1: W splits
    dim3 gW((FD*FD/4 + 255)/256, 4);
    split_w_kernel<<<gW, 256>>>(Wq, Wk, Wv, Wo);
    // 2: fused QKV projection (z = 0,1,2)
    dim3 gQKV(MROWS/BM, FD/BN, 3);
    gemm_fused<<<gQKV, 512, SMEM_BYTES>>>(xh, xl, 0, bq, bk, bv, bo, out);
    // 3: fused flash attention
    dim3 gA(TT/64, NBH);
    attn_kernel<<<gA, 256, ATT_SMEM>>>();
    // 4: output projection (mode 3)
    dim3 gO(MROWS/BM, FD/BN, 1);
    gemm_fused<<<gO, 512, SMEM_BYTES>>>(oh, ol, 3, bq, bk, bv, bo, out);
}

// round 11
// speedup vs baseline: 1.4623x; 1.3519x over previous
#include <cuda_runtime.h>
#include <cuda_bf16.h>
#include <cuda_fp16.h>
#include <cstdint>

#define TT 2048
#define BB 8
#define FD 768
#define HH 3
#define DH 256
#define MROWS (TT*BB)      // 16384
#define NBH (BB*HH)        // 24

// ------------------------- device scratch (static) -------------------------
__device__ __align__(16) __nv_bfloat16 g_xh[MROWS*FD], g_xl[MROWS*FD];   // x bf16 hi/lo (Q,K proj)
__device__ __align__(16) __half        g_xh16[MROWS*FD], g_xl16[MROWS*FD]; // x fp16 hi/lo (V proj)
__device__ __align__(16) __nv_bfloat16 g_wqh[FD*FD], g_wql[FD*FD];
__device__ __align__(16) __nv_bfloat16 g_wkh[FD*FD], g_wkl[FD*FD];
__device__ __align__(16) __half        g_wv16[FD*FD];                    // Wv single fp16
__device__ __align__(16) __half        g_wo16[FD*FD];                    // Wo single fp16
__device__ __align__(16) __half        g_q16h[NBH*TT*DH], g_q16l[NBH*TT*DH]; // Q fp16 hi/lo (scaled)
__device__ __align__(16) __half        g_k16[NBH*TT*DH];                 // K fp16 single
__device__ __align__(16) __half        g_v16[NBH*TT*DH];                 // V fp16 single
__device__ __align__(16) __half        g_o16[MROWS*FD];                  // attn out fp16 single

// ------------------------------ PTX helpers --------------------------------
__device__ __forceinline__ uint32_t smem_u32(const void* p) {
    uint32_t a;
    asm("{ .reg .u64 t; cvta.to.shared.u64 t, %1; cvt.u32.u64 %0, t; }" : "=r"(a) : "l"(p));
    return a;
}
#define CP16(dst, src) \
    asm volatile("cp.async.cg.shared.global [%0], [%1], 16;" :: "r"(dst), "l"(src) : "memory")
#define CP_COMMIT() asm volatile("cp.async.commit_group;" ::: "memory")
#define CP_WAIT1()  asm volatile("cp.async.wait_group 1;" ::: "memory")

#define LDSM4(r, addr) \
    asm volatile("ldmatrix.sync.aligned.m8n8.x4.shared.b16 {%0,%1,%2,%3}, [%4];" \
        : "=r"((r)[0]), "=r"((r)[1]), "=r"((r)[2]), "=r"((r)[3]) : "r"(addr))
#define LDSM4T(r, addr) \
    asm volatile("ldmatrix.sync.aligned.m8n8.x4.trans.shared.b16 {%0,%1,%2,%3}, [%4];" \
        : "=r"((r)[0]), "=r"((r)[1]), "=r"((r)[2]), "=r"((r)[3]) : "r"(addr))

#define MMA16816(d, a, b0v, b1v) \
    asm volatile("mma.sync.aligned.m16n8k16.row.col.f32.bf16.bf16.f32 " \
        "{%0,%1,%2,%3}, {%4,%5,%6,%7}, {%8,%9}, {%0,%1,%2,%3};" \
        : "+f"((d)[0]), "+f"((d)[1]), "+f"((d)[2]), "+f"((d)[3]) \
        : "r"((a)[0]), "r"((a)[1]), "r"((a)[2]), "r"((a)[3]), "r"(b0v), "r"(b1v))

#define MMA16816H(d, a, b0v, b1v) \
    asm volatile("mma.sync.aligned.m16n8k16.row.col.f32.f16.f16.f32 " \
        "{%0,%1,%2,%3}, {%4,%5,%6,%7}, {%8,%9}, {%0,%1,%2,%3};" \
        : "+f"((d)[0]), "+f"((d)[1]), "+f"((d)[2]), "+f"((d)[3]) \
        : "r"((a)[0]), "r"((a)[1]), "r"((a)[2]), "r"((a)[3]), "r"(b0v), "r"(b1v))

#define SWZ(o) ((uint32_t)(o) ^ ((((uint32_t)(o)) >> 3) & 0x70))

__device__ __forceinline__ void split2(float v, __nv_bfloat16& h, __nv_bfloat16& l) {
    h = __float2bfloat16(v);
    l = __float2bfloat16(v - __bfloat162float(h));
}
__device__ __forceinline__ void split2h(float v, __half& h, __half& l) {
    h = __float2half(v);
    l = __float2half(v - __half2float(h));
}

#define QSCALE 0.1803368801111204f    // 0.125 * log2(e)

// ---------------- bf16 3-term GEMM (Q,K projections), 512 thr ---------------
#define BM 256
#define BN 128
#define BK 32
#define ROWB 80
#define MAT_A (256*ROWB)
#define MAT_B (128*ROWB)
#define OFF_AH 0
#define OFF_AL MAT_A
#define OFF_BH (2*MAT_A)
#define OFF_BL (2*MAT_A + MAT_B)
#define STAGE_BYTES (2*MAT_A + 2*MAT_B)
#define NSTAGE 3
#define SMEM_BYTES (NSTAGE*STAGE_BYTES)   // 184320

// mode = blockIdx.z: 0=Q (fp16 hi/lo out, scaled), 1=K (fp16 single out)
__global__ __launch_bounds__(512, 1) void gemm_bf3(
    const float* __restrict__ bq, const float* __restrict__ bk)
{
    extern __shared__ char smem[];
    const uint32_t sb = smem_u32(smem);

    const int tid = threadIdx.x;
    const int wid = tid >> 5, lane = tid & 31;
    const int wm = wid >> 2, wn = wid & 3;
    const int m0 = blockIdx.x * BM, n0 = blockIdx.y * BN;
    const int mode = blockIdx.z;

    const __nv_bfloat16* Ah = g_xh;
    const __nv_bfloat16* Al = g_xl;
    const __nv_bfloat16* Bh = mode == 0 ? g_wqh : g_wkh;
    const __nv_bfloat16* Bl = mode == 0 ? g_wql : g_wkl;
    const float* bias = mode == 0 ? bq : bk;
    const int K = FD;

    float acc[4][4][4] = {};

    const int ra0 = tid >> 2,          ca0 = tid & 3;
    const int ra1 = (tid + 512) >> 2,  ca1 = (tid + 512) & 3;
    const int rb  = tid >> 2,          cb  = tid & 3;

    auto load_stage = [&](int kb, int s) {
        const uint32_t st = sb + s * STAGE_BYTES;
        {
            size_t g = (size_t)(m0 + ra0) * K + kb * BK + ca0 * 8;
            uint32_t so = ra0 * ROWB + ca0 * 16;
            CP16(st + OFF_AH + so, Ah + g);
            CP16(st + OFF_AL + so, Al + g);
        }
        {
            size_t g = (size_t)(m0 + ra1) * K + kb * BK + ca1 * 8;
            uint32_t so = ra1 * ROWB + ca1 * 16;
            CP16(st + OFF_AH + so, Ah + g);
            CP16(st + OFF_AL + so, Al + g);
        }
        {
            size_t g = (size_t)(n0 + rb) * K + kb * BK + cb * 8;
            uint32_t so = rb * ROWB + cb * 16;
            CP16(st + OFF_BH + so, Bh + g);
            CP16(st + OFF_BL + so, Bl + g);
        }
    };

    const int NKB = K / BK;
    load_stage(0, 0); CP_COMMIT();
    load_stage(1, 1); CP_COMMIT();

    const int a_row = wm * 64 + (lane & 7) + ((lane >> 3) & 1) * 8;
    const int a_kb  = ((lane >> 4) & 1) * 16;
    const int b_row = wn * 32 + (lane & 7) + (lane >= 16 ? 8 : 0);
    const int b_kb  = ((lane >> 3) & 1) * 16;

    for (int kb = 0; kb < NKB; kb++) {
        CP_WAIT1();
        __syncthreads();
        if (kb + 2 < NKB) load_stage(kb + 2, (kb + 2) % NSTAGE);
        CP_COMMIT();

        const uint32_t st = sb + (kb % NSTAGE) * STAGE_BYTES;
        #pragma unroll
        for (int ks = 0; ks < 2; ks++) {
            uint32_t bhf[2][4], blf[2][4];
            #pragma unroll
            for (int np = 0; np < 2; np++) {
                uint32_t bo2 = (b_row + np * 16) * ROWB + b_kb + ks * 32;
                LDSM4(bhf[np], st + OFF_BH + bo2);
                LDSM4(blf[np], st + OFF_BL + bo2);
            }
            #pragma unroll
            for (int mf = 0; mf < 4; mf++) {
                uint32_t ah[4], al[4];
                uint32_t ao = (a_row + mf * 16) * ROWB + a_kb + ks * 32;
                LDSM4(ah, st + OFF_AH + ao);
                LDSM4(al, st + OFF_AL + ao);
                #pragma unroll
                for (int np = 0; np < 2; np++) {
                    MMA16816(acc[mf][np*2],   ah, bhf[np][0], bhf[np][1]);
                    MMA16816(acc[mf][np*2+1], ah, bhf[np][2], bhf[np][3]);
                }
                #pragma unroll
                for (int np = 0; np < 2; np++) {
                    MMA16816(acc[mf][np*2],   ah, blf[np][0], blf[np][1]);
                    MMA16816(acc[mf][np*2+1], ah, blf[np][2], blf[np][3]);
                }
                #pragma unroll
                for (int np = 0; np < 2; np++) {
                    MMA16816(acc[mf][np*2],   al, bhf[np][0], bhf[np][1]);
                    MMA16816(acc[mf][np*2+1], al, bhf[np][2], bhf[np][3]);
                }
            }
        }
        __syncthreads();
    }

    const int mrow = m0 + wm * 64 + (lane >> 2);
    const int ncol = n0 + wn * 32 + (lane & 3) * 2;
    const float oscale = (mode == 0) ? QSCALE : 1.0f;

    #pragma unroll
    for (int mf = 0; mf < 4; mf++) {
        #pragma unroll
        for (int half2i = 0; half2i < 2; half2i++) {
            const int m = mrow + mf * 16 + half2i * 8;
            #pragma unroll
            for (int nf = 0; nf < 4; nf++) {
                const int n = ncol + nf * 8;
                float v0 = (acc[mf][nf][half2i * 2]     + __ldg(&bias[n]))     * oscale;
                float v1 = (acc[mf][nf][half2i * 2 + 1] + __ldg(&bias[n + 1])) * oscale;
                const int t = m >> 3, b = m & 7, h = n >> 8, d = n & 255;
                size_t o = ((size_t)(b * HH + h) * TT + t) * DH + d;
                if (mode == 0) {           // Q: fp16 hi/lo
                    __half h0, l0, h1, l1; split2h(v0, h0, l0); split2h(v1, h1, l1);
                    __half2 ph; ph.x = h0; ph.y = h1;
                    __half2 pl; pl.x = l0; pl.y = l1;
                    *(__half2*)(g_q16h + o) = ph;
                    *(__half2*)(g_q16l + o) = pl;
                } else {                   // K: fp16 single
                    __half2 p; p.x = __float2half(v0); p.y = __float2half(v1);
                    *(__half2*)(g_k16 + o) = p;
                }
            }
        }
    }
}

// -------------- fp16 GEMM, TERMS in {1,2} (V 2-term, O 1-term) --------------
template<int TERMS, bool OUTH>
__global__ __launch_bounds__(512, 1) void gemm_h(
    const __half* __restrict__ Ah, const __half* __restrict__ Al,
    const __half* __restrict__ Bh,
    const float* __restrict__ bias,
    __half* __restrict__ outH, float* __restrict__ outF)
{
    constexpr int HOFF_AH = 0;
    constexpr int HOFF_AL = MAT_A;
    constexpr int HOFF_BH = (TERMS == 2) ? 2 * MAT_A : MAT_A;
    constexpr int HSTAGE  = HOFF_BH + MAT_B;

    extern __shared__ char smem[];
    const uint32_t sb = smem_u32(smem);

    const int tid = threadIdx.x;
    const int wid = tid >> 5, lane = tid & 31;
    const int wm = wid >> 2, wn = wid & 3;
    const int m0 = blockIdx.x * BM, n0 = blockIdx.y * BN;
    const int K = FD;

    float acc[4][4][4] = {};

    const int ra0 = tid >> 2,          ca0 = tid & 3;
    const int ra1 = (tid + 512) >> 2,  ca1 = (tid + 512) & 3;
    const int rb  = tid >> 2,          cb  = tid & 3;

    auto load_stage = [&](int kb, int s) {
        const uint32_t st = sb + s * HSTAGE;
        {
            size_t g = (size_t)(m0 + ra0) * K + kb * BK + ca0 * 8;
            uint32_t so = ra0 * ROWB + ca0 * 16;
            CP16(st + HOFF_AH + so, Ah + g);
            if (TERMS == 2) CP16(st + HOFF_AL + so, Al + g);
        }
        {
            size_t g = (size_t)(m0 + ra1) * K + kb * BK + ca1 * 8;
            uint32_t so = ra1 * ROWB + ca1 * 16;
            CP16(st + HOFF_AH + so, Ah + g);
            if (TERMS == 2) CP16(st + HOFF_AL + so, Al + g);
        }
        {
            size_t g = (size_t)(n0 + rb) * K + kb * BK + cb * 8;
            uint32_t so = rb * ROWB + cb * 16;
            CP16(st + HOFF_BH + so, Bh + g);
        }
    };

    const int NKB = K / BK;
    load_stage(0, 0); CP_COMMIT();
    load_stage(1, 1); CP_COMMIT();

    const int a_row = wm * 64 + (lane & 7) + ((lane >> 3) & 1) * 8;
    const int a_kb  = ((lane >> 4) & 1) * 16;
    const int b_row = wn * 32 + (lane & 7) + (lane >= 16 ? 8 : 0);
    const int b_kb  = ((lane >> 3) & 1) * 16;

    for (int kb = 0; kb < NKB; kb++) {
        CP_WAIT1();
        __syncthreads();
        if (kb + 2 < NKB) load_stage(kb + 2, (kb + 2) % NSTAGE);
        CP_COMMIT();

        const uint32_t st = sb + (kb % NSTAGE) * HSTAGE;
        #pragma unroll
        for (int ks = 0; ks < 2; ks++) {
            uint32_t bhf[2][4];
            #pragma unroll
            for (int np = 0; np < 2; np++) {
                uint32_t bo2 = (b_row + np * 16) * ROWB + b_kb + ks * 32;
                LDSM4(bhf[np], st + HOFF_BH + bo2);
            }
            #pragma unroll
            for (int mf = 0; mf < 4; mf++) {
                uint32_t ah[4], al[4];
                uint32_t ao = (a_row + mf * 16) * ROWB + a_kb + ks * 32;
                LDSM4(ah, st + HOFF_AH + ao);
                if (TERMS == 2) LDSM4(al, st + HOFF_AL + ao);
                #pragma unroll
                for (int np = 0; np < 2; np++) {
                    MMA16816H(acc[mf][np*2],   ah, bhf[np][0], bhf[np][1]);
                    MMA16816H(acc[mf][np*2+1], ah, bhf[np][2], bhf[np][3]);
                }
                if (TERMS == 2) {
                    #pragma unroll
                    for (int np = 0; np < 2; np++) {
                        MMA16816H(acc[mf][np*2],   al, bhf[np][0], bhf[np][1]);
                        MMA16816H(acc[mf][np*2+1], al, bhf[np][2], bhf[np][3]);
                    }
                }
            }
        }
        __syncthreads();
    }

    const int mrow = m0 + wm * 64 + (lane >> 2);
    const int ncol = n0 + wn * 32 + (lane & 3) * 2;

    #pragma unroll
    for (int mf = 0; mf < 4; mf++) {
        #pragma unroll
        for (int half2i = 0; half2i < 2; half2i++) {
            const int m = mrow + mf * 16 + half2i * 8;
            #pragma unroll
            for (int nf = 0; nf < 4; nf++) {
                const int n = ncol + nf * 8;
                float v0 = acc[mf][nf][half2i * 2]     + __ldg(&bias[n]);
                float v1 = acc[mf][nf][half2i * 2 + 1] + __ldg(&bias[n + 1]);
                if (OUTH) {                // V: (BH,T,D) fp16 single
                    const int t = m >> 3, b = m & 7, h = n >> 8, d = n & 255;
                    size_t o = ((size_t)(b * HH + h) * TT + t) * DH + d;
                    __half2 p; p.x = __float2half(v0); p.y = __float2half(v1);
                    *(__half2*)(outH + o) = p;
                } else {                   // out projection: fp32 (T*B, F)
                    size_t o = (size_t)m * FD + n;
                    float2 f; f.x = v0; f.y = v1;
                    *(float2*)(outF + o) = f;
                }
            }
        }
    }
}

// --------------------------- fused flash attention --------------------------
// CTA: 64 q-rows of one bh; 16 kv-tiles of 128 t. 256 threads, warps 2m x 4n.
// QK: fp16 2-term (Q hi/lo x K single), warp tile m32 x t32.
// AV: fp16 1-term (P single x V single), warp tile m32 x d32.
// Ping-pong buffers (32KB): [dh 0/1] mats of [128t x 64d] fp16 at dh*16384.
#define Q_OFF 0           // 64KB: mats (j*2+hl)*8192
#define B0_OFF 65536      // 32KB
#define B1_OFF 98304      // 32KB
#define P_OFF 131072      // 16KB: two 8KB t-half mats
#define RMAX_OFF 147456
#define RSUM_OFF 148480
#define ATT_SMEM 149504
#define NKV (TT/128)      // 16

__global__ __launch_bounds__(256, 1) void attn_kernel()
{
    extern __shared__ char sm[];
    const uint32_t sb = smem_u32(sm);
    const int tid = threadIdx.x, lane = tid & 31, wid = tid >> 5;
    const int wm = wid >> 2, wn = wid & 3;             // 2m x 4n
    const int bh = blockIdx.y, m0 = blockIdx.x * 64;

    // K chunk (single fp16): [128t x 64d] per dh
    auto load_k = [&](int tile, int c, uint32_t bufoff) {
        #pragma unroll
        for (int dh = 0; dh < 2; dh++) {
            #pragma unroll
            for (int i = 0; i < 4; i++) {
                int ci = tid + i * 256;
                int r = ci >> 3, cc = ci & 7;
                size_t g = ((size_t)bh * TT + tile * 128 + r) * DH + c * 128 + dh * 64 + cc * 8;
                CP16(sb + bufoff + dh * 16384 + SWZ(r * 128 + cc * 16), g_k16 + g);
            }
        }
    };
    auto load_v = [&](int tile, int c, uint32_t bufoff) {
        #pragma unroll
        for (int dh = 0; dh < 2; dh++) {
            #pragma unroll
            for (int i = 0; i < 4; i++) {
                int ci = tid + i * 256;
                int r = ci >> 3, cc = ci & 7;
                size_t g = ((size_t)bh * TT + tile * 128 + r) * DH + c * 128 + dh * 64 + cc * 8;
                CP16(sb + bufoff + dh * 16384 + SWZ(r * 128 + cc * 16), g_v16 + g);
            }
        }
    };

    // Q resident: 8 mats [j 0..3][hl]
    #pragma unroll
    for (int i = 0; i < 16; i++) {
        int ci = tid + i * 256;
        int mat = ci >> 9, w = ci & 511, r = w >> 3, c = w & 7;
        int j = mat >> 1, hl = mat & 1;
        size_t g = ((size_t)bh * TT + m0 + r) * DH + j * 64 + c * 8;
        const __half* src = hl ? g_q16l : g_q16h;
        CP16(sb + Q_OFF + mat * 8192 + SWZ(r * 128 + c * 16), src + g);
    }
    load_k(0, 0, B0_OFF); CP_COMMIT();
    load_k(0, 1, B1_OFF); CP_COMMIT();

    const int a_rl = (lane & 7) + ((lane >> 3) & 1) * 8;
    const int a_kb = ((lane >> 4) & 1) * 16;
    const int b_rl = (lane & 7) + (lane >= 16 ? 8 : 0);
    const int b_kb = ((lane >> 3) & 1) * 16;
    const int v_rl = (lane & 7) + ((lane >> 3) & 1) * 8;
    const int v_cb = ((lane >> 4) & 1) * 16;

    float oacc[16][4] = {};
    float sacc[8][4];
    float mrun[2][2], lrun[2][2];
    #pragma unroll
    for (int i = 0; i < 2; i++)
        #pragma unroll
        for (int j = 0; j < 2; j++) { mrun[i][j] = -1e30f; lrun[i][j] = 0.f; }

    const int rl = lane >> 2;
    float* rmax = (float*)(sm + RMAX_OFF);   // [4 wn][64 rows]
    float* rsum = (float*)(sm + RSUM_OFF);

    for (int tile = 0; tile < NKV; tile++) {
        #pragma unroll
        for (int f = 0; f < 8; f++) { sacc[f][0]=0.f; sacc[f][1]=0.f; sacc[f][2]=0.f; sacc[f][3]=0.f; }

        // ---- QK: 2 phases over d-halves; fp16 2-term ----
        #pragma unroll
        for (int c = 0; c < 2; c++) {
            CP_WAIT1(); __syncthreads();
            const uint32_t kb_buf = sb + (c ? B1_OFF : B0_OFF);
            #pragma unroll
            for (int ks = 0; ks < 8; ks++) {
                const uint32_t qm = sb + Q_OFF + (c * 2 + (ks >> 2)) * 16384;
                const uint32_t km = kb_buf + (ks >> 2) * 16384;
                uint32_t qh2[2][4], ql2[2][4], kh[2][4];
                #pragma unroll
                for (int mf = 0; mf < 2; mf++) {
                    uint32_t ao = SWZ((wm * 32 + mf * 16 + a_rl) * 128 + (ks & 3) * 32 + a_kb);
                    LDSM4(qh2[mf], qm + ao);
                    LDSM4(ql2[mf], qm + 8192 + ao);
                }
                #pragma unroll
                for (int g = 0; g < 2; g++) {
                    uint32_t bo = SWZ((wn * 32 + g * 16 + b_rl) * 128 + (ks & 3) * 32 + b_kb);
                    LDSM4(kh[g], km + bo);
                }
                #pragma unroll
                for (int mf = 0; mf < 2; mf++)
                    #pragma unroll
                    for (int g = 0; g < 2; g++) {
                        MMA16816H(sacc[mf*4+g*2],   qh2[mf], kh[g][0], kh[g][1]);
                        MMA16816H(sacc[mf*4+g*2+1], qh2[mf], kh[g][2], kh[g][3]);
                    }
                #pragma unroll
                for (int mf = 0; mf < 2; mf++)
                    #pragma unroll
                    for (int g = 0; g < 2; g++) {
                        MMA16816H(sacc[mf*4+g*2],   ql2[mf], kh[g][0], kh[g][1]);
                        MMA16816H(sacc[mf*4+g*2+1], ql2[mf], kh[g][2], kh[g][3]);
                    }
            }
            __syncthreads();
            load_v(tile, c, c ? B1_OFF : B0_OFF);
            CP_COMMIT();
        }

        // ---- online softmax (log2 units via folded QSCALE) ----
        float mx[2][2];
        #pragma unroll
        for (int mf = 0; mf < 2; mf++) { mx[mf][0] = -1e30f; mx[mf][1] = -1e30f; }
        #pragma unroll
        for (int f = 0; f < 8; f++) {
            const int mf = f >> 2;
            mx[mf][0] = fmaxf(mx[mf][0], fmaxf(sacc[f][0], sacc[f][1]));
            mx[mf][1] = fmaxf(mx[mf][1], fmaxf(sacc[f][2], sacc[f][3]));
        }
        #pragma unroll
        for (int mf = 0; mf < 2; mf++)
            #pragma unroll
            for (int hf = 0; hf < 2; hf++) {
                mx[mf][hf] = fmaxf(mx[mf][hf], __shfl_xor_sync(0xffffffffu, mx[mf][hf], 1));
                mx[mf][hf] = fmaxf(mx[mf][hf], __shfl_xor_sync(0xffffffffu, mx[mf][hf], 2));
            }
        if ((lane & 3) == 0) {
            #pragma unroll
            for (int mf = 0; mf < 2; mf++)
                #pragma unroll
                for (int hf = 0; hf < 2; hf++)
                    rmax[wn * 64 + wm * 32 + mf * 16 + hf * 8 + rl] = mx[mf][hf];
        }
        __syncthreads();

        float aa[2][2];
        #pragma unroll
        for (int mf = 0; mf < 2; mf++)
            #pragma unroll
            for (int hf = 0; hf < 2; hf++) {
                const int row = wm * 32 + mf * 16 + hf * 8 + rl;
                float mn = mrun[mf][hf];
                #pragma unroll
                for (int w = 0; w < 4; w++) mn = fmaxf(mn, rmax[w * 64 + row]);
                aa[mf][hf] = exp2f(mrun[mf][hf] - mn);
                mrun[mf][hf] = mn;
            }

        float ss[2][2] = {};
        #pragma unroll
        for (int f = 0; f < 8; f++) {
            const int mf = f >> 2;
            sacc[f][0] = exp2f(sacc[f][0] - mrun[mf][0]);
            sacc[f][1] = exp2f(sacc[f][1] - mrun[mf][0]);
            sacc[f][2] = exp2f(sacc[f][2] - mrun[mf][1]);
            sacc[f][3] = exp2f(sacc[f][3] - mrun[mf][1]);
            ss[mf][0] += sacc[f][0] + sacc[f][1];
            ss[mf][1] += sacc[f][2] + sacc[f][3];
        }
        #pragma unroll
        for (int mf = 0; mf < 2; mf++)
            #pragma unroll
            for (int hf = 0; hf < 2; hf++) {
                ss[mf][hf] += __shfl_xor_sync(0xffffffffu, ss[mf][hf], 1);
                ss[mf][hf] += __shfl_xor_sync(0xffffffffu, ss[mf][hf], 2);
            }
        if ((lane & 3) == 0) {
            #pragma unroll
            for (int mf = 0; mf < 2; mf++)
                #pragma unroll
                for (int hf = 0; hf < 2; hf++)
                    rsum[wn * 64 + wm * 32 + mf * 16 + hf * 8 + rl] = ss[mf][hf];
        }

        // rescale O accumulators (skip when running max unchanged warp-wide)
        {
            bool need = (aa[0][0] < 1.f) || (aa[0][1] < 1.f) ||
                        (aa[1][0] < 1.f) || (aa[1][1] < 1.f);
            if (__any_sync(0xffffffffu, need)) {
                #pragma unroll
                for (int f = 0; f < 16; f++) {
                    const int mf = (f >> 2) & 1;
                    oacc[f][0] *= aa[mf][0]; oacc[f][1] *= aa[mf][0];
                    oacc[f][2] *= aa[mf][1]; oacc[f][3] *= aa[mf][1];
                }
            }
        }

        // P -> smem, fp16 single: two 8KB t-half mats
        {
            const int th = wn >> 1, cbase = (wn & 1) * 32;
            #pragma unroll
            for (int f = 0; f < 8; f++) {
                const int mf = f >> 2, g = (f >> 1) & 1, f8 = f & 1;
                const int colm = cbase + g * 16 + f8 * 8 + (lane & 3) * 2;
                const uint32_t pmo = P_OFF + th * 8192;
                __half2 p0; p0.x = __float2half(sacc[f][0]); p0.y = __float2half(sacc[f][1]);
                __half2 p1; p1.x = __float2half(sacc[f][2]); p1.y = __float2half(sacc[f][3]);
                uint32_t off = SWZ((wm * 32 + mf * 16 + rl) * 128 + colm * 2);
                *(__half2*)(sm + pmo + off) = p0;
                off = SWZ((wm * 32 + mf * 16 + 8 + rl) * 128 + colm * 2);
                *(__half2*)(sm + pmo + off) = p1;
            }
        }
        __syncthreads();

        #pragma unroll
        for (int mf = 0; mf < 2; mf++)
            #pragma unroll
            for (int hf = 0; hf < 2; hf++) {
                const int row = wm * 32 + mf * 16 + hf * 8 + rl;
                float s = 0.f;
                #pragma unroll
                for (int w = 0; w < 4; w++) s += rsum[w * 64 + row];
                lrun[mf][hf] = lrun[mf][hf] * aa[mf][hf] + s;
            }

        // ---- AV: 2 phases over d-halves; fp16 1-term (P single, V single) ----
        #pragma unroll
        for (int c = 0; c < 2; c++) {
            CP_WAIT1(); __syncthreads();
            const uint32_t v_buf = sb + (c ? B1_OFF : B0_OFF) + (wn >> 1) * 16384;
            const int vcb = (wn & 1) * 64;
            #pragma unroll
            for (int ks = 0; ks < 8; ks++) {
                const uint32_t pm = sb + P_OFF + (ks >> 2) * 8192;
                uint32_t ph2[2][4], vh[2][4];
                #pragma unroll
                for (int mf = 0; mf < 2; mf++) {
                    uint32_t ao = SWZ((wm * 32 + mf * 16 + a_rl) * 128 + (ks & 3) * 32 + a_kb);
                    LDSM4(ph2[mf], pm + ao);
                }
                const uint32_t vrow = ks * 16 + v_rl;
                #pragma unroll
                for (int g = 0; g < 2; g++) {
                    uint32_t bo = SWZ(vrow * 128 + vcb + g * 32 + v_cb);
                    LDSM4T(vh[g], v_buf + bo);
                }
                #pragma unroll
                for (int mf = 0; mf < 2; mf++)
                    #pragma unroll
                    for (int g = 0; g < 2; g++) {
                        MMA16816H(oacc[c*8+mf*4+g*2],   ph2[mf], vh[g][0], vh[g][1]);
                        MMA16816H(oacc[c*8+mf*4+g*2+1], ph2[mf], vh[g][2], vh[g][3]);
                    }
            }
            __syncthreads();
            if (tile + 1 < NKV) load_k(tile + 1, c, c ? B1_OFF : B0_OFF);
            CP_COMMIT();
        }
    }

    // ---- epilogue: normalize + write fp16 single for output projection ----
    const int bb = bh / HH, hh = bh % HH;
    #pragma unroll
    for (int f = 0; f < 16; f++) {
        const int c = f >> 3, mf = (f >> 2) & 1, g = (f >> 1) & 1, f8 = f & 1;
        const int d = c * 128 + wn * 32 + g * 16 + f8 * 8 + (lane & 3) * 2;
        #pragma unroll
        for (int hf = 0; hf < 2; hf++) {
            const int t = m0 + wm * 32 + mf * 16 + hf * 8 + rl;
            const float inv = 1.f / lrun[mf][hf];
            float v0 = oacc[f][hf*2] * inv, v1 = oacc[f][hf*2+1] * inv;
            size_t o = ((size_t)t * BB + bb) * FD + hh * DH + d;
            __half2 p; p.x = __float2half(v0); p.y = __float2half(v1);
            *(__half2*)(g_o16 + o) = p;
        }
    }
}

// ------------------------------ helper kernels ------------------------------
// x -> bf16 hi/lo (Q,K proj) + fp16 hi/lo (V proj)
__global__ __launch_bounds__(256) void split_x_kernel(
    const float* __restrict__ in, int n4)
{
    int i = blockIdx.x * 256 + threadIdx.x;
    if (i >= n4) return;
    float4 v = *(const float4*)(in + (size_t)i * 4);
    {
        __nv_bfloat16 h0,l0,h1,l1,h2,l2,h3,l3;
        split2(v.x,h0,l0); split2(v.y,h1,l1); split2(v.z,h2,l2); split2(v.w,h3,l3);
        __nv_bfloat162 a; a.x=h0; a.y=h1; __nv_bfloat162 b; b.x=h2; b.y=h3;
        __nv_bfloat162 c; c.x=l0; c.y=l1; __nv_bfloat162 d; d.x=l2; d.y=l3;
        *(__nv_bfloat162*)(g_xh + (size_t)i*4)     = a;
        *(__nv_bfloat162*)(g_xh + (size_t)i*4 + 2) = b;
        *(__nv_bfloat162*)(g_xl + (size_t)i*4)     = c;
        *(__nv_bfloat162*)(g_xl + (size_t)i*4 + 2) = d;
    }
    {
        __half h0,l0,h1,l1,h2,l2,h3,l3;
        split2h(v.x,h0,l0); split2h(v.y,h1,l1); split2h(v.z,h2,l2); split2h(v.w,h3,l3);
        __half2 a; a.x=h0; a.y=h1; __half2 b; b.x=h2; b.y=h3;
        __half2 c; c.x=l0; c.y=l1; __half2 d; d.x=l2; d.y=l3;
        *(__half2*)(g_xh16 + (size_t)i*4)     = a;
        *(__half2*)(g_xh16 + (size_t)i*4 + 2) = b;
        *(__half2*)(g_xl16 + (size_t)i*4)     = c;
        *(__half2*)(g_xl16 + (size_t)i*4 + 2) = d;
    }
}

// Wq,Wk -> bf16 hi/lo; Wv,Wo -> fp16 single
__global__ __launch_bounds__(256) void split_w_kernel(
    const float* __restrict__ w0, const float* __restrict__ w1,
    const float* __restrict__ w2, const float* __restrict__ w3)
{
    const int which = blockIdx.y;
    int i = blockIdx.x * 256 + threadIdx.x;
    if (i >= FD*FD/4) return;
    const float* in = which == 0 ? w0 : which == 1 ? w1 : which == 2 ? w2 : w3;
    float4 v = *(const float4*)(in + (size_t)i * 4);
    if (which <= 1) {
        __nv_bfloat16* h = which == 0 ? g_wqh : g_wkh;
        __nv_bfloat16* l = which == 0 ? g_wql : g_wkl;
        __nv_bfloat16 a0,b0,a1,b1,a2,b2,a3,b3;
        split2(v.x,a0,b0); split2(v.y,a1,b1); split2(v.z,a2,b2); split2(v.w,a3,b3);
        __nv_bfloat162 p; p.x=a0; p.y=a1; __nv_bfloat162 q; q.x=a2; q.y=a3;
        __nv_bfloat162 r; r.x=b0; r.y=b1; __nv_bfloat162 s; s.x=b2; s.y=b3;
        *(__nv_bfloat162*)(h + (size_t)i*4)     = p;
        *(__nv_bfloat162*)(h + (size_t)i*4 + 2) = q;
        *(__nv_bfloat162*)(l + (size_t)i*4)     = r;
        *(__nv_bfloat162*)(l + (size_t)i*4 + 2) = s;
    } else {
        __half* h = which == 2 ? g_wv16 : g_wo16;
        __half2 p; p.x=__float2half(v.x); p.y=__float2half(v.y);
        __half2 q; q.x=__float2half(v.z); q.y=__float2half(v.w);
        *(__half2*)(h + (size_t)i*4)     = p;
        *(__half2*)(h + (size_t)i*4 + 2) = q;
    }
}

// --------------------------------- launch ----------------------------------
extern "C" void kernel_launch(void* const* d_in, const int* in_sizes, int n_in,
                              void* d_out, int out_size)
{
    const float* x  = (const float*)d_in[0];
    const float* Wq = (const float*)d_in[1];
    const float* bq = (const float*)d_in[2];
    const float* Wk = (const float*)d_in[3];
    const float* bk = (const float*)d_in[4];
    const float* Wv = (const float*)d_in[5];
    const float* bv = (const float*)d_in[6];
    const float* Wo = (const float*)d_in[7];
    const float* bo = (const float*)d_in[8];
    float* out = (float*)d_out;

    constexpr int H2_SMEM = 3 * (2 * MAT_A + MAT_B);   // 153600
    constexpr int H1_SMEM = 3 * (MAT_A + MAT_B);       // 92160

    cudaFuncSetAttribute(gemm_bf3,        cudaFuncAttributeMaxDynamicSharedMemorySize, SMEM_BYTES);
    cudaFuncSetAttribute(gemm_h<2,true>,  cudaFuncAttributeMaxDynamicSharedMemorySize, H2_SMEM);
    cudaFuncSetAttribute(gemm_h<1,false>, cudaFuncAttributeMaxDynamicSharedMemorySize, H1_SMEM);
    cudaFuncSetAttribute(attn_kernel,     cudaFuncAttributeMaxDynamicSharedMemorySize, ATT_SMEM);

    __half *xh16, *xl16, *wv16, *wo16, *o16;
    cudaGetSymbolAddress((void**)&xh16, g_xh16);
    cudaGetSymbolAddress((void**)&xl16, g_xl16);
    cudaGetSymbolAddress((void**)&wv16, g_wv16);
    cudaGetSymbolAddress((void**)&wo16, g_wo16);
    cudaGetSymbolAddress((void**)&o16,  g_o16);

    // 0: x split
    split_x_kernel<<<(MROWS*FD/4 + 255)/256, 256>>>(x, MROWS*FD/4);
    // 1: W splits
    dim3 gW((FD*FD/4 + 255)/256, 4);
    split_w_kernel<<<gW, 256>>>(Wq, Wk, Wv, Wo);
    // 2: Q,K projections (bf16 3-term), z = 0,1
    dim3 gQK(MROWS/BM, FD/BN, 2);
    gemm_bf3<<<gQK, 512, SMEM_BYTES>>>(bq, bk);
    // 3: V projection (fp16 2-term)
    dim3 gP(MROWS/BM, FD/BN);
    __half* vdst; cudaGetSymbolAddress((void**)&vdst, g_v16);
    gemm_h<2,true><<<gP, 512, H2_SMEM>>>(xh16, xl16, wv16, bv, vdst, nullptr);
    // 4: fused flash attention
    dim3 gA(TT/64, NBH);
    attn_kernel<<<gA, 256, ATT_SMEM>>>();
    // 5: output projection (fp16 1-term)
    gemm_h<1,false><<<gP, 512, H1_SMEM>>>(o16, nullptr, wo16, bo, nullptr, out);
}

// round 12
// speedup vs baseline: 1.5939x; 1.0900x over previous
#include <cuda_runtime.h>
#include <cuda_bf16.h>
#include <cuda_fp16.h>
#include <cstdint>

#define TT 2048
#define BB 8
#define FD 768
#define HH 3
#define DH 256
#define MROWS (TT*BB)      // 16384
#define NBH (BB*HH)        // 24

// ------------------------- device scratch (static) -------------------------
__device__ __align__(16) __nv_bfloat16 g_xh[MROWS*FD], g_xl[MROWS*FD];   // x bf16 hi/lo (Q,K proj)
__device__ __align__(16) __half        g_xh16[MROWS*FD], g_xl16[MROWS*FD]; // x fp16 hi/lo (V proj)
__device__ __align__(16) __nv_bfloat16 g_wqh[FD*FD], g_wql[FD*FD];
__device__ __align__(16) __nv_bfloat16 g_wkh[FD*FD], g_wkl[FD*FD];
__device__ __align__(16) __half        g_wv16[FD*FD];                    // Wv single fp16
__device__ __align__(16) __half        g_wo16[FD*FD];                    // Wo single fp16
__device__ __align__(16) __half        g_q16[NBH*TT*DH];                 // Q fp16 single (scaled)
__device__ __align__(16) __half        g_k16[NBH*TT*DH];                 // K fp16 single
__device__ __align__(16) __half        g_v16[NBH*TT*DH];                 // V fp16 single
__device__ __align__(16) __half        g_o16[MROWS*FD];                  // attn out fp16 single

// ------------------------------ PTX helpers --------------------------------
__device__ __forceinline__ uint32_t smem_u32(const void* p) {
    uint32_t a;
    asm("{ .reg .u64 t; cvta.to.shared.u64 t, %1; cvt.u32.u64 %0, t; }" : "=r"(a) : "l"(p));
    return a;
}
#define CP16(dst, src) \
    asm volatile("cp.async.cg.shared.global [%0], [%1], 16;" :: "r"(dst), "l"(src) : "memory")
#define CP_COMMIT() asm volatile("cp.async.commit_group;" ::: "memory")
#define CP_WAIT1()  asm volatile("cp.async.wait_group 1;" ::: "memory")

#define LDSM4(r, addr) \
    asm volatile("ldmatrix.sync.aligned.m8n8.x4.shared.b16 {%0,%1,%2,%3}, [%4];" \
        : "=r"((r)[0]), "=r"((r)[1]), "=r"((r)[2]), "=r"((r)[3]) : "r"(addr))
#define LDSM4T(r, addr) \
    asm volatile("ldmatrix.sync.aligned.m8n8.x4.trans.shared.b16 {%0,%1,%2,%3}, [%4];" \
        : "=r"((r)[0]), "=r"((r)[1]), "=r"((r)[2]), "=r"((r)[3]) : "r"(addr))

#define MMA16816(d, a, b0v, b1v) \
    asm volatile("mma.sync.aligned.m16n8k16.row.col.f32.bf16.bf16.f32 " \
        "{%0,%1,%2,%3}, {%4,%5,%6,%7}, {%8,%9}, {%0,%1,%2,%3};" \
        : "+f"((d)[0]), "+f"((d)[1]), "+f"((d)[2]), "+f"((d)[3]) \
        : "r"((a)[0]), "r"((a)[1]), "r"((a)[2]), "r"((a)[3]), "r"(b0v), "r"(b1v))

#define MMA16816H(d, a, b0v, b1v) \
    asm volatile("mma.sync.aligned.m16n8k16.row.col.f32.f16.f16.f32 " \
        "{%0,%1,%2,%3}, {%4,%5,%6,%7}, {%8,%9}, {%0,%1,%2,%3};" \
        : "+f"((d)[0]), "+f"((d)[1]), "+f"((d)[2]), "+f"((d)[3]) \
        : "r"((a)[0]), "r"((a)[1]), "r"((a)[2]), "r"((a)[3]), "r"(b0v), "r"(b1v))

#define SWZ(o) ((uint32_t)(o) ^ ((((uint32_t)(o)) >> 3) & 0x70))

__device__ __forceinline__ void split2(float v, __nv_bfloat16& h, __nv_bfloat16& l) {
    h = __float2bfloat16(v);
    l = __float2bfloat16(v - __bfloat162float(h));
}
__device__ __forceinline__ void split2h(float v, __half& h, __half& l) {
    h = __float2half(v);
    l = __float2half(v - __half2float(h));
}

#define QSCALE 0.1803368801111204f    // 0.125 * log2(e)

// ---------------- bf16 3-term GEMM (Q,K projections), 512 thr ---------------
#define BM 256
#define BN 128
#define BK 32
#define ROWB 80
#define MAT_A (256*ROWB)
#define MAT_B (128*ROWB)
#define OFF_AH 0
#define OFF_AL MAT_A
#define OFF_BH (2*MAT_A)
#define OFF_BL (2*MAT_A + MAT_B)
#define STAGE_BYTES (2*MAT_A + 2*MAT_B)
#define NSTAGE 3
#define SMEM_BYTES (NSTAGE*STAGE_BYTES)   // 184320

// mode = blockIdx.z: 0=Q (fp16 single out, scaled), 1=K (fp16 single out)
__global__ __launch_bounds__(512, 1) void gemm_bf3(
    const float* __restrict__ bq, const float* __restrict__ bk)
{
    extern __shared__ char smem[];
    const uint32_t sb = smem_u32(smem);

    const int tid = threadIdx.x;
    const int wid = tid >> 5, lane = tid & 31;
    const int wm = wid >> 2, wn = wid & 3;
    const int m0 = blockIdx.x * BM, n0 = blockIdx.y * BN;
    const int mode = blockIdx.z;

    const __nv_bfloat16* Ah = g_xh;
    const __nv_bfloat16* Al = g_xl;
    const __nv_bfloat16* Bh = mode == 0 ? g_wqh : g_wkh;
    const __nv_bfloat16* Bl = mode == 0 ? g_wql : g_wkl;
    const float* bias = mode == 0 ? bq : bk;
    const int K = FD;

    float acc[4][4][4] = {};

    const int ra0 = tid >> 2,          ca0 = tid & 3;
    const int ra1 = (tid + 512) >> 2,  ca1 = (tid + 512) & 3;
    const int rb  = tid >> 2,          cb  = tid & 3;

    auto load_stage = [&](int kb, int s) {
        const uint32_t st = sb + s * STAGE_BYTES;
        {
            size_t g = (size_t)(m0 + ra0) * K + kb * BK + ca0 * 8;
            uint32_t so = ra0 * ROWB + ca0 * 16;
            CP16(st + OFF_AH + so, Ah + g);
            CP16(st + OFF_AL + so, Al + g);
        }
        {
            size_t g = (size_t)(m0 + ra1) * K + kb * BK + ca1 * 8;
            uint32_t so = ra1 * ROWB + ca1 * 16;
            CP16(st + OFF_AH + so, Ah + g);
            CP16(st + OFF_AL + so, Al + g);
        }
        {
            size_t g = (size_t)(n0 + rb) * K + kb * BK + cb * 8;
            uint32_t so = rb * ROWB + cb * 16;
            CP16(st + OFF_BH + so, Bh + g);
            CP16(st + OFF_BL + so, Bl + g);
        }
    };

    const int NKB = K / BK;
    load_stage(0, 0); CP_COMMIT();
    load_stage(1, 1); CP_COMMIT();

    const int a_row = wm * 64 + (lane & 7) + ((lane >> 3) & 1) * 8;
    const int a_kb  = ((lane >> 4) & 1) * 16;
    const int b_row = wn * 32 + (lane & 7) + (lane >= 16 ? 8 : 0);
    const int b_kb  = ((lane >> 3) & 1) * 16;

    for (int kb = 0; kb < NKB; kb++) {
        CP_WAIT1();
        __syncthreads();
        if (kb + 2 < NKB) load_stage(kb + 2, (kb + 2) % NSTAGE);
        CP_COMMIT();

        const uint32_t st = sb + (kb % NSTAGE) * STAGE_BYTES;
        #pragma unroll
        for (int ks = 0; ks < 2; ks++) {
            uint32_t bhf[2][4], blf[2][4];
            #pragma unroll
            for (int np = 0; np < 2; np++) {
                uint32_t bo2 = (b_row + np * 16) * ROWB + b_kb + ks * 32;
                LDSM4(bhf[np], st + OFF_BH + bo2);
                LDSM4(blf[np], st + OFF_BL + bo2);
            }
            #pragma unroll
            for (int mf = 0; mf < 4; mf++) {
                uint32_t ah[4], al[4];
                uint32_t ao = (a_row + mf * 16) * ROWB + a_kb + ks * 32;
                LDSM4(ah, st + OFF_AH + ao);
                LDSM4(al, st + OFF_AL + ao);
                #pragma unroll
                for (int np = 0; np < 2; np++) {
                    MMA16816(acc[mf][np*2],   ah, bhf[np][0], bhf[np][1]);
                    MMA16816(acc[mf][np*2+1], ah, bhf[np][2], bhf[np][3]);
                }
                #pragma unroll
                for (int np = 0; np < 2; np++) {
                    MMA16816(acc[mf][np*2],   ah, blf[np][0], blf[np][1]);
                    MMA16816(acc[mf][np*2+1], ah, blf[np][2], blf[np][3]);
                }
                #pragma unroll
                for (int np = 0; np < 2; np++) {
                    MMA16816(acc[mf][np*2],   al, bhf[np][0], bhf[np][1]);
                    MMA16816(acc[mf][np*2+1], al, bhf[np][2], bhf[np][3]);
                }
            }
        }
        __syncthreads();
    }

    const int mrow = m0 + wm * 64 + (lane >> 2);
    const int ncol = n0 + wn * 32 + (lane & 3) * 2;
    const float oscale = (mode == 0) ? QSCALE : 1.0f;
    __half* dst = (mode == 0) ? g_q16 : g_k16;

    #pragma unroll
    for (int mf = 0; mf < 4; mf++) {
        #pragma unroll
        for (int half2i = 0; half2i < 2; half2i++) {
            const int m = mrow + mf * 16 + half2i * 8;
            #pragma unroll
            for (int nf = 0; nf < 4; nf++) {
                const int n = ncol + nf * 8;
                float v0 = (acc[mf][nf][half2i * 2]     + __ldg(&bias[n]))     * oscale;
                float v1 = (acc[mf][nf][half2i * 2 + 1] + __ldg(&bias[n + 1])) * oscale;
                const int t = m >> 3, b = m & 7, h = n >> 8, d = n & 255;
                size_t o = ((size_t)(b * HH + h) * TT + t) * DH + d;
                __half2 p; p.x = __float2half(v0); p.y = __float2half(v1);
                *(__half2*)(dst + o) = p;
            }
        }
    }
}

// -------------- fp16 GEMM, TERMS in {1,2} (V 2-term, O 1-term) --------------
template<int TERMS, bool OUTH>
__global__ __launch_bounds__(512, 1) void gemm_h(
    const __half* __restrict__ Ah, const __half* __restrict__ Al,
    const __half* __restrict__ Bh,
    const float* __restrict__ bias,
    __half* __restrict__ outH, float* __restrict__ outF)
{
    constexpr int HOFF_AH = 0;
    constexpr int HOFF_AL = MAT_A;
    constexpr int HOFF_BH = (TERMS == 2) ? 2 * MAT_A : MAT_A;
    constexpr int HSTAGE  = HOFF_BH + MAT_B;

    extern __shared__ char smem[];
    const uint32_t sb = smem_u32(smem);

    const int tid = threadIdx.x;
    const int wid = tid >> 5, lane = tid & 31;
    const int wm = wid >> 2, wn = wid & 3;
    const int m0 = blockIdx.x * BM, n0 = blockIdx.y * BN;
    const int K = FD;

    float acc[4][4][4] = {};

    const int ra0 = tid >> 2,          ca0 = tid & 3;
    const int ra1 = (tid + 512) >> 2,  ca1 = (tid + 512) & 3;
    const int rb  = tid >> 2,          cb  = tid & 3;

    auto load_stage = [&](int kb, int s) {
        const uint32_t st = sb + s * HSTAGE;
        {
            size_t g = (size_t)(m0 + ra0) * K + kb * BK + ca0 * 8;
            uint32_t so = ra0 * ROWB + ca0 * 16;
            CP16(st + HOFF_AH + so, Ah + g);
            if (TERMS == 2) CP16(st + HOFF_AL + so, Al + g);
        }
        {
            size_t g = (size_t)(m0 + ra1) * K + kb * BK + ca1 * 8;
            uint32_t so = ra1 * ROWB + ca1 * 16;
            CP16(st + HOFF_AH + so, Ah + g);
            if (TERMS == 2) CP16(st + HOFF_AL + so, Al + g);
        }
        {
            size_t g = (size_t)(n0 + rb) * K + kb * BK + cb * 8;
            uint32_t so = rb * ROWB + cb * 16;
            CP16(st + HOFF_BH + so, Bh + g);
        }
    };

    const int NKB = K / BK;
    load_stage(0, 0); CP_COMMIT();
    load_stage(1, 1); CP_COMMIT();

    const int a_row = wm * 64 + (lane & 7) + ((lane >> 3) & 1) * 8;
    const int a_kb  = ((lane >> 4) & 1) * 16;
    const int b_row = wn * 32 + (lane & 7) + (lane >= 16 ? 8 : 0);
    const int b_kb  = ((lane >> 3) & 1) * 16;

    for (int kb = 0; kb < NKB; kb++) {
        CP_WAIT1();
        __syncthreads();
        if (kb + 2 < NKB) load_stage(kb + 2, (kb + 2) % NSTAGE);
        CP_COMMIT();

        const uint32_t st = sb + (kb % NSTAGE) * HSTAGE;
        #pragma unroll
        for (int ks = 0; ks < 2; ks++) {
            uint32_t bhf[2][4];
            #pragma unroll
            for (int np = 0; np < 2; np++) {
                uint32_t bo2 = (b_row + np * 16) * ROWB + b_kb + ks * 32;
                LDSM4(bhf[np], st + HOFF_BH + bo2);
            }
            #pragma unroll
            for (int mf = 0; mf < 4; mf++) {
                uint32_t ah[4], al[4];
                uint32_t ao = (a_row + mf * 16) * ROWB + a_kb + ks * 32;
                LDSM4(ah, st + HOFF_AH + ao);
                if (TERMS == 2) LDSM4(al, st + HOFF_AL + ao);
                #pragma unroll
                for (int np = 0; np < 2; np++) {
                    MMA16816H(acc[mf][np*2],   ah, bhf[np][0], bhf[np][1]);
                    MMA16816H(acc[mf][np*2+1], ah, bhf[np][2], bhf[np][3]);
                }
                if (TERMS == 2) {
                    #pragma unroll
                    for (int np = 0; np < 2; np++) {
                        MMA16816H(acc[mf][np*2],   al, bhf[np][0], bhf[np][1]);
                        MMA16816H(acc[mf][np*2+1], al, bhf[np][2], bhf[np][3]);
                    }
                }
            }
        }
        __syncthreads();
    }

    const int mrow = m0 + wm * 64 + (lane >> 2);
    const int ncol = n0 + wn * 32 + (lane & 3) * 2;

    #pragma unroll
    for (int mf = 0; mf < 4; mf++) {
        #pragma unroll
        for (int half2i = 0; half2i < 2; half2i++) {
            const int m = mrow + mf * 16 + half2i * 8;
            #pragma unroll
            for (int nf = 0; nf < 4; nf++) {
                const int n = ncol + nf * 8;
                float v0 = acc[mf][nf][half2i * 2]     + __ldg(&bias[n]);
                float v1 = acc[mf][nf][half2i * 2 + 1] + __ldg(&bias[n + 1]);
                if (OUTH) {                // V: (BH,T,D) fp16 single
                    const int t = m >> 3, b = m & 7, h = n >> 8, d = n & 255;
                    size_t o = ((size_t)(b * HH + h) * TT + t) * DH + d;
                    __half2 p; p.x = __float2half(v0); p.y = __float2half(v1);
                    *(__half2*)(outH + o) = p;
                } else {                   // out projection: fp32 (T*B, F)
                    size_t o = (size_t)m * FD + n;
                    float2 f; f.x = v0; f.y = v1;
                    *(float2*)(outF + o) = f;
                }
            }
        }
    }
}

// --------------------------- fused flash attention --------------------------
// CTA: 64 q-rows of one bh; 16 kv-tiles of 128 t. 256 threads, warps 2m x 4n.
// QK: fp16 1-term (Q single x K single), warp tile m32 x t32.
// AV: fp16 1-term (P single x V single), warp tile m32 x d32.
// Q resident 32KB (4 mats of 64d). Ping-pong 32KB buffers for K/V chunks.
#define Q_OFF 0           // 32KB: mats j*8192
#define B0_OFF 32768      // 32KB
#define B1_OFF 65536      // 32KB
#define P_OFF 98304       // 16KB: two 8KB t-half mats
#define RMAX_OFF 114688
#define RSUM_OFF 115712
#define ATT_SMEM 116736
#define NKV (TT/128)      // 16

__global__ __launch_bounds__(256, 1) void attn_kernel()
{
    extern __shared__ char sm[];
    const uint32_t sb = smem_u32(sm);
    const int tid = threadIdx.x, lane = tid & 31, wid = tid >> 5;
    const int wm = wid >> 2, wn = wid & 3;             // 2m x 4n
    const int bh = blockIdx.y, m0 = blockIdx.x * 64;

    auto load_k = [&](int tile, int c, uint32_t bufoff) {
        #pragma unroll
        for (int dh = 0; dh < 2; dh++) {
            #pragma unroll
            for (int i = 0; i < 4; i++) {
                int ci = tid + i * 256;
                int r = ci >> 3, cc = ci & 7;
                size_t g = ((size_t)bh * TT + tile * 128 + r) * DH + c * 128 + dh * 64 + cc * 8;
                CP16(sb + bufoff + dh * 16384 + SWZ(r * 128 + cc * 16), g_k16 + g);
            }
        }
    };
    auto load_v = [&](int tile, int c, uint32_t bufoff) {
        #pragma unroll
        for (int dh = 0; dh < 2; dh++) {
            #pragma unroll
            for (int i = 0; i < 4; i++) {
                int ci = tid + i * 256;
                int r = ci >> 3, cc = ci & 7;
                size_t g = ((size_t)bh * TT + tile * 128 + r) * DH + c * 128 + dh * 64 + cc * 8;
                CP16(sb + bufoff + dh * 16384 + SWZ(r * 128 + cc * 16), g_v16 + g);
            }
        }
    };

    // Q resident: 4 mats [j 0..3] of [64 rows x 64 d]
    #pragma unroll
    for (int i = 0; i < 8; i++) {
        int ci = tid + i * 256;
        int mat = ci >> 9, w = ci & 511, r = w >> 3, c = w & 7;
        size_t g = ((size_t)bh * TT + m0 + r) * DH + mat * 64 + c * 8;
        CP16(sb + Q_OFF + mat * 8192 + SWZ(r * 128 + c * 16), g_q16 + g);
    }
    load_k(0, 0, B0_OFF); CP_COMMIT();
    load_k(0, 1, B1_OFF); CP_COMMIT();

    const int a_rl = (lane & 7) + ((lane >> 3) & 1) * 8;
    const int a_kb = ((lane >> 4) & 1) * 16;
    const int b_rl = (lane & 7) + (lane >= 16 ? 8 : 0);
    const int b_kb = ((lane >> 3) & 1) * 16;
    const int v_rl = (lane & 7) + ((lane >> 3) & 1) * 8;
    const int v_cb = ((lane >> 4) & 1) * 16;

    float oacc[16][4] = {};
    float sacc[8][4];
    float mrun[2][2], lrun[2][2];
    #pragma unroll
    for (int i = 0; i < 2; i++)
        #pragma unroll
        for (int j = 0; j < 2; j++) { mrun[i][j] = -1e30f; lrun[i][j] = 0.f; }

    const int rl = lane >> 2;
    float* rmax = (float*)(sm + RMAX_OFF);   // [4 wn][64 rows]
    float* rsum = (float*)(sm + RSUM_OFF);

    for (int tile = 0; tile < NKV; tile++) {
        #pragma unroll
        for (int f = 0; f < 8; f++) { sacc[f][0]=0.f; sacc[f][1]=0.f; sacc[f][2]=0.f; sacc[f][3]=0.f; }

        // ---- QK: 2 phases over d-halves; fp16 1-term ----
        #pragma unroll
        for (int c = 0; c < 2; c++) {
            CP_WAIT1(); __syncthreads();
            const uint32_t kb_buf = sb + (c ? B1_OFF : B0_OFF);
            #pragma unroll
            for (int ks = 0; ks < 8; ks++) {
                const uint32_t qm = sb + Q_OFF + (c * 2 + (ks >> 2)) * 8192;
                const uint32_t km = kb_buf + (ks >> 2) * 16384;
                uint32_t q2[2][4], kh[2][4];
                #pragma unroll
                for (int mf = 0; mf < 2; mf++) {
                    uint32_t ao = SWZ((wm * 32 + mf * 16 + a_rl) * 128 + (ks & 3) * 32 + a_kb);
                    LDSM4(q2[mf], qm + ao);
                }
                #pragma unroll
                for (int g = 0; g < 2; g++) {
                    uint32_t bo = SWZ((wn * 32 + g * 16 + b_rl) * 128 + (ks & 3) * 32 + b_kb);
                    LDSM4(kh[g], km + bo);
                }
                #pragma unroll
                for (int mf = 0; mf < 2; mf++)
                    #pragma unroll
                    for (int g = 0; g < 2; g++) {
                        MMA16816H(sacc[mf*4+g*2],   q2[mf], kh[g][0], kh[g][1]);
                        MMA16816H(sacc[mf*4+g*2+1], q2[mf], kh[g][2], kh[g][3]);
                    }
            }
            __syncthreads();
            load_v(tile, c, c ? B1_OFF : B0_OFF);
            CP_COMMIT();
        }

        // ---- online softmax (log2 units via folded QSCALE) ----
        float mx[2][2];
        #pragma unroll
        for (int mf = 0; mf < 2; mf++) { mx[mf][0] = -1e30f; mx[mf][1] = -1e30f; }
        #pragma unroll
        for (int f = 0; f < 8; f++) {
            const int mf = f >> 2;
            mx[mf][0] = fmaxf(mx[mf][0], fmaxf(sacc[f][0], sacc[f][1]));
            mx[mf][1] = fmaxf(mx[mf][1], fmaxf(sacc[f][2], sacc[f][3]));
        }
        #pragma unroll
        for (int mf = 0; mf < 2; mf++)
            #pragma unroll
            for (int hf = 0; hf < 2; hf++) {
                mx[mf][hf] = fmaxf(mx[mf][hf], __shfl_xor_sync(0xffffffffu, mx[mf][hf], 1));
                mx[mf][hf] = fmaxf(mx[mf][hf], __shfl_xor_sync(0xffffffffu, mx[mf][hf], 2));
            }
        if ((lane & 3) == 0) {
            #pragma unroll
            for (int mf = 0; mf < 2; mf++)
                #pragma unroll
                for (int hf = 0; hf < 2; hf++)
                    rmax[wn * 64 + wm * 32 + mf * 16 + hf * 8 + rl] = mx[mf][hf];
        }
        __syncthreads();

        float aa[2][2];
        #pragma unroll
        for (int mf = 0; mf < 2; mf++)
            #pragma unroll
            for (int hf = 0; hf < 2; hf++) {
                const int row = wm * 32 + mf * 16 + hf * 8 + rl;
                float mn = mrun[mf][hf];
                #pragma unroll
                for (int w = 0; w < 4; w++) mn = fmaxf(mn, rmax[w * 64 + row]);
                aa[mf][hf] = exp2f(mrun[mf][hf] - mn);
                mrun[mf][hf] = mn;
            }

        float ss[2][2] = {};
        #pragma unroll
        for (int f = 0; f < 8; f++) {
            const int mf = f >> 2;
            sacc[f][0] = exp2f(sacc[f][0] - mrun[mf][0]);
            sacc[f][1] = exp2f(sacc[f][1] - mrun[mf][0]);
            sacc[f][2] = exp2f(sacc[f][2] - mrun[mf][1]);
            sacc[f][3] = exp2f(sacc[f][3] - mrun[mf][1]);
            ss[mf][0] += sacc[f][0] + sacc[f][1];
            ss[mf][1] += sacc[f][2] + sacc[f][3];
        }
        #pragma unroll
        for (int mf = 0; mf < 2; mf++)
            #pragma unroll
            for (int hf = 0; hf < 2; hf++) {
                ss[mf][hf] += __shfl_xor_sync(0xffffffffu, ss[mf][hf], 1);
                ss[mf][hf] += __shfl_xor_sync(0xffffffffu, ss[mf][hf], 2);
            }
        if ((lane & 3) == 0) {
            #pragma unroll
            for (int mf = 0; mf < 2; mf++)
                #pragma unroll
                for (int hf = 0; hf < 2; hf++)
                    rsum[wn * 64 + wm * 32 + mf * 16 + hf * 8 + rl] = ss[mf][hf];
        }

        // rescale O accumulators (skip when running max unchanged warp-wide)
        {
            bool need = (aa[0][0] < 1.f) || (aa[0][1] < 1.f) ||
                        (aa[1][0] < 1.f) || (aa[1][1] < 1.f);
            if (__any_sync(0xffffffffu, need)) {
                #pragma unroll
                for (int f = 0; f < 16; f++) {
                    const int mf = (f >> 2) & 1;
                    oacc[f][0] *= aa[mf][0]; oacc[f][1] *= aa[mf][0];
                    oacc[f][2] *= aa[mf][1]; oacc[f][3] *= aa[mf][1];
                }
            }
        }

        // P -> smem, fp16 single: two 8KB t-half mats
        {
            const int th = wn >> 1, cbase = (wn & 1) * 32;
            #pragma unroll
            for (int f = 0; f < 8; f++) {
                const int mf = f >> 2, g = (f >> 1) & 1, f8 = f & 1;
                const int colm = cbase + g * 16 + f8 * 8 + (lane & 3) * 2;
                const uint32_t pmo = P_OFF + th * 8192;
                __half2 p0; p0.x = __float2half(sacc[f][0]); p0.y = __float2half(sacc[f][1]);
                __half2 p1; p1.x = __float2half(sacc[f][2]); p1.y = __float2half(sacc[f][3]);
                uint32_t off = SWZ((wm * 32 + mf * 16 + rl) * 128 + colm * 2);
                *(__half2*)(sm + pmo + off) = p0;
                off = SWZ((wm * 32 + mf * 16 + 8 + rl) * 128 + colm * 2);
                *(__half2*)(sm + pmo + off) = p1;
            }
        }
        __syncthreads();

        #pragma unroll
        for (int mf = 0; mf < 2; mf++)
            #pragma unroll
            for (int hf = 0; hf < 2; hf++) {
                const int row = wm * 32 + mf * 16 + hf * 8 + rl;
                float s = 0.f;
                #pragma unroll
                for (int w = 0; w < 4; w++) s += rsum[w * 64 + row];
                lrun[mf][hf] = lrun[mf][hf] * aa[mf][hf] + s;
            }

        // ---- AV: 2 phases over d-halves; fp16 1-term (P single, V single) ----
        #pragma unroll
        for (int c = 0; c < 2; c++) {
            CP_WAIT1(); __syncthreads();
            const uint32_t v_buf = sb + (c ? B1_OFF : B0_OFF) + (wn >> 1) * 16384;
            const int vcb = (wn & 1) * 64;
            #pragma unroll
            for (int ks = 0; ks < 8; ks++) {
                const uint32_t pm = sb + P_OFF + (ks >> 2) * 8192;
                uint32_t ph2[2][4], vh[2][4];
                #pragma unroll
                for (int mf = 0; mf < 2; mf++) {
                    uint32_t ao = SWZ((wm * 32 + mf * 16 + a_rl) * 128 + (ks & 3) * 32 + a_kb);
                    LDSM4(ph2[mf], pm + ao);
                }
                const uint32_t vrow = ks * 16 + v_rl;
                #pragma unroll
                for (int g = 0; g < 2; g++) {
                    uint32_t bo = SWZ(vrow * 128 + vcb + g * 32 + v_cb);
                    LDSM4T(vh[g], v_buf + bo);
                }
                #pragma unroll
                for (int mf = 0; mf < 2; mf++)
                    #pragma unroll
                    for (int g = 0; g < 2; g++) {
                        MMA16816H(oacc[c*8+mf*4+g*2],   ph2[mf], vh[g][0], vh[g][1]);
                        MMA16816H(oacc[c*8+mf*4+g*2+1], ph2[mf], vh[g][2], vh[g][3]);
                    }
            }
            __syncthreads();
            if (tile + 1 < NKV) load_k(tile + 1, c, c ? B1_OFF : B0_OFF);
            CP_COMMIT();
        }
    }

    // ---- epilogue: normalize + write fp16 single for output projection ----
    const int bb = bh / HH, hh = bh % HH;
    #pragma unroll
    for (int f = 0; f < 16; f++) {
        const int c = f >> 3, mf = (f >> 2) & 1, g = (f >> 1) & 1, f8 = f & 1;
        const int d = c * 128 + wn * 32 + g * 16 + f8 * 8 + (lane & 3) * 2;
        #pragma unroll
        for (int hf = 0; hf < 2; hf++) {
            const int t = m0 + wm * 32 + mf * 16 + hf * 8 + rl;
            const float inv = 1.f / lrun[mf][hf];
            float v0 = oacc[f][hf*2] * inv, v1 = oacc[f][hf*2+1] * inv;
            size_t o = ((size_t)t * BB + bb) * FD + hh * DH + d;
            __half2 p; p.x = __float2half(v0); p.y = __float2half(v1);
            *(__half2*)(g_o16 + o) = p;
        }
    }
}

// ------------------------------ helper kernels ------------------------------
// x -> bf16 hi/lo (Q,K proj) + fp16 hi/lo (V proj)
__global__ __launch_bounds__(256) void split_x_kernel(
    const float* __restrict__ in, int n4)
{
    int i = blockIdx.x * 256 + threadIdx.x;
    if (i >= n4) return;
    float4 v = *(const float4*)(in + (size_t)i * 4);
    {
        __nv_bfloat16 h0,l0,h1,l1,h2,l2,h3,l3;
        split2(v.x,h0,l0); split2(v.y,h1,l1); split2(v.z,h2,l2); split2(v.w,h3,l3);
        __nv_bfloat162 a; a.x=h0; a.y=h1; __nv_bfloat162 b; b.x=h2; b.y=h3;
        __nv_bfloat162 c; c.x=l0; c.y=l1; __nv_bfloat162 d; d.x=l2; d.y=l3;
        *(__nv_bfloat162*)(g_xh + (size_t)i*4)     = a;
        *(__nv_bfloat162*)(g_xh + (size_t)i*4 + 2) = b;
        *(__nv_bfloat162*)(g_xl + (size_t)i*4)     = c;
        *(__nv_bfloat162*)(g_xl + (size_t)i*4 + 2) = d;
    }
    {
        __half h0,l0,h1,l1,h2,l2,h3,l3;
        split2h(v.x,h0,l0); split2h(v.y,h1,l1); split2h(v.z,h2,l2); split2h(v.w,h3,l3);
        __half2 a; a.x=h0; a.y=h1; __half2 b; b.x=h2; b.y=h3;
        __half2 c; c.x=l0; c.y=l1; __half2 d; d.x=l2; d.y=l3;
        *(__half2*)(g_xh16 + (size_t)i*4)     = a;
        *(__half2*)(g_xh16 + (size_t)i*4 + 2) = b;
        *(__half2*)(g_xl16 + (size_t)i*4)     = c;
        *(__half2*)(g_xl16 + (size_t)i*4 + 2) = d;
    }
}

// Wq,Wk -> bf16 hi/lo; Wv,Wo -> fp16 single
__global__ __launch_bounds__(256) void split_w_kernel(
    const float* __restrict__ w0, const float* __restrict__ w1,
    const float* __restrict__ w2, const float* __restrict__ w3)
{
    const int which = blockIdx.y;
    int i = blockIdx.x * 256 + threadIdx.x;
    if (i >= FD*FD/4) return;
    const float* in = which == 0 ? w0 : which == 1 ? w1 : which == 2 ? w2 : w3;
    float4 v = *(const float4*)(in + (size_t)i * 4);
    if (which <= 1) {
        __nv_bfloat16* h = which == 0 ? g_wqh : g_wkh;
        __nv_bfloat16* l = which == 0 ? g_wql : g_wkl;
        __nv_bfloat16 a0,b0,a1,b1,a2,b2,a3,b3;
        split2(v.x,a0,b0); split2(v.y,a1,b1); split2(v.z,a2,b2); split2(v.w,a3,b3);
        __nv_bfloat162 p; p.x=a0; p.y=a1; __nv_bfloat162 q; q.x=a2; q.y=a3;
        __nv_bfloat162 r; r.x=b0; r.y=b1; __nv_bfloat162 s; s.x=b2; s.y=b3;
        *(__nv_bfloat162*)(h + (size_t)i*4)     = p;
        *(__nv_bfloat162*)(h + (size_t)i*4 + 2) = q;
        *(__nv_bfloat162*)(l + (size_t)i*4)     = r;
        *(__nv_bfloat162*)(l + (size_t)i*4 + 2) = s;
    } else {
        __half* h = which == 2 ? g_wv16 : g_wo16;
        __half2 p; p.x=__float2half(v.x); p.y=__float2half(v.y);
        __half2 q; q.x=__float2half(v.z); q.y=__float2half(v.w);
        *(__half2*)(h + (size_t)i*4)     = p;
        *(__half2*)(h + (size_t)i*4 + 2) = q;
    }
}

// --------------------------------- launch ----------------------------------
extern "C" void kernel_launch(void* const* d_in, const int* in_sizes, int n_in,
                              void* d_out, int out_size)
{
    const float* x  = (const float*)d_in[0];
    const float* Wq = (const float*)d_in[1];
    const float* bq = (const float*)d_in[2];
    const float* Wk = (const float*)d_in[3];
    const float* bk = (const float*)d_in[4];
    const float* Wv = (const float*)d_in[5];
    const float* bv = (const float*)d_in[6];
    const float* Wo = (const float*)d_in[7];
    const float* bo = (const float*)d_in[8];
    float* out = (float*)d_out;

    constexpr int H2_SMEM = 3 * (2 * MAT_A + MAT_B);   // 153600
    constexpr int H1_SMEM = 3 * (MAT_A + MAT_B);       // 92160

    cudaFuncSetAttribute(gemm_bf3,        cudaFuncAttributeMaxDynamicSharedMemorySize, SMEM_BYTES);
    cudaFuncSetAttribute(gemm_h<2,true>,  cudaFuncAttributeMaxDynamicSharedMemorySize, H2_SMEM);
    cudaFuncSetAttribute(gemm_h<1,false>, cudaFuncAttributeMaxDynamicSharedMemorySize, H1_SMEM);
    cudaFuncSetAttribute(attn_kernel,     cudaFuncAttributeMaxDynamicSharedMemorySize, ATT_SMEM);

    __half *xh16, *xl16, *wv16, *wo16, *o16;
    cudaGetSymbolAddress((void**)&xh16, g_xh16);
    cudaGetSymbolAddress((void**)&xl16, g_xl16);
    cudaGetSymbolAddress((void**)&wv16, g_wv16);
    cudaGetSymbolAddress((void**)&wo16, g_wo16);
    cudaGetSymbolAddress((void**)&o16,  g_o16);

    // 0: x split
    split_x_kernel<<<(MROWS*FD/4 + 255)/256, 256>>>(x, MROWS*FD/4);
    // 1: W splits
    dim3 gW((FD*FD/4 + 255)/256, 4);
    split_w_kernel<<<gW, 256>>>(Wq, Wk, Wv, Wo);
    // 2: Q,K projections (bf16 3-term), z = 0,1
    dim3 gQK(MROWS/BM, FD/BN, 2);
    gemm_bf3<<<gQK, 512, SMEM_BYTES>>>(bq, bk);
    // 3: V projection (fp16 2-term)
    dim3 gP(MROWS/BM, FD/BN);
    __half* vdst; cudaGetSymbolAddress((void**)&vdst, g_v16);
    gemm_h<2,true><<<gP, 512, H2_SMEM>>>(xh16, xl16, wv16, bv, vdst, nullptr);
    // 4: fused flash attention
    dim3 gA(TT/64, NBH);
    attn_kernel<<<gA, 256, ATT_SMEM>>>();
    // 5: output projection (fp16 1-term)
    gemm_h<1,false><<<gP, 512, H1_SMEM>>>(o16, nullptr, wo16, bo, nullptr, out);
}

// round 13
// speedup vs baseline: 1.8725x; 1.1748x over previous
#include <cuda_runtime.h>
#include <cuda_bf16.h>
#include <cuda_fp16.h>
#include <cstdint>

#define TT 2048
#define BB 8
#define FD 768
#define HH 3
#define DH 256
#define MROWS (TT*BB)      // 16384
#define NBH (BB*HH)        // 24

// ------------------------- device scratch (static) -------------------------
__device__ __align__(16) __half g_xh16[MROWS*FD], g_xl16[MROWS*FD];  // x fp16 hi/lo
__device__ __align__(16) __half g_wq16[FD*FD];                       // W single fp16
__device__ __align__(16) __half g_wk16[FD*FD];
__device__ __align__(16) __half g_wv16[FD*FD];
__device__ __align__(16) __half g_wo16[FD*FD];
__device__ __align__(16) __half g_q16[NBH*TT*DH];                    // Q fp16 (scaled)
__device__ __align__(16) __half g_k16[NBH*TT*DH];                    // K fp16
__device__ __align__(16) __half g_v16[NBH*TT*DH];                    // V fp16
__device__ __align__(16) __half g_o16[MROWS*FD];                     // attn out fp16

// ------------------------------ PTX helpers --------------------------------
__device__ __forceinline__ uint32_t smem_u32(const void* p) {
    uint32_t a;
    asm("{ .reg .u64 t; cvta.to.shared.u64 t, %1; cvt.u32.u64 %0, t; }" : "=r"(a) : "l"(p));
    return a;
}
#define CP16(dst, src) \
    asm volatile("cp.async.cg.shared.global [%0], [%1], 16;" :: "r"(dst), "l"(src) : "memory")
#define CP_COMMIT() asm volatile("cp.async.commit_group;" ::: "memory")
#define CP_WAIT1()  asm volatile("cp.async.wait_group 1;" ::: "memory")

#define LDSM4(r, addr) \
    asm volatile("ldmatrix.sync.aligned.m8n8.x4.shared.b16 {%0,%1,%2,%3}, [%4];" \
        : "=r"((r)[0]), "=r"((r)[1]), "=r"((r)[2]), "=r"((r)[3]) : "r"(addr))
#define LDSM4T(r, addr) \
    asm volatile("ldmatrix.sync.aligned.m8n8.x4.trans.shared.b16 {%0,%1,%2,%3}, [%4];" \
        : "=r"((r)[0]), "=r"((r)[1]), "=r"((r)[2]), "=r"((r)[3]) : "r"(addr))

#define MMA16816H(d, a, b0v, b1v) \
    asm volatile("mma.sync.aligned.m16n8k16.row.col.f32.f16.f16.f32 " \
        "{%0,%1,%2,%3}, {%4,%5,%6,%7}, {%8,%9}, {%0,%1,%2,%3};" \
        : "+f"((d)[0]), "+f"((d)[1]), "+f"((d)[2]), "+f"((d)[3]) \
        : "r"((a)[0]), "r"((a)[1]), "r"((a)[2]), "r"((a)[3]), "r"(b0v), "r"(b1v))

#define SWZ(o) ((uint32_t)(o) ^ ((((uint32_t)(o)) >> 3) & 0x70))

__device__ __forceinline__ void split2h(float v, __half& h, __half& l) {
    h = __float2half(v);
    l = __float2half(v - __half2float(h));
}

#define QSCALE 0.1803368801111204f    // 0.125 * log2(e)

// ------------------ fp16 GEMM, TERMS in {1,2}, 512 threads ------------------
#define BM 256
#define BN 128
#define BK 32
#define ROWB 80
#define MAT_A (256*ROWB)
#define MAT_B (128*ROWB)
#define NSTAGE 3

// QKV projection: fp16 2-term (x hi/lo × W single). mode = blockIdx.z:
// 0=Q (scaled fp16 out), 1=K, 2=V.
__global__ __launch_bounds__(512, 1) void gemm_qkv(
    const float* __restrict__ bq, const float* __restrict__ bk,
    const float* __restrict__ bv)
{
    constexpr int OFF_AH = 0;
    constexpr int OFF_AL = MAT_A;
    constexpr int OFF_B  = 2 * MAT_A;
    constexpr int STG    = 2 * MAT_A + MAT_B;

    extern __shared__ char smem[];
    const uint32_t sb = smem_u32(smem);

    const int tid = threadIdx.x;
    const int wid = tid >> 5, lane = tid & 31;
    const int wm = wid >> 2, wn = wid & 3;
    const int m0 = blockIdx.x * BM, n0 = blockIdx.y * BN;
    const int mode = blockIdx.z;
    const int K = FD;

    const __half* Bw = mode == 0 ? g_wq16 : mode == 1 ? g_wk16 : g_wv16;
    const float* bias = mode == 0 ? bq : mode == 1 ? bk : bv;

    float acc[4][4][4] = {};

    const int ra0 = tid >> 2,          ca0 = tid & 3;
    const int ra1 = (tid + 512) >> 2,  ca1 = (tid + 512) & 3;
    const int rb  = tid >> 2,          cb  = tid & 3;

    auto load_stage = [&](int kb, int s) {
        const uint32_t st = sb + s * STG;
        {
            size_t g = (size_t)(m0 + ra0) * K + kb * BK + ca0 * 8;
            uint32_t so = ra0 * ROWB + ca0 * 16;
            CP16(st + OFF_AH + so, g_xh16 + g);
            CP16(st + OFF_AL + so, g_xl16 + g);
        }
        {
            size_t g = (size_t)(m0 + ra1) * K + kb * BK + ca1 * 8;
            uint32_t so = ra1 * ROWB + ca1 * 16;
            CP16(st + OFF_AH + so, g_xh16 + g);
            CP16(st + OFF_AL + so, g_xl16 + g);
        }
        {
            size_t g = (size_t)(n0 + rb) * K + kb * BK + cb * 8;
            uint32_t so = rb * ROWB + cb * 16;
            CP16(st + OFF_B + so, Bw + g);
        }
    };

    const int NKB = K / BK;
    load_stage(0, 0); CP_COMMIT();
    load_stage(1, 1); CP_COMMIT();

    const int a_row = wm * 64 + (lane & 7) + ((lane >> 3) & 1) * 8;
    const int a_kb  = ((lane >> 4) & 1) * 16;
    const int b_row = wn * 32 + (lane & 7) + (lane >= 16 ? 8 : 0);
    const int b_kb  = ((lane >> 3) & 1) * 16;

    for (int kb = 0; kb < NKB; kb++) {
        CP_WAIT1();
        __syncthreads();
        if (kb + 2 < NKB) load_stage(kb + 2, (kb + 2) % NSTAGE);
        CP_COMMIT();

        const uint32_t st = sb + (kb % NSTAGE) * STG;
        #pragma unroll
        for (int ks = 0; ks < 2; ks++) {
            uint32_t bhf[2][4];
            #pragma unroll
            for (int np = 0; np < 2; np++) {
                uint32_t bo2 = (b_row + np * 16) * ROWB + b_kb + ks * 32;
                LDSM4(bhf[np], st + OFF_B + bo2);
            }
            #pragma unroll
            for (int mf = 0; mf < 4; mf++) {
                uint32_t ah[4], al[4];
                uint32_t ao = (a_row + mf * 16) * ROWB + a_kb + ks * 32;
                LDSM4(ah, st + OFF_AH + ao);
                LDSM4(al, st + OFF_AL + ao);
                #pragma unroll
                for (int np = 0; np < 2; np++) {
                    MMA16816H(acc[mf][np*2],   ah, bhf[np][0], bhf[np][1]);
                    MMA16816H(acc[mf][np*2+1], ah, bhf[np][2], bhf[np][3]);
                }
                #pragma unroll
                for (int np = 0; np < 2; np++) {
                    MMA16816H(acc[mf][np*2],   al, bhf[np][0], bhf[np][1]);
                    MMA16816H(acc[mf][np*2+1], al, bhf[np][2], bhf[np][3]);
                }
            }
        }
        __syncthreads();
    }

    const int mrow = m0 + wm * 64 + (lane >> 2);
    const int ncol = n0 + wn * 32 + (lane & 3) * 2;
    const float oscale = (mode == 0) ? QSCALE : 1.0f;
    __half* dst = mode == 0 ? g_q16 : mode == 1 ? g_k16 : g_v16;

    #pragma unroll
    for (int mf = 0; mf < 4; mf++) {
        #pragma unroll
        for (int hi = 0; hi < 2; hi++) {
            const int m = mrow + mf * 16 + hi * 8;
            #pragma unroll
            for (int nf = 0; nf < 4; nf++) {
                const int n = ncol + nf * 8;
                float v0 = (acc[mf][nf][hi * 2]     + __ldg(&bias[n]))     * oscale;
                float v1 = (acc[mf][nf][hi * 2 + 1] + __ldg(&bias[n + 1])) * oscale;
                const int t = m >> 3, b = m & 7, h = n >> 8, d = n & 255;
                size_t o = ((size_t)(b * HH + h) * TT + t) * DH + d;
                __half2 p; p.x = __float2half(v0); p.y = __float2half(v1);
                *(__half2*)(dst + o) = p;
            }
        }
    }
}

// O projection: fp16 1-term (o single × Wo single), fp32 out
__global__ __launch_bounds__(512, 1) void gemm_out(
    const float* __restrict__ bias, float* __restrict__ outF)
{
    constexpr int OFF_A = 0;
    constexpr int OFF_B = MAT_A;
    constexpr int STG   = MAT_A + MAT_B;

    extern __shared__ char smem[];
    const uint32_t sb = smem_u32(smem);

    const int tid = threadIdx.x;
    const int wid = tid >> 5, lane = tid & 31;
    const int wm = wid >> 2, wn = wid & 3;
    const int m0 = blockIdx.x * BM, n0 = blockIdx.y * BN;
    const int K = FD;

    float acc[4][4][4] = {};

    const int ra0 = tid >> 2,          ca0 = tid & 3;
    const int ra1 = (tid + 512) >> 2,  ca1 = (tid + 512) & 3;
    const int rb  = tid >> 2,          cb  = tid & 3;

    auto load_stage = [&](int kb, int s) {
        const uint32_t st = sb + s * STG;
        {
            size_t g = (size_t)(m0 + ra0) * K + kb * BK + ca0 * 8;
            CP16(st + OFF_A + ra0 * ROWB + ca0 * 16, g_o16 + g);
        }
        {
            size_t g = (size_t)(m0 + ra1) * K + kb * BK + ca1 * 8;
            CP16(st + OFF_A + ra1 * ROWB + ca1 * 16, g_o16 + g);
        }
        {
            size_t g = (size_t)(n0 + rb) * K + kb * BK + cb * 8;
            CP16(st + OFF_B + rb * ROWB + cb * 16, g_wo16 + g);
        }
    };

    const int NKB = K / BK;
    load_stage(0, 0); CP_COMMIT();
    load_stage(1, 1); CP_COMMIT();

    const int a_row = wm * 64 + (lane & 7) + ((lane >> 3) & 1) * 8;
    const int a_kb  = ((lane >> 4) & 1) * 16;
    const int b_row = wn * 32 + (lane & 7) + (lane >= 16 ? 8 : 0);
    const int b_kb  = ((lane >> 3) & 1) * 16;

    for (int kb = 0; kb < NKB; kb++) {
        CP_WAIT1();
        __syncthreads();
        if (kb + 2 < NKB) load_stage(kb + 2, (kb + 2) % NSTAGE);
        CP_COMMIT();

        const uint32_t st = sb + (kb % NSTAGE) * STG;
        #pragma unroll
        for (int ks = 0; ks < 2; ks++) {
            uint32_t bhf[2][4];
            #pragma unroll
            for (int np = 0; np < 2; np++) {
                uint32_t bo2 = (b_row + np * 16) * ROWB + b_kb + ks * 32;
                LDSM4(bhf[np], st + OFF_B + bo2);
            }
            #pragma unroll
            for (int mf = 0; mf < 4; mf++) {
                uint32_t ah[4];
                uint32_t ao = (a_row + mf * 16) * ROWB + a_kb + ks * 32;
                LDSM4(ah, st + OFF_A + ao);
                #pragma unroll
                for (int np = 0; np < 2; np++) {
                    MMA16816H(acc[mf][np*2],   ah, bhf[np][0], bhf[np][1]);
                    MMA16816H(acc[mf][np*2+1], ah, bhf[np][2], bhf[np][3]);
                }
            }
        }
        __syncthreads();
    }

    const int mrow = m0 + wm * 64 + (lane >> 2);
    const int ncol = n0 + wn * 32 + (lane & 3) * 2;

    #pragma unroll
    for (int mf = 0; mf < 4; mf++) {
        #pragma unroll
        for (int hi = 0; hi < 2; hi++) {
            const int m = mrow + mf * 16 + hi * 8;
            #pragma unroll
            for (int nf = 0; nf < 4; nf++) {
                const int n = ncol + nf * 8;
                float2 f;
                f.x = acc[mf][nf][hi * 2]     + __ldg(&bias[n]);
                f.y = acc[mf][nf][hi * 2 + 1] + __ldg(&bias[n + 1]);
                *(float2*)(outF + (size_t)m * FD + n) = f;
            }
        }
    }
}

// --------------------------- fused flash attention --------------------------
// CTA: 64 q-rows of one bh; 16 kv-tiles of 128 t. 256 threads, warps 2m x 4n.
// QK: fp16 1-term, warp tile m32 x t32.  AV: fp16 1-term, warp tile m32 x d32.
#define Q_OFF 0           // 32KB: mats j*8192
#define B0_OFF 32768      // 32KB
#define B1_OFF 65536      // 32KB
#define P_OFF 98304       // 16KB: two 8KB t-half mats
#define RMAX_OFF 114688
#define RSUM_OFF 115712
#define ATT_SMEM 116736
#define NKV (TT/128)      // 16

__global__ __launch_bounds__(256, 1) void attn_kernel()
{
    extern __shared__ char sm[];
    const uint32_t sb = smem_u32(sm);
    const int tid = threadIdx.x, lane = tid & 31, wid = tid >> 5;
    const int wm = wid >> 2, wn = wid & 3;             // 2m x 4n
    const int bh = blockIdx.y, m0 = blockIdx.x * 64;

    auto load_kv = [&](const __half* __restrict__ src, int tile, int c, uint32_t bufoff) {
        #pragma unroll
        for (int dh = 0; dh < 2; dh++) {
            #pragma unroll
            for (int i = 0; i < 4; i++) {
                int ci = tid + i * 256;
                int r = ci >> 3, cc = ci & 7;
                size_t g = ((size_t)bh * TT + tile * 128 + r) * DH + c * 128 + dh * 64 + cc * 8;
                CP16(sb + bufoff + dh * 16384 + SWZ(r * 128 + cc * 16), src + g);
            }
        }
    };

    // Q resident: 4 mats [j 0..3] of [64 rows x 64 d]
    #pragma unroll
    for (int i = 0; i < 8; i++) {
        int ci = tid + i * 256;
        int mat = ci >> 9, w = ci & 511, r = w >> 3, c = w & 7;
        size_t g = ((size_t)bh * TT + m0 + r) * DH + mat * 64 + c * 8;
        CP16(sb + Q_OFF + mat * 8192 + SWZ(r * 128 + c * 16), g_q16 + g);
    }
    load_kv(g_k16, 0, 0, B0_OFF); CP_COMMIT();
    load_kv(g_k16, 0, 1, B1_OFF); CP_COMMIT();

    const int a_rl = (lane & 7) + ((lane >> 3) & 1) * 8;
    const int a_kb = ((lane >> 4) & 1) * 16;
    const int b_rl = (lane & 7) + (lane >= 16 ? 8 : 0);
    const int b_kb = ((lane >> 3) & 1) * 16;
    const int v_rl = (lane & 7) + ((lane >> 3) & 1) * 8;
    const int v_cb = ((lane >> 4) & 1) * 16;

    float oacc[16][4] = {};
    float sacc[8][4];
    float mrun[2][2], lrun[2][2];
    #pragma unroll
    for (int i = 0; i < 2; i++)
        #pragma unroll
        for (int j = 0; j < 2; j++) { mrun[i][j] = -1e30f; lrun[i][j] = 0.f; }

    const int rl = lane >> 2;
    float* rmax = (float*)(sm + RMAX_OFF);   // [4 wn][64 rows]
    float* rsum = (float*)(sm + RSUM_OFF);

    for (int tile = 0; tile < NKV; tile++) {
        #pragma unroll
        for (int f = 0; f < 8; f++) { sacc[f][0]=0.f; sacc[f][1]=0.f; sacc[f][2]=0.f; sacc[f][3]=0.f; }

        // ---- QK: 2 phases over d-halves; fp16 1-term ----
        #pragma unroll
        for (int c = 0; c < 2; c++) {
            CP_WAIT1(); __syncthreads();
            const uint32_t kb_buf = sb + (c ? B1_OFF : B0_OFF);
            #pragma unroll
            for (int ks = 0; ks < 8; ks++) {
                const uint32_t qm = sb + Q_OFF + (c * 2 + (ks >> 2)) * 8192;
                const uint32_t km = kb_buf + (ks >> 2) * 16384;
                uint32_t q2[2][4], kh[2][4];
                #pragma unroll
                for (int mf = 0; mf < 2; mf++) {
                    uint32_t ao = SWZ((wm * 32 + mf * 16 + a_rl) * 128 + (ks & 3) * 32 + a_kb);
                    LDSM4(q2[mf], qm + ao);
                }
                #pragma unroll
                for (int g = 0; g < 2; g++) {
                    uint32_t bo = SWZ((wn * 32 + g * 16 + b_rl) * 128 + (ks & 3) * 32 + b_kb);
                    LDSM4(kh[g], km + bo);
                }
                #pragma unroll
                for (int mf = 0; mf < 2; mf++)
                    #pragma unroll
                    for (int g = 0; g < 2; g++) {
                        MMA16816H(sacc[mf*4+g*2],   q2[mf], kh[g][0], kh[g][1]);
                        MMA16816H(sacc[mf*4+g*2+1], q2[mf], kh[g][2], kh[g][3]);
                    }
            }
            __syncthreads();
            load_kv(g_v16, tile, c, c ? B1_OFF : B0_OFF);
            CP_COMMIT();
        }

        // ---- online softmax (log2 units via folded QSCALE) ----
        float mx[2][2];
        #pragma unroll
        for (int mf = 0; mf < 2; mf++) { mx[mf][0] = -1e30f; mx[mf][1] = -1e30f; }
        #pragma unroll
        for (int f = 0; f < 8; f++) {
            const int mf = f >> 2;
            mx[mf][0] = fmaxf(mx[mf][0], fmaxf(sacc[f][0], sacc[f][1]));
            mx[mf][1] = fmaxf(mx[mf][1], fmaxf(sacc[f][2], sacc[f][3]));
        }
        #pragma unroll
        for (int mf = 0; mf < 2; mf++)
            #pragma unroll
            for (int hf = 0; hf < 2; hf++) {
                mx[mf][hf] = fmaxf(mx[mf][hf], __shfl_xor_sync(0xffffffffu, mx[mf][hf], 1));
                mx[mf][hf] = fmaxf(mx[mf][hf], __shfl_xor_sync(0xffffffffu, mx[mf][hf], 2));
            }
        if ((lane & 3) == 0) {
            #pragma unroll
            for (int mf = 0; mf < 2; mf++)
                #pragma unroll
                for (int hf = 0; hf < 2; hf++)
                    rmax[wn * 64 + wm * 32 + mf * 16 + hf * 8 + rl] = mx[mf][hf];
        }
        __syncthreads();

        float aa[2][2];
        #pragma unroll
        for (int mf = 0; mf < 2; mf++)
            #pragma unroll
            for (int hf = 0; hf < 2; hf++) {
                const int row = wm * 32 + mf * 16 + hf * 8 + rl;
                float mn = mrun[mf][hf];
                #pragma unroll
                for (int w = 0; w < 4; w++) mn = fmaxf(mn, rmax[w * 64 + row]);
                aa[mf][hf] = exp2f(mrun[mf][hf] - mn);
                mrun[mf][hf] = mn;
            }

        float ss[2][2] = {};
        #pragma unroll
        for (int f = 0; f < 8; f++) {
            const int mf = f >> 2;
            sacc[f][0] = exp2f(sacc[f][0] - mrun[mf][0]);
            sacc[f][1] = exp2f(sacc[f][1] - mrun[mf][0]);
            sacc[f][2] = exp2f(sacc[f][2] - mrun[mf][1]);
            sacc[f][3] = exp2f(sacc[f][3] - mrun[mf][1]);
            ss[mf][0] += sacc[f][0] + sacc[f][1];
            ss[mf][1] += sacc[f][2] + sacc[f][3];
        }
        #pragma unroll
        for (int mf = 0; mf < 2; mf++)
            #pragma unroll
            for (int hf = 0; hf < 2; hf++) {
                ss[mf][hf] += __shfl_xor_sync(0xffffffffu, ss[mf][hf], 1);
                ss[mf][hf] += __shfl_xor_sync(0xffffffffu, ss[mf][hf], 2);
            }
        if ((lane & 3) == 0) {
            #pragma unroll
            for (int mf = 0; mf < 2; mf++)
                #pragma unroll
                for (int hf = 0; hf < 2; hf++)
                    rsum[wn * 64 + wm * 32 + mf * 16 + hf * 8 + rl] = ss[mf][hf];
        }

        // rescale O accumulators (skip when running max unchanged warp-wide)
        {
            bool need = (aa[0][0] < 1.f) || (aa[0][1] < 1.f) ||
                        (aa[1][0] < 1.f) || (aa[1][1] < 1.f);
            if (__any_sync(0xffffffffu, need)) {
                #pragma unroll
                for (int f = 0; f < 16; f++) {
                    const int mf = (f >> 2) & 1;
                    oacc[f][0] *= aa[mf][0]; oacc[f][1] *= aa[mf][0];
                    oacc[f][2] *= aa[mf][1]; oacc[f][3] *= aa[mf][1];
                }
            }
        }

        // P -> smem, fp16 single: two 8KB t-half mats
        {
            const int th = wn >> 1, cbase = (wn & 1) * 32;
            #pragma unroll
            for (int f = 0; f < 8; f++) {
                const int mf = f >> 2, g = (f >> 1) & 1, f8 = f & 1;
                const int colm = cbase + g * 16 + f8 * 8 + (lane & 3) * 2;
                const uint32_t pmo = P_OFF + th * 8192;
                __half2 p0; p0.x = __float2half(sacc[f][0]); p0.y = __float2half(sacc[f][1]);
                __half2 p1; p1.x = __float2half(sacc[f][2]); p1.y = __float2half(sacc[f][3]);
                uint32_t off = SWZ((wm * 32 + mf * 16 + rl) * 128 + colm * 2);
                *(__half2*)(sm + pmo + off) = p0;
                off = SWZ((wm * 32 + mf * 16 + 8 + rl) * 128 + colm * 2);
                *(__half2*)(sm + pmo + off) = p1;
            }
        }
        __syncthreads();

        #pragma unroll
        for (int mf = 0; mf < 2; mf++)
            #pragma unroll
            for (int hf = 0; hf < 2; hf++) {
                const int row = wm * 32 + mf * 16 + hf * 8 + rl;
                float s = 0.f;
                #pragma unroll
                for (int w = 0; w < 4; w++) s += rsum[w * 64 + row];
                lrun[mf][hf] = lrun[mf][hf] * aa[mf][hf] + s;
            }

        // ---- AV: 2 phases over d-halves; fp16 1-term ----
        #pragma unroll
        for (int c = 0; c < 2; c++) {
            CP_WAIT1(); __syncthreads();
            const uint32_t v_buf = sb + (c ? B1_OFF : B0_OFF) + (wn >> 1) * 16384;
            const int vcb = (wn & 1) * 64;
            #pragma unroll
            for (int ks = 0; ks < 8; ks++) {
                const uint32_t pm = sb + P_OFF + (ks >> 2) * 8192;
                uint32_t ph2[2][4], vh[2][4];
                #pragma unroll
                for (int mf = 0; mf < 2; mf++) {
                    uint32_t ao = SWZ((wm * 32 + mf * 16 + a_rl) * 128 + (ks & 3) * 32 + a_kb);
                    LDSM4(ph2[mf], pm + ao);
                }
                const uint32_t vrow = ks * 16 + v_rl;
                #pragma unroll
                for (int g = 0; g < 2; g++) {
                    uint32_t bo = SWZ(vrow * 128 + vcb + g * 32 + v_cb);
                    LDSM4T(vh[g], v_buf + bo);
                }
                #pragma unroll
                for (int mf = 0; mf < 2; mf++)
                    #pragma unroll
                    for (int g = 0; g < 2; g++) {
                        MMA16816H(oacc[c*8+mf*4+g*2],   ph2[mf], vh[g][0], vh[g][1]);
                        MMA16816H(oacc[c*8+mf*4+g*2+1], ph2[mf], vh[g][2], vh[g][3]);
                    }
            }
            __syncthreads();
            if (tile + 1 < NKV) load_kv(g_k16, tile + 1, c, c ? B1_OFF : B0_OFF);
            CP_COMMIT();
        }
    }

    // ---- epilogue: normalize + write fp16 single for output projection ----
    const int bb = bh / HH, hh = bh % HH;
    #pragma unroll
    for (int f = 0; f < 16; f++) {
        const int c = f >> 3, mf = (f >> 2) & 1, g = (f >> 1) & 1, f8 = f & 1;
        const int d = c * 128 + wn * 32 + g * 16 + f8 * 8 + (lane & 3) * 2;
        #pragma unroll
        for (int hf = 0; hf < 2; hf++) {
            const int t = m0 + wm * 32 + mf * 16 + hf * 8 + rl;
            const float inv = 1.f / lrun[mf][hf];
            float v0 = oacc[f][hf*2] * inv, v1 = oacc[f][hf*2+1] * inv;
            size_t o = ((size_t)t * BB + bb) * FD + hh * DH + d;
            __half2 p; p.x = __float2half(v0); p.y = __float2half(v1);
            *(__half2*)(g_o16 + o) = p;
        }
    }
}

// ------------------------------ helper kernels ------------------------------
// x -> fp16 hi/lo
__global__ __launch_bounds__(256) void split_x_kernel(
    const float* __restrict__ in, int n4)
{
    int i = blockIdx.x * 256 + threadIdx.x;
    if (i >= n4) return;
    float4 v = *(const float4*)(in + (size_t)i * 4);
    __half h0,l0,h1,l1,h2,l2,h3,l3;
    split2h(v.x,h0,l0); split2h(v.y,h1,l1); split2h(v.z,h2,l2); split2h(v.w,h3,l3);
    __half2 a; a.x=h0; a.y=h1; __half2 b; b.x=h2; b.y=h3;
    __half2 c; c.x=l0; c.y=l1; __half2 d; d.x=l2; d.y=l3;
    *(__half2*)(g_xh16 + (size_t)i*4)     = a;
    *(__half2*)(g_xh16 + (size_t)i*4 + 2) = b;
    *(__half2*)(g_xl16 + (size_t)i*4)     = c;
    *(__half2*)(g_xl16 + (size_t)i*4 + 2) = d;
}

// all W -> single fp16
__global__ __launch_bounds__(256) void split_w_kernel(
    const float* __restrict__ w0, const float* __restrict__ w1,
    const float* __restrict__ w2, const float* __restrict__ w3)
{
    const int which = blockIdx.y;
    int i = blockIdx.x * 256 + threadIdx.x;
    if (i >= FD*FD/4) return;
    const float* in = which == 0 ? w0 : which == 1 ? w1 : which == 2 ? w2 : w3;
    __half* h = which == 0 ? g_wq16 : which == 1 ? g_wk16 : which == 2 ? g_wv16 : g_wo16;
    float4 v = *(const float4*)(in + (size_t)i * 4);
    __half2 p; p.x=__float2half(v.x); p.y=__float2half(v.y);
    __half2 q; q.x=__float2half(v.z); q.y=__float2half(v.w);
    *(__half2*)(h + (size_t)i*4)     = p;
    *(__half2*)(h + (size_t)i*4 + 2) = q;
}

// --------------------------------- launch ----------------------------------
extern "C" void kernel_launch(void* const* d_in, const int* in_sizes, int n_in,
                              void* d_out, int out_size)
{
    const float* x  = (const float*)d_in[0];
    const float* Wq = (const float*)d_in[1];
    const float* bq = (const float*)d_in[2];
    const float* Wk = (const float*)d_in[3];
    const float* bk = (const float*)d_in[4];
    const float* Wv = (const float*)d_in[5];
    const float* bv = (const float*)d_in[6];
    const float* Wo = (const float*)d_in[7];
    const float* bo = (const float*)d_in[8];
    float* out = (float*)d_out;

    constexpr int H2_SMEM = 3 * (2 * MAT_A + MAT_B);   // 153600
    constexpr int H1_SMEM = 3 * (MAT_A + MAT_B);       // 92160

    cudaFuncSetAttribute(gemm_qkv,    cudaFuncAttributeMaxDynamicSharedMemorySize, H2_SMEM);
    cudaFuncSetAttribute(gemm_out,    cudaFuncAttributeMaxDynamicSharedMemorySize, H1_SMEM);
    cudaFuncSetAttribute(attn_kernel, cudaFuncAttributeMaxDynamicSharedMemorySize, ATT_SMEM);

    // 0: x split (fp16 hi/lo)
    split_x_kernel<<<(MROWS*FD/4 + 255)/256, 256>>>(x, MROWS*FD/4);
    // 1: W splits (all single fp16)
    dim3 gW((FD*FD/4 + 255)/256, 4);
    split_w_kernel<<<gW, 256>>>(Wq, Wk, Wv, Wo);
    // 2: fused QKV projection (fp16 2-term), z = 0,1,2
    dim3 gQKV(MROWS/BM, FD/BN, 3);
    gemm_qkv<<<gQKV, 512, H2_SMEM>>>(bq, bk, bv);
    // 3: fused flash attention
    dim3 gA(TT/64, NBH);
    attn_kernel<<<gA, 256, ATT_SMEM>>>();
    // 4: output projection (fp16 1-term)
    dim3 gO(MROWS/BM, FD/BN);
    gemm_out<<<gO, 512, H1_SMEM>>>(bo, out);
}

// round 14
// speedup vs baseline: 2.4484x; 1.3075x over previous
#include <cuda_runtime.h>
#include <cuda_fp16.h>
#include <cstdint>

#define TT 2048
#define BB 8
#define FD 768
#define HH 3
#define DH 256
#define MROWS (TT*BB)      // 16384
#define NBH (BB*HH)        // 24

// ------------------------- device scratch (static) -------------------------
__device__ __align__(16) __half g_x16[MROWS*FD];                     // x fp16 single
__device__ __align__(16) __half g_wq16[FD*FD];
__device__ __align__(16) __half g_wk16[FD*FD];
__device__ __align__(16) __half g_wv16[FD*FD];
__device__ __align__(16) __half g_wo16[FD*FD];
__device__ __align__(16) __half g_q16[NBH*TT*DH];                    // Q fp16 (scaled)
__device__ __align__(16) __half g_k16[NBH*TT*DH];
__device__ __align__(16) __half g_v16[NBH*TT*DH];
__device__ __align__(16) __half g_o16[MROWS*FD];                     // attn out fp16

// ------------------------------ PTX helpers --------------------------------
__device__ __forceinline__ uint32_t smem_u32(const void* p) {
    uint32_t a;
    asm("{ .reg .u64 t; cvta.to.shared.u64 t, %1; cvt.u32.u64 %0, t; }" : "=r"(a) : "l"(p));
    return a;
}
#define CP16(dst, src) \
    asm volatile("cp.async.cg.shared.global [%0], [%1], 16;" :: "r"(dst), "l"(src) : "memory")
#define CP_COMMIT() asm volatile("cp.async.commit_group;" ::: "memory")
#define CP_WAIT1()  asm volatile("cp.async.wait_group 1;" ::: "memory")

#define LDSM4(r, addr) \
    asm volatile("ldmatrix.sync.aligned.m8n8.x4.shared.b16 {%0,%1,%2,%3}, [%4];" \
        : "=r"((r)[0]), "=r"((r)[1]), "=r"((r)[2]), "=r"((r)[3]) : "r"(addr))
#define LDSM4T(r, addr) \
    asm volatile("ldmatrix.sync.aligned.m8n8.x4.trans.shared.b16 {%0,%1,%2,%3}, [%4];" \
        : "=r"((r)[0]), "=r"((r)[1]), "=r"((r)[2]), "=r"((r)[3]) : "r"(addr))

#define MMA16816H(d, a, b0v, b1v) \
    asm volatile("mma.sync.aligned.m16n8k16.row.col.f32.f16.f16.f32 " \
        "{%0,%1,%2,%3}, {%4,%5,%6,%7}, {%8,%9}, {%0,%1,%2,%3};" \
        : "+f"((d)[0]), "+f"((d)[1]), "+f"((d)[2]), "+f"((d)[3]) \
        : "r"((a)[0]), "r"((a)[1]), "r"((a)[2]), "r"((a)[3]), "r"(b0v), "r"(b1v))

#define SWZ(o) ((uint32_t)(o) ^ ((((uint32_t)(o)) >> 3) & 0x70))

#define QSCALE 0.1803368801111204f    // 0.125 * log2(e)

// ---------------- fp16 1-term GEMM (all projections), 512 thr ---------------
#define BM 256
#define BN 128
#define BK 32
#define ROWB 80
#define MAT_A (256*ROWB)
#define MAT_B (128*ROWB)
#define NSTAGE 3
#define G1_STG  (MAT_A + MAT_B)       // 30720
#define G1_SMEM (NSTAGE*G1_STG)       // 92160

// mode = blockIdx.z + mode_base: 0=Q (scaled fp16 out), 1=K, 2=V, 3=O (fp32 out)
__global__ __launch_bounds__(512, 1) void gemm_1t(
    const __half* __restrict__ A, int mode_base,
    const float* __restrict__ bq, const float* __restrict__ bk,
    const float* __restrict__ bv, const float* __restrict__ bo,
    float* __restrict__ outF)
{
    constexpr int OFF_A = 0;
    constexpr int OFF_B = MAT_A;

    extern __shared__ char smem[];
    const uint32_t sb = smem_u32(smem);

    const int tid = threadIdx.x;
    const int wid = tid >> 5, lane = tid & 31;
    const int wm = wid >> 2, wn = wid & 3;
    const int m0 = blockIdx.x * BM, n0 = blockIdx.y * BN;
    const int mode = blockIdx.z + mode_base;
    const int K = FD;

    const __half* Bw = mode == 0 ? g_wq16 : mode == 1 ? g_wk16 : mode == 2 ? g_wv16 : g_wo16;
    const float* bias = mode == 0 ? bq : mode == 1 ? bk : mode == 2 ? bv : bo;

    float acc[4][4][4] = {};

    const int ra0 = tid >> 2,          ca0 = tid & 3;
    const int ra1 = (tid + 512) >> 2,  ca1 = (tid + 512) & 3;
    const int rb  = tid >> 2,          cb  = tid & 3;

    auto load_stage = [&](int kb, int s) {
        const uint32_t st = sb + s * G1_STG;
        {
            size_t g = (size_t)(m0 + ra0) * K + kb * BK + ca0 * 8;
            CP16(st + OFF_A + ra0 * ROWB + ca0 * 16, A + g);
        }
        {
            size_t g = (size_t)(m0 + ra1) * K + kb * BK + ca1 * 8;
            CP16(st + OFF_A + ra1 * ROWB + ca1 * 16, A + g);
        }
        {
            size_t g = (size_t)(n0 + rb) * K + kb * BK + cb * 8;
            CP16(st + OFF_B + rb * ROWB + cb * 16, Bw + g);
        }
    };

    const int NKB = K / BK;
    load_stage(0, 0); CP_COMMIT();
    load_stage(1, 1); CP_COMMIT();

    const int a_row = wm * 64 + (lane & 7) + ((lane >> 3) & 1) * 8;
    const int a_kb  = ((lane >> 4) & 1) * 16;
    const int b_row = wn * 32 + (lane & 7) + (lane >= 16 ? 8 : 0);
    const int b_kb  = ((lane >> 3) & 1) * 16;

    for (int kb = 0; kb < NKB; kb++) {
        CP_WAIT1();
        __syncthreads();
        if (kb + 2 < NKB) load_stage(kb + 2, (kb + 2) % NSTAGE);
        CP_COMMIT();

        const uint32_t st = sb + (kb % NSTAGE) * G1_STG;
        #pragma unroll
        for (int ks = 0; ks < 2; ks++) {
            uint32_t bhf[2][4];
            #pragma unroll
            for (int np = 0; np < 2; np++) {
                uint32_t bo2 = (b_row + np * 16) * ROWB + b_kb + ks * 32;
                LDSM4(bhf[np], st + OFF_B + bo2);
            }
            #pragma unroll
            for (int mf = 0; mf < 4; mf++) {
                uint32_t ah[4];
                uint32_t ao = (a_row + mf * 16) * ROWB + a_kb + ks * 32;
                LDSM4(ah, st + OFF_A + ao);
                #pragma unroll
                for (int np = 0; np < 2; np++) {
                    MMA16816H(acc[mf][np*2],   ah, bhf[np][0], bhf[np][1]);
                    MMA16816H(acc[mf][np*2+1], ah, bhf[np][2], bhf[np][3]);
                }
            }
        }
        __syncthreads();
    }

    const int mrow = m0 + wm * 64 + (lane >> 2);
    const int ncol = n0 + wn * 32 + (lane & 3) * 2;
    const float oscale = (mode == 0) ? QSCALE : 1.0f;
    __half* dst = mode == 0 ? g_q16 : mode == 1 ? g_k16 : g_v16;

    #pragma unroll
    for (int mf = 0; mf < 4; mf++) {
        #pragma unroll
        for (int hi = 0; hi < 2; hi++) {
            const int m = mrow + mf * 16 + hi * 8;
            #pragma unroll
            for (int nf = 0; nf < 4; nf++) {
                const int n = ncol + nf * 8;
                float v0 = (acc[mf][nf][hi * 2]     + __ldg(&bias[n]))     * oscale;
                float v1 = (acc[mf][nf][hi * 2 + 1] + __ldg(&bias[n + 1])) * oscale;
                if (mode <= 2) {           // Q/K/V: (BH,T,D) fp16
                    const int t = m >> 3, b = m & 7, h = n >> 8, d = n & 255;
                    size_t o = ((size_t)(b * HH + h) * TT + t) * DH + d;
                    __half2 p; p.x = __float2half(v0); p.y = __float2half(v1);
                    *(__half2*)(dst + o) = p;
                } else {                   // O: fp32 (T*B, F)
                    float2 f; f.x = v0; f.y = v1;
                    *(float2*)(outF + (size_t)m * FD + n) = f;
                }
            }
        }
    }
}

// --------------------------- fused flash attention --------------------------
// CTA: 64 q-rows of one bh; 16 kv-tiles of 128 t. 256 threads, warps 2m x 4n.
// QK: fp16 1-term, warp tile m32 x t32.  AV: fp16 1-term, warp tile m32 x d32.
#define Q_OFF 0           // 32KB: mats j*8192
#define B0_OFF 32768      // 32KB
#define B1_OFF 65536      // 32KB
#define P_OFF 98304       // 16KB: two 8KB t-half mats
#define RMAX_OFF 114688
#define RSUM_OFF 115712
#define ATT_SMEM 116736
#define NKV (TT/128)      // 16

__global__ __launch_bounds__(256, 1) void attn_kernel()
{
    extern __shared__ char sm[];
    const uint32_t sb = smem_u32(sm);
    const int tid = threadIdx.x, lane = tid & 31, wid = tid >> 5;
    const int wm = wid >> 2, wn = wid & 3;             // 2m x 4n
    const int bh = blockIdx.y, m0 = blockIdx.x * 64;

    auto load_kv = [&](const __half* __restrict__ src, int tile, int c, uint32_t bufoff) {
        #pragma unroll
        for (int dh = 0; dh < 2; dh++) {
            #pragma unroll
            for (int i = 0; i < 4; i++) {
                int ci = tid + i * 256;
                int r = ci >> 3, cc = ci & 7;
                size_t g = ((size_t)bh * TT + tile * 128 + r) * DH + c * 128 + dh * 64 + cc * 8;
                CP16(sb + bufoff + dh * 16384 + SWZ(r * 128 + cc * 16), src + g);
            }
        }
    };

    // Q resident: 4 mats [j 0..3] of [64 rows x 64 d]
    #pragma unroll
    for (int i = 0; i < 8; i++) {
        int ci = tid + i * 256;
        int mat = ci >> 9, w = ci & 511, r = w >> 3, c = w & 7;
        size_t g = ((size_t)bh * TT + m0 + r) * DH + mat * 64 + c * 8;
        CP16(sb + Q_OFF + mat * 8192 + SWZ(r * 128 + c * 16), g_q16 + g);
    }
    load_kv(g_k16, 0, 0, B0_OFF); CP_COMMIT();
    load_kv(g_k16, 0, 1, B1_OFF); CP_COMMIT();

    const int a_rl = (lane & 7) + ((lane >> 3) & 1) * 8;
    const int a_kb = ((lane >> 4) & 1) * 16;
    const int b_rl = (lane & 7) + (lane >= 16 ? 8 : 0);
    const int b_kb = ((lane >> 3) & 1) * 16;
    const int v_rl = (lane & 7) + ((lane >> 3) & 1) * 8;
    const int v_cb = ((lane >> 4) & 1) * 16;

    float oacc[16][4] = {};
    float sacc[8][4];
    float mrun[2][2], lrun[2][2];
    #pragma unroll
    for (int i = 0; i < 2; i++)
        #pragma unroll
        for (int j = 0; j < 2; j++) { mrun[i][j] = -1e30f; lrun[i][j] = 0.f; }

    const int rl = lane >> 2;
    float* rmax = (float*)(sm + RMAX_OFF);   // [4 wn][64 rows]
    float* rsum = (float*)(sm + RSUM_OFF);

    for (int tile = 0; tile < NKV; tile++) {
        #pragma unroll
        for (int f = 0; f < 8; f++) { sacc[f][0]=0.f; sacc[f][1]=0.f; sacc[f][2]=0.f; sacc[f][3]=0.f; }

        // ---- QK: 2 phases over d-halves; fp16 1-term ----
        #pragma unroll
        for (int c = 0; c < 2; c++) {
            CP_WAIT1(); __syncthreads();
            const uint32_t kb_buf = sb + (c ? B1_OFF : B0_OFF);
            #pragma unroll
            for (int ks = 0; ks < 8; ks++) {
                const uint32_t qm = sb + Q_OFF + (c * 2 + (ks >> 2)) * 8192;
                const uint32_t km = kb_buf + (ks >> 2) * 16384;
                uint32_t q2[2][4], kh[2][4];
                #pragma unroll
                for (int mf = 0; mf < 2; mf++) {
                    uint32_t ao = SWZ((wm * 32 + mf * 16 + a_rl) * 128 + (ks & 3) * 32 + a_kb);
                    LDSM4(q2[mf], qm + ao);
                }
                #pragma unroll
                for (int g = 0; g < 2; g++) {
                    uint32_t bo = SWZ((wn * 32 + g * 16 + b_rl) * 128 + (ks & 3) * 32 + b_kb);
                    LDSM4(kh[g], km + bo);
                }
                #pragma unroll
                for (int mf = 0; mf < 2; mf++)
                    #pragma unroll
                    for (int g = 0; g < 2; g++) {
                        MMA16816H(sacc[mf*4+g*2],   q2[mf], kh[g][0], kh[g][1]);
                        MMA16816H(sacc[mf*4+g*2+1], q2[mf], kh[g][2], kh[g][3]);
                    }
            }
            __syncthreads();
            load_kv(g_v16, tile, c, c ? B1_OFF : B0_OFF);
            CP_COMMIT();
        }

        // ---- online softmax (log2 units via folded QSCALE) ----
        float mx[2][2];
        #pragma unroll
        for (int mf = 0; mf < 2; mf++) { mx[mf][0] = -1e30f; mx[mf][1] = -1e30f; }
        #pragma unroll
        for (int f = 0; f < 8; f++) {
            const int mf = f >> 2;
            mx[mf][0] = fmaxf(mx[mf][0], fmaxf(sacc[f][0], sacc[f][1]));
            mx[mf][1] = fmaxf(mx[mf][1], fmaxf(sacc[f][2], sacc[f][3]));
        }
        #pragma unroll
        for (int mf = 0; mf < 2; mf++)
            #pragma unroll
            for (int hf = 0; hf < 2; hf++) {
                mx[mf][hf] = fmaxf(mx[mf][hf], __shfl_xor_sync(0xffffffffu, mx[mf][hf], 1));
                mx[mf][hf] = fmaxf(mx[mf][hf], __shfl_xor_sync(0xffffffffu, mx[mf][hf], 2));
            }
        if ((lane & 3) == 0) {
            #pragma unroll
            for (int mf = 0; mf < 2; mf++)
                #pragma unroll
                for (int hf = 0; hf < 2; hf++)
                    rmax[wn * 64 + wm * 32 + mf * 16 + hf * 8 + rl] = mx[mf][hf];
        }
        __syncthreads();

        float aa[2][2];
        #pragma unroll
        for (int mf = 0; mf < 2; mf++)
            #pragma unroll
            for (int hf = 0; hf < 2; hf++) {
                const int row = wm * 32 + mf * 16 + hf * 8 + rl;
                float mn = mrun[mf][hf];
                #pragma unroll
                for (int w = 0; w < 4; w++) mn = fmaxf(mn, rmax[w * 64 + row]);
                aa[mf][hf] = exp2f(mrun[mf][hf] - mn);
                mrun[mf][hf] = mn;
            }

        float ss[2][2] = {};
        #pragma unroll
        for (int f = 0; f < 8; f++) {
            const int mf = f >> 2;
            sacc[f][0] = exp2f(sacc[f][0] - mrun[mf][0]);
            sacc[f][1] = exp2f(sacc[f][1] - mrun[mf][0]);
            sacc[f][2] = exp2f(sacc[f][2] - mrun[mf][1]);
            sacc[f][3] = exp2f(sacc[f][3] - mrun[mf][1]);
            ss[mf][0] += sacc[f][0] + sacc[f][1];
            ss[mf][1] += sacc[f][2] + sacc[f][3];
        }
        #pragma unroll
        for (int mf = 0; mf < 2; mf++)
            #pragma unroll
            for (int hf = 0; hf < 2; hf++) {
                ss[mf][hf] += __shfl_xor_sync(0xffffffffu, ss[mf][hf], 1);
                ss[mf][hf] += __shfl_xor_sync(0xffffffffu, ss[mf][hf], 2);
            }
        if ((lane & 3) == 0) {
            #pragma unroll
            for (int mf = 0; mf < 2; mf++)
                #pragma unroll
                for (int hf = 0; hf < 2; hf++)
                    rsum[wn * 64 + wm * 32 + mf * 16 + hf * 8 + rl] = ss[mf][hf];
        }

        // rescale O accumulators (skip when running max unchanged warp-wide)
        {
            bool need = (aa[0][0] < 1.f) || (aa[0][1] < 1.f) ||
                        (aa[1][0] < 1.f) || (aa[1][1] < 1.f);
            if (__any_sync(0xffffffffu, need)) {
                #pragma unroll
                for (int f = 0; f < 16; f++) {
                    const int mf = (f >> 2) & 1;
                    oacc[f][0] *= aa[mf][0]; oacc[f][1] *= aa[mf][0];
                    oacc[f][2] *= aa[mf][1]; oacc[f][3] *= aa[mf][1];
                }
            }
        }

        // P -> smem, fp16 single: two 8KB t-half mats
        {
            const int th = wn >> 1, cbase = (wn & 1) * 32;
            #pragma unroll
            for (int f = 0; f < 8; f++) {
                const int mf = f >> 2, g = (f >> 1) & 1, f8 = f & 1;
                const int colm = cbase + g * 16 + f8 * 8 + (lane & 3) * 2;
                const uint32_t pmo = P_OFF + th * 8192;
                __half2 p0; p0.x = __float2half(sacc[f][0]); p0.y = __float2half(sacc[f][1]);
                __half2 p1; p1.x = __float2half(sacc[f][2]); p1.y = __float2half(sacc[f][3]);
                uint32_t off = SWZ((wm * 32 + mf * 16 + rl) * 128 + colm * 2);
                *(__half2*)(sm + pmo + off) = p0;
                off = SWZ((wm * 32 + mf * 16 + 8 + rl) * 128 + colm * 2);
                *(__half2*)(sm + pmo + off) = p1;
            }
        }
        __syncthreads();

        #pragma unroll
        for (int mf = 0; mf < 2; mf++)
            #pragma unroll
            for (int hf = 0; hf < 2; hf++) {
                const int row = wm * 32 + mf * 16 + hf * 8 + rl;
                float s = 0.f;
                #pragma unroll
                for (int w = 0; w < 4; w++) s += rsum[w * 64 + row];
                lrun[mf][hf] = lrun[mf][hf] * aa[mf][hf] + s;
            }

        // ---- AV: 2 phases over d-halves; fp16 1-term ----
        #pragma unroll
        for (int c = 0; c < 2; c++) {
            CP_WAIT1(); __syncthreads();
            const uint32_t v_buf = sb + (c ? B1_OFF : B0_OFF) + (wn >> 1) * 16384;
            const int vcb = (wn & 1) * 64;
            #pragma unroll
            for (int ks = 0; ks < 8; ks++) {
                const uint32_t pm = sb + P_OFF + (ks >> 2) * 8192;
                uint32_t ph2[2][4], vh[2][4];
                #pragma unroll
                for (int mf = 0; mf < 2; mf++) {
                    uint32_t ao = SWZ((wm * 32 + mf * 16 + a_rl) * 128 + (ks & 3) * 32 + a_kb);
                    LDSM4(ph2[mf], pm + ao);
                }
                const uint32_t vrow = ks * 16 + v_rl;
                #pragma unroll
                for (int g = 0; g < 2; g++) {
                    uint32_t bo = SWZ(vrow * 128 + vcb + g * 32 + v_cb);
                    LDSM4T(vh[g], v_buf + bo);
                }
                #pragma unroll
                for (int mf = 0; mf < 2; mf++)
                    #pragma unroll
                    for (int g = 0; g < 2; g++) {
                        MMA16816H(oacc[c*8+mf*4+g*2],   ph2[mf], vh[g][0], vh[g][1]);
                        MMA16816H(oacc[c*8+mf*4+g*2+1], ph2[mf], vh[g][2], vh[g][3]);
                    }
            }
            __syncthreads();
            if (tile + 1 < NKV) load_kv(g_k16, tile + 1, c, c ? B1_OFF : B0_OFF);
            CP_COMMIT();
        }
    }

    // ---- epilogue: normalize + write fp16 single for output projection ----
    const int bb = bh / HH, hh = bh % HH;
    #pragma unroll
    for (int f = 0; f < 16; f++) {
        const int c = f >> 3, mf = (f >> 2) & 1, g = (f >> 1) & 1, f8 = f & 1;
        const int d = c * 128 + wn * 32 + g * 16 + f8 * 8 + (lane & 3) * 2;
        #pragma unroll
        for (int hf = 0; hf < 2; hf++) {
            const int t = m0 + wm * 32 + mf * 16 + hf * 8 + rl;
            const float inv = 1.f / lrun[mf][hf];
            float v0 = oacc[f][hf*2] * inv, v1 = oacc[f][hf*2+1] * inv;
            size_t o = ((size_t)t * BB + bb) * FD + hh * DH + d;
            __half2 p; p.x = __float2half(v0); p.y = __float2half(v1);
            *(__half2*)(g_o16 + o) = p;
        }
    }
}

// ------------------------------ helper kernels ------------------------------
// x -> fp16 single
__global__ __launch_bounds__(256) void split_x_kernel(
    const float* __restrict__ in, int n4)
{
    int i = blockIdx.x * 256 + threadIdx.x;
    if (i >= n4) return;
    float4 v = *(const float4*)(in + (size_t)i * 4);
    __half2 p; p.x = __float2half(v.x); p.y = __float2half(v.y);
    __half2 q; q.x = __float2half(v.z); q.y = __float2half(v.w);
    *(__half2*)(g_x16 + (size_t)i*4)     = p;
    *(__half2*)(g_x16 + (size_t)i*4 + 2) = q;
}

// all W -> single fp16
__global__ __launch_bounds__(256) void split_w_kernel(
    const float* __restrict__ w0, const float* __restrict__ w1,
    const float* __restrict__ w2, const float* __restrict__ w3)
{
    const int which = blockIdx.y;
    int i = blockIdx.x * 256 + threadIdx.x;
    if (i >= FD*FD/4) return;
    const float* in = which == 0 ? w0 : which == 1 ? w1 : which == 2 ? w2 : w3;
    __half* h = which == 0 ? g_wq16 : which == 1 ? g_wk16 : which == 2 ? g_wv16 : g_wo16;
    float4 v = *(const float4*)(in + (size_t)i * 4);
    __half2 p; p.x=__float2half(v.x); p.y=__float2half(v.y);
    __half2 q; q.x=__float2half(v.z); q.y=__float2half(v.w);
    *(__half2*)(h + (size_t)i*4)     = p;
    *(__half2*)(h + (size_t)i*4 + 2) = q;
}

// --------------------------------- launch ----------------------------------
extern "C" void kernel_launch(void* const* d_in, const int* in_sizes, int n_in,
                              void* d_out, int out_size)
{
    const float* x  = (const float*)d_in[0];
    const float* Wq = (const float*)d_in[1];
    const float* bq = (const float*)d_in[2];
    const float* Wk = (const float*)d_in[3];
    const float* bk = (const float*)d_in[4];
    const float* Wv = (const float*)d_in[5];
    const float* bv = (const float*)d_in[6];
    const float* Wo = (const float*)d_in[7];
    const float* bo = (const float*)d_in[8];
    float* out = (float*)d_out;

    cudaFuncSetAttribute(gemm_1t,     cudaFuncAttributeMaxDynamicSharedMemorySize, G1_SMEM);
    cudaFuncSetAttribute(attn_kernel, cudaFuncAttributeMaxDynamicSharedMemorySize, ATT_SMEM);

    __half *x16, *o16;
    cudaGetSymbolAddress((void**)&x16, g_x16);
    cudaGetSymbolAddress((void**)&o16, g_o16);

    // 0: x split (fp16 single)
    split_x_kernel<<<(MROWS*FD/4 + 255)/256, 256>>>(x, MROWS*FD/4);
    // 1: W splits (all single fp16)
    dim3 gW((FD*FD/4 + 255)/256, 4);
    split_w_kernel<<<gW, 256>>>(Wq, Wk, Wv, Wo);
    // 2: fused QKV projection (fp16 1-term), z = 0,1,2
    dim3 gQKV(MROWS/BM, FD/BN, 3);
    gemm_1t<<<gQKV, 512, G1_SMEM>>>(x16, 0, bq, bk, bv, bo, nullptr);
    // 3: fused flash attention
    dim3 gA(TT/64, NBH);
    attn_kernel<<<gA, 256, ATT_SMEM>>>();
    // 4: output projection (fp16 1-term, mode 3)
    dim3 gO(MROWS/BM, FD/BN, 1);
    gemm_1t<<<gO, 512, G1_SMEM>>>(o16, 3, bq, bk, bv, bo, out);
}

// round 15
// speedup vs baseline: 2.5643x; 1.0474x over previous
#include <cuda_runtime.h>
#include <cuda_fp16.h>
#include <cstdint>

#define TT 2048
#define BB 8
#define FD 768
#define HH 3
#define DH 256
#define MROWS (TT*BB)      // 16384
#define NBH (BB*HH)        // 24

// ------------------------- device scratch (static) -------------------------
__device__ __align__(16) __half g_x16[MROWS*FD];
__device__ __align__(16) __half g_wq16[FD*FD];
__device__ __align__(16) __half g_wk16[FD*FD];
__device__ __align__(16) __half g_wv16[FD*FD];
__device__ __align__(16) __half g_wo16[FD*FD];
__device__ __align__(16) __half g_q16[NBH*TT*DH];                    // Q fp16 (scaled)
__device__ __align__(16) __half g_k16[NBH*TT*DH];
__device__ __align__(16) __half g_v16[NBH*TT*DH];
__device__ __align__(16) __half g_o16[MROWS*FD];

// ------------------------------ PTX helpers --------------------------------
__device__ __forceinline__ uint32_t smem_u32(const void* p) {
    uint32_t a;
    asm("{ .reg .u64 t; cvta.to.shared.u64 t, %1; cvt.u32.u64 %0, t; }" : "=r"(a) : "l"(p));
    return a;
}
#define CP16(dst, src) \
    asm volatile("cp.async.cg.shared.global [%0], [%1], 16;" :: "r"(dst), "l"(src) : "memory")
#define CP_COMMIT() asm volatile("cp.async.commit_group;" ::: "memory")
#define CP_WAIT1()  asm volatile("cp.async.wait_group 1;" ::: "memory")

#define LDSM4(r, addr) \
    asm volatile("ldmatrix.sync.aligned.m8n8.x4.shared.b16 {%0,%1,%2,%3}, [%4];" \
        : "=r"((r)[0]), "=r"((r)[1]), "=r"((r)[2]), "=r"((r)[3]) : "r"(addr))
#define LDSM4T(r, addr) \
    asm volatile("ldmatrix.sync.aligned.m8n8.x4.trans.shared.b16 {%0,%1,%2,%3}, [%4];" \
        : "=r"((r)[0]), "=r"((r)[1]), "=r"((r)[2]), "=r"((r)[3]) : "r"(addr))

#define MMA16816H(d, a, b0v, b1v) \
    asm volatile("mma.sync.aligned.m16n8k16.row.col.f32.f16.f16.f32 " \
        "{%0,%1,%2,%3}, {%4,%5,%6,%7}, {%8,%9}, {%0,%1,%2,%3};" \
        : "+f"((d)[0]), "+f"((d)[1]), "+f"((d)[2]), "+f"((d)[3]) \
        : "r"((a)[0]), "r"((a)[1]), "r"((a)[2]), "r"((a)[3]), "r"(b0v), "r"(b1v))

#define SWZ(o) ((uint32_t)(o) ^ ((((uint32_t)(o)) >> 3) & 0x70))

#define QSCALE 0.1803368801111204f    // 0.125 * log2(e)

// ---------------- fp16 1-term GEMM (all projections), 512 thr ---------------
#define BM 256
#define BN 128
#define BK 32
#define ROWB 80
#define MAT_A (256*ROWB)
#define MAT_B (128*ROWB)
#define NSTAGE 3
#define G1_STG  (MAT_A + MAT_B)       // 30720
#define G1_SMEM (NSTAGE*G1_STG)       // 92160

// mode = blockIdx.z + mode_base: 0=Q (scaled fp16 out), 1=K, 2=V, 3=O (fp32 out)
__global__ __launch_bounds__(512, 1) void gemm_1t(
    const __half* __restrict__ A, int mode_base,
    const float* __restrict__ bq, const float* __restrict__ bk,
    const float* __restrict__ bv, const float* __restrict__ bo,
    float* __restrict__ outF)
{
    constexpr int OFF_A = 0;
    constexpr int OFF_B = MAT_A;

    extern __shared__ char smem[];
    const uint32_t sb = smem_u32(smem);

    const int tid = threadIdx.x;
    const int wid = tid >> 5, lane = tid & 31;
    const int wm = wid >> 2, wn = wid & 3;
    const int m0 = blockIdx.x * BM, n0 = blockIdx.y * BN;
    const int mode = blockIdx.z + mode_base;
    const int K = FD;

    const __half* Bw = mode == 0 ? g_wq16 : mode == 1 ? g_wk16 : mode == 2 ? g_wv16 : g_wo16;
    const float* bias = mode == 0 ? bq : mode == 1 ? bk : mode == 2 ? bv : bo;

    float acc[4][4][4] = {};

    const int ra0 = tid >> 2,          ca0 = tid & 3;
    const int ra1 = (tid + 512) >> 2,  ca1 = (tid + 512) & 3;
    const int rb  = tid >> 2,          cb  = tid & 3;

    auto load_stage = [&](int kb, int s) {
        const uint32_t st = sb + s * G1_STG;
        {
            size_t g = (size_t)(m0 + ra0) * K + kb * BK + ca0 * 8;
            CP16(st + OFF_A + ra0 * ROWB + ca0 * 16, A + g);
        }
        {
            size_t g = (size_t)(m0 + ra1) * K + kb * BK + ca1 * 8;
            CP16(st + OFF_A + ra1 * ROWB + ca1 * 16, A + g);
        }
        {
            size_t g = (size_t)(n0 + rb) * K + kb * BK + cb * 8;
            CP16(st + OFF_B + rb * ROWB + cb * 16, Bw + g);
        }
    };

    const int NKB = K / BK;
    load_stage(0, 0); CP_COMMIT();
    load_stage(1, 1); CP_COMMIT();

    const int a_row = wm * 64 + (lane & 7) + ((lane >> 3) & 1) * 8;
    const int a_kb  = ((lane >> 4) & 1) * 16;
    const int b_row = wn * 32 + (lane & 7) + (lane >= 16 ? 8 : 0);
    const int b_kb  = ((lane >> 3) & 1) * 16;

    for (int kb = 0; kb < NKB; kb++) {
        CP_WAIT1();
        __syncthreads();
        if (kb + 2 < NKB) load_stage(kb + 2, (kb + 2) % NSTAGE);
        CP_COMMIT();

        const uint32_t st = sb + (kb % NSTAGE) * G1_STG;
        #pragma unroll
        for (int ks = 0; ks < 2; ks++) {
            uint32_t bhf[2][4];
            #pragma unroll
            for (int np = 0; np < 2; np++) {
                uint32_t bo2 = (b_row + np * 16) * ROWB + b_kb + ks * 32;
                LDSM4(bhf[np], st + OFF_B + bo2);
            }
            #pragma unroll
            for (int mf = 0; mf < 4; mf++) {
                uint32_t ah[4];
                uint32_t ao = (a_row + mf * 16) * ROWB + a_kb + ks * 32;
                LDSM4(ah, st + OFF_A + ao);
                #pragma unroll
                for (int np = 0; np < 2; np++) {
                    MMA16816H(acc[mf][np*2],   ah, bhf[np][0], bhf[np][1]);
                    MMA16816H(acc[mf][np*2+1], ah, bhf[np][2], bhf[np][3]);
                }
            }
        }
        __syncthreads();
    }

    const int mrow = m0 + wm * 64 + (lane >> 2);
    const int ncol = n0 + wn * 32 + (lane & 3) * 2;
    const float oscale = (mode == 0) ? QSCALE : 1.0f;
    __half* dst = mode == 0 ? g_q16 : mode == 1 ? g_k16 : g_v16;

    #pragma unroll
    for (int mf = 0; mf < 4; mf++) {
        #pragma unroll
        for (int hi = 0; hi < 2; hi++) {
            const int m = mrow + mf * 16 + hi * 8;
            #pragma unroll
            for (int nf = 0; nf < 4; nf++) {
                const int n = ncol + nf * 8;
                float v0 = (acc[mf][nf][hi * 2]     + __ldg(&bias[n]))     * oscale;
                float v1 = (acc[mf][nf][hi * 2 + 1] + __ldg(&bias[n + 1])) * oscale;
                if (mode <= 2) {           // Q/K/V: (BH,T,D) fp16
                    const int t = m >> 3, b = m & 7, h = n >> 8, d = n & 255;
                    size_t o = ((size_t)(b * HH + h) * TT + t) * DH + d;
                    __half2 p; p.x = __float2half(v0); p.y = __float2half(v1);
                    *(__half2*)(dst + o) = p;
                } else {                   // O: fp32 (T*B, F)
                    float2 f; f.x = v0; f.y = v1;
                    *(float2*)(outF + (size_t)m * FD + n) = f;
                }
            }
        }
    }
}

// --------------------------- fused flash attention --------------------------
// CTA: 32 q-rows of one bh; 16 kv-tiles of 128 t. 128 threads (4 warps, 1m x 4n),
// 2 CTAs/SM (cross-CTA softmax/MMA overlap).
// QK: fp16 1-term, warp tile m32 x t32.  AV: fp16 1-term, warp tile m32 x d32.
#define Q_OFF 0           // 16KB: 4 mats [32r x 64d] at j*4096
#define B0_OFF 16384      // 32KB: [dh 0/1][128t x 64d]
#define B1_OFF 49152      // 32KB
#define P_OFF 81920       // 8KB: two 4KB t-half mats [32r x 64t]
#define RMAX_OFF 90112    // [4 wn][32 rows]
#define RSUM_OFF 90624
#define ATT_SMEM 91136
#define NKV (TT/128)      // 16

__global__ __launch_bounds__(128, 2) void attn_kernel()
{
    extern __shared__ char sm[];
    const uint32_t sb = smem_u32(sm);
    const int tid = threadIdx.x, lane = tid & 31, wn = tid >> 5;   // 4 warps = 4n
    const int bh = blockIdx.y, m0 = blockIdx.x * 32;

    auto load_kv = [&](const __half* __restrict__ src, int tile, int c, uint32_t bufoff) {
        #pragma unroll
        for (int dh = 0; dh < 2; dh++) {
            #pragma unroll
            for (int i = 0; i < 8; i++) {
                int ci = tid + i * 128;
                int r = ci >> 3, cc = ci & 7;
                size_t g = ((size_t)bh * TT + tile * 128 + r) * DH + c * 128 + dh * 64 + cc * 8;
                CP16(sb + bufoff + dh * 16384 + SWZ(r * 128 + cc * 16), src + g);
            }
        }
    };

    // Q resident: 4 mats [j 0..3] of [32 rows x 64 d] (4KB each)
    #pragma unroll
    for (int i = 0; i < 8; i++) {
        int ci = tid + i * 128;
        int mat = ci >> 8, w = ci & 255, r = w >> 3, c = w & 7;
        size_t g = ((size_t)bh * TT + m0 + r) * DH + mat * 64 + c * 8;
        CP16(sb + Q_OFF + mat * 4096 + SWZ(r * 128 + c * 16), g_q16 + g);
    }
    load_kv(g_k16, 0, 0, B0_OFF); CP_COMMIT();
    load_kv(g_k16, 0, 1, B1_OFF); CP_COMMIT();

    const int a_rl = (lane & 7) + ((lane >> 3) & 1) * 8;
    const int a_kb = ((lane >> 4) & 1) * 16;
    const int b_rl = (lane & 7) + (lane >= 16 ? 8 : 0);
    const int b_kb = ((lane >> 3) & 1) * 16;
    const int v_rl = (lane & 7) + ((lane >> 3) & 1) * 8;
    const int v_cb = ((lane >> 4) & 1) * 16;

    float oacc[16][4] = {};      // [c*8 + mf*4 + g*2 + f8]
    float sacc[8][4];            // [mf*4 + g*2 + f8]
    float mrun[2][2], lrun[2][2];
    #pragma unroll
    for (int i = 0; i < 2; i++)
        #pragma unroll
        for (int j = 0; j < 2; j++) { mrun[i][j] = -1e30f; lrun[i][j] = 0.f; }

    const int rl = lane >> 2;
    float* rmax = (float*)(sm + RMAX_OFF);   // [4 wn][32 rows]
    float* rsum = (float*)(sm + RSUM_OFF);

    for (int tile = 0; tile < NKV; tile++) {
        #pragma unroll
        for (int f = 0; f < 8; f++) { sacc[f][0]=0.f; sacc[f][1]=0.f; sacc[f][2]=0.f; sacc[f][3]=0.f; }

        // ---- QK: 2 phases over d-halves; fp16 1-term; warp tile m32 x t32 ----
        #pragma unroll
        for (int c = 0; c < 2; c++) {
            CP_WAIT1(); __syncthreads();
            const uint32_t kb_buf = sb + (c ? B1_OFF : B0_OFF);
            #pragma unroll
            for (int ks = 0; ks < 8; ks++) {
                const uint32_t qm = sb + Q_OFF + (c * 2 + (ks >> 2)) * 4096;
                const uint32_t km = kb_buf + (ks >> 2) * 16384;
                uint32_t q2[2][4], kh[2][4];
                #pragma unroll
                for (int mf = 0; mf < 2; mf++) {
                    uint32_t ao = SWZ((mf * 16 + a_rl) * 128 + (ks & 3) * 32 + a_kb);
                    LDSM4(q2[mf], qm + ao);
                }
                #pragma unroll
                for (int g = 0; g < 2; g++) {
                    uint32_t bo = SWZ((wn * 32 + g * 16 + b_rl) * 128 + (ks & 3) * 32 + b_kb);
                    LDSM4(kh[g], km + bo);
                }
                #pragma unroll
                for (int mf = 0; mf < 2; mf++)
                    #pragma unroll
                    for (int g = 0; g < 2; g++) {
                        MMA16816H(sacc[mf*4+g*2],   q2[mf], kh[g][0], kh[g][1]);
                        MMA16816H(sacc[mf*4+g*2+1], q2[mf], kh[g][2], kh[g][3]);
                    }
            }
            __syncthreads();
            load_kv(g_v16, tile, c, c ? B1_OFF : B0_OFF);
            CP_COMMIT();
        }

        // ---- online softmax (log2 units via folded QSCALE) ----
        float mx[2][2];
        #pragma unroll
        for (int mf = 0; mf < 2; mf++) { mx[mf][0] = -1e30f; mx[mf][1] = -1e30f; }
        #pragma unroll
        for (int f = 0; f < 8; f++) {
            const int mf = f >> 2;
            mx[mf][0] = fmaxf(mx[mf][0], fmaxf(sacc[f][0], sacc[f][1]));
            mx[mf][1] = fmaxf(mx[mf][1], fmaxf(sacc[f][2], sacc[f][3]));
        }
        #pragma unroll
        for (int mf = 0; mf < 2; mf++)
            #pragma unroll
            for (int hf = 0; hf < 2; hf++) {
                mx[mf][hf] = fmaxf(mx[mf][hf], __shfl_xor_sync(0xffffffffu, mx[mf][hf], 1));
                mx[mf][hf] = fmaxf(mx[mf][hf], __shfl_xor_sync(0xffffffffu, mx[mf][hf], 2));
            }
        if ((lane & 3) == 0) {
            #pragma unroll
            for (int mf = 0; mf < 2; mf++)
                #pragma unroll
                for (int hf = 0; hf < 2; hf++)
                    rmax[wn * 32 + mf * 16 + hf * 8 + rl] = mx[mf][hf];
        }
        __syncthreads();

        float aa[2][2];
        #pragma unroll
        for (int mf = 0; mf < 2; mf++)
            #pragma unroll
            for (int hf = 0; hf < 2; hf++) {
                const int row = mf * 16 + hf * 8 + rl;
                float mn = mrun[mf][hf];
                #pragma unroll
                for (int w = 0; w < 4; w++) mn = fmaxf(mn, rmax[w * 32 + row]);
                aa[mf][hf] = exp2f(mrun[mf][hf] - mn);
                mrun[mf][hf] = mn;
            }

        float ss[2][2] = {};
        #pragma unroll
        for (int f = 0; f < 8; f++) {
            const int mf = f >> 2;
            sacc[f][0] = exp2f(sacc[f][0] - mrun[mf][0]);
            sacc[f][1] = exp2f(sacc[f][1] - mrun[mf][0]);
            sacc[f][2] = exp2f(sacc[f][2] - mrun[mf][1]);
            sacc[f][3] = exp2f(sacc[f][3] - mrun[mf][1]);
            ss[mf][0] += sacc[f][0] + sacc[f][1];
            ss[mf][1] += sacc[f][2] + sacc[f][3];
        }
        #pragma unroll
        for (int mf = 0; mf < 2; mf++)
            #pragma unroll
            for (int hf = 0; hf < 2; hf++) {
                ss[mf][hf] += __shfl_xor_sync(0xffffffffu, ss[mf][hf], 1);
                ss[mf][hf] += __shfl_xor_sync(0xffffffffu, ss[mf][hf], 2);
            }
        if ((lane & 3) == 0) {
            #pragma unroll
            for (int mf = 0; mf < 2; mf++)
                #pragma unroll
                for (int hf = 0; hf < 2; hf++)
                    rsum[wn * 32 + mf * 16 + hf * 8 + rl] = ss[mf][hf];
        }

        // rescale O accumulators (skip when running max unchanged warp-wide)
        {
            bool need = (aa[0][0] < 1.f) || (aa[0][1] < 1.f) ||
                        (aa[1][0] < 1.f) || (aa[1][1] < 1.f);
            if (__any_sync(0xffffffffu, need)) {
                #pragma unroll
                for (int f = 0; f < 16; f++) {
                    const int mf = (f >> 2) & 1;
                    oacc[f][0] *= aa[mf][0]; oacc[f][1] *= aa[mf][0];
                    oacc[f][2] *= aa[mf][1]; oacc[f][3] *= aa[mf][1];
                }
            }
        }

        // P -> smem, fp16: two 4KB t-half mats [32 r x 64 t]
        {
            const int th = wn >> 1, cbase = (wn & 1) * 32;
            #pragma unroll
            for (int f = 0; f < 8; f++) {
                const int mf = f >> 2, g = (f >> 1) & 1, f8 = f & 1;
                const int colm = cbase + g * 16 + f8 * 8 + (lane & 3) * 2;
                const uint32_t pmo = P_OFF + th * 4096;
                __half2 p0; p0.x = __float2half(sacc[f][0]); p0.y = __float2half(sacc[f][1]);
                __half2 p1; p1.x = __float2half(sacc[f][2]); p1.y = __float2half(sacc[f][3]);
                uint32_t off = SWZ((mf * 16 + rl) * 128 + colm * 2);
                *(__half2*)(sm + pmo + off) = p0;
                off = SWZ((mf * 16 + 8 + rl) * 128 + colm * 2);
                *(__half2*)(sm + pmo + off) = p1;
            }
        }
        __syncthreads();

        #pragma unroll
        for (int mf = 0; mf < 2; mf++)
            #pragma unroll
            for (int hf = 0; hf < 2; hf++) {
                const int row = mf * 16 + hf * 8 + rl;
                float s = 0.f;
                #pragma unroll
                for (int w = 0; w < 4; w++) s += rsum[w * 32 + row];
                lrun[mf][hf] = lrun[mf][hf] * aa[mf][hf] + s;
            }

        // ---- AV: 2 phases over d-halves; fp16 1-term; warp tile m32 x d32 ----
        #pragma unroll
        for (int c = 0; c < 2; c++) {
            CP_WAIT1(); __syncthreads();
            const uint32_t v_buf = sb + (c ? B1_OFF : B0_OFF) + (wn >> 1) * 16384;
            const int vcb = (wn & 1) * 64;
            #pragma unroll
            for (int ks = 0; ks < 8; ks++) {
                const uint32_t pm = sb + P_OFF + (ks >> 2) * 4096;
                uint32_t ph2[2][4], vh[2][4];
                #pragma unroll
                for (int mf = 0; mf < 2; mf++) {
                    uint32_t ao = SWZ((mf * 16 + a_rl) * 128 + (ks & 3) * 32 + a_kb);
                    LDSM4(ph2[mf], pm + ao);
                }
                const uint32_t vrow = ks * 16 + v_rl;
                #pragma unroll
                for (int g = 0; g < 2; g++) {
                    uint32_t bo = SWZ(vrow * 128 + vcb + g * 32 + v_cb);
                    LDSM4T(vh[g], v_buf + bo);
                }
                #pragma unroll
                for (int mf = 0; mf < 2; mf++)
                    #pragma unroll
                    for (int g = 0; g < 2; g++) {
                        MMA16816H(oacc[c*8+mf*4+g*2],   ph2[mf], vh[g][0], vh[g][1]);
                        MMA16816H(oacc[c*8+mf*4+g*2+1], ph2[mf], vh[g][2], vh[g][3]);
                    }
            }
            __syncthreads();
            if (tile + 1 < NKV) load_kv(g_k16, tile + 1, c, c ? B1_OFF : B0_OFF);
            CP_COMMIT();
        }
    }

    // ---- epilogue: normalize + write fp16 single for output projection ----
    const int bb = bh / HH, hh = bh % HH;
    #pragma unroll
    for (int f = 0; f < 16; f++) {
        const int c = f >> 3, mf = (f >> 2) & 1, g = (f >> 1) & 1, f8 = f & 1;
        const int d = c * 128 + wn * 32 + g * 16 + f8 * 8 + (lane & 3) * 2;
        #pragma unroll
        for (int hf = 0; hf < 2; hf++) {
            const int t = m0 + mf * 16 + hf * 8 + rl;
            const float inv = 1.f / lrun[mf][hf];
            float v0 = oacc[f][hf*2] * inv, v1 = oacc[f][hf*2+1] * inv;
            size_t o = ((size_t)t * BB + bb) * FD + hh * DH + d;
            __half2 p; p.x = __float2half(v0); p.y = __float2half(v1);
            *(__half2*)(g_o16 + o) = p;
        }
    }
}

// ------------------------------ helper kernels ------------------------------
__global__ __launch_bounds__(256) void split_x_kernel(
    const float* __restrict__ in, int n4)
{
    int i = blockIdx.x * 256 + threadIdx.x;
    if (i >= n4) return;
    float4 v = *(const float4*)(in + (size_t)i * 4);
    __half2 p; p.x = __float2half(v.x); p.y = __float2half(v.y);
    __half2 q; q.x = __float2half(v.z); q.y = __float2half(v.w);
    *(__half2*)(g_x16 + (size_t)i*4)     = p;
    *(__half2*)(g_x16 + (size_t)i*4 + 2) = q;
}

__global__ __launch_bounds__(256) void split_w_kernel(
    const float* __restrict__ w0, const float* __restrict__ w1,
    const float* __restrict__ w2, const float* __restrict__ w3)
{
    const int which = blockIdx.y;
    int i = blockIdx.x * 256 + threadIdx.x;
    if (i >= FD*FD/4) return;
    const float* in = which == 0 ? w0 : which == 1 ? w1 : which == 2 ? w2 : w3;
    __half* h = which == 0 ? g_wq16 : which == 1 ? g_wk16 : which == 2 ? g_wv16 : g_wo16;
    float4 v = *(const float4*)(in + (size_t)i * 4);
    __half2 p; p.x=__float2half(v.x); p.y=__float2half(v.y);
    __half2 q; q.x=__float2half(v.z); q.y=__float2half(v.w);
    *(__half2*)(h + (size_t)i*4)     = p;
    *(__half2*)(h + (size_t)i*4 + 2) = q;
}

// --------------------------------- launch ----------------------------------
extern "C" void kernel_launch(void* const* d_in, const int* in_sizes, int n_in,
                              void* d_out, int out_size)
{
    const float* x  = (const float*)d_in[0];
    const float* Wq = (const float*)d_in[1];
    const float* bq = (const float*)d_in[2];
    const float* Wk = (const float*)d_in[3];
    const float* bk = (const float*)d_in[4];
    const float* Wv = (const float*)d_in[5];
    const float* bv = (const float*)d_in[6];
    const float* Wo = (const float*)d_in[7];
    const float* bo = (const float*)d_in[8];
    float* out = (float*)d_out;

    cudaFuncSetAttribute(gemm_1t,     cudaFuncAttributeMaxDynamicSharedMemorySize, G1_SMEM);
    cudaFuncSetAttribute(attn_kernel, cudaFuncAttributeMaxDynamicSharedMemorySize, ATT_SMEM);

    __half *x16, *o16;
    cudaGetSymbolAddress((void**)&x16, g_x16);
    cudaGetSymbolAddress((void**)&o16, g_o16);

    // 0: x split (fp16 single)
    split_x_kernel<<<(MROWS*FD/4 + 255)/256, 256>>>(x, MROWS*FD/4);
    // 1: W splits (all single fp16)
    dim3 gW((FD*FD/4 + 255)/256, 4);
    split_w_kernel<<<gW, 256>>>(Wq, Wk, Wv, Wo);
    // 2: fused QKV projection (fp16 1-term), z = 0,1,2
    dim3 gQKV(MROWS/BM, FD/BN, 3);
    gemm_1t<<<gQKV, 512, G1_SMEM>>>(x16, 0, bq, bk, bv, bo, nullptr);
    // 3: fused flash attention (32 q-rows/CTA, 2 CTAs/SM)
    dim3 gA(TT/32, NBH);
    attn_kernel<<<gA, 128, ATT_SMEM>>>();
    // 4: output projection (fp16 1-term, mode 3)
    dim3 gO(MROWS/BM, FD/BN, 1);
    gemm_1t<<<gO, 512, G1_SMEM>>>(o16, 3, bq, bk, bv, bo, out);
}